// round 2
// baseline (speedup 1.0000x reference)
#include <cuda_runtime.h>
#include <cuda_bf16.h>
#include <math.h>

// ---------------------------------------------------------------------------
// Problem constants
// ---------------------------------------------------------------------------
#define BB   2            // batch
#define LL   2048         // seq len
#define DM   1024         // d_model
#define DI   2048         // d_inner
#define DS   16           // d_state
#define DR   64           // dt_rank
#define DCONV 4
#define NXP  96           // dt_rank + 2*d_state
#define NXPP 128          // padded
#define MROWS (BB*LL)     // 4096 "token rows"

// ---------------------------------------------------------------------------
// Scratch (device globals — no allocation allowed)
// ---------------------------------------------------------------------------
__device__ float g_xz   [(size_t)BB*LL*2*DI];   // 67 MB: [b,l, 0:2048]=xin, [2048:4096]=z
__device__ float g_u    [(size_t)BB*LL*DI];     // 33.5 MB: silu(conv(xin))
__device__ float g_xdbl [(size_t)BB*LL*NXPP];   // padded x_dbl: cols 0:64 dt_low, 64:80 B, 80:96 C
__device__ float g_dt   [(size_t)BB*LL*DI];     // softplus(dt_low@W_dt + b_dt)
__device__ float g_y    [(size_t)BB*LL*DI];     // scan output (incl. +u*D and *silu(z))
__device__ float g_wxpp [(size_t)DI*NXPP];      // W_xproj padded to 128 cols

// ---------------------------------------------------------------------------
// Generic SGEMM, 128x128x8 tile, 8x8 microtile, 256 threads
// EPI: 0 = plain store, 1 = +bias[col] then softplus, 2 = +E0[row*ldc+col] (residual)
// Requires M%128==0, N%128==0, K%8==0
// ---------------------------------------------------------------------------
template<int EPI>
__global__ __launch_bounds__(256) void sgemm128(
    const float* __restrict__ A, int lda,
    const float* __restrict__ B, int ldb,
    float* __restrict__ C, int ldc,
    int K,
    const float* __restrict__ E0)
{
    constexpr int BM = 128, BN = 128, BK = 8;
    __shared__ float As[BK][BM + 4];
    __shared__ float Bs[BK][BN];

    const int tid = threadIdx.x;
    const int bm = blockIdx.y * BM;
    const int bn = blockIdx.x * BN;

    const int arow = tid >> 1;          // 0..127
    const int acol = (tid & 1) * 4;     // 0 or 4
    const int brow = tid >> 5;          // 0..7
    const int bcol = (tid & 31) * 4;    // 0..124

    const int tr = (tid >> 4) * 8;      // micro-tile row offset
    const int tc = (tid & 15) * 8;      // micro-tile col offset

    float acc[8][8];
    #pragma unroll
    for (int i = 0; i < 8; i++)
        #pragma unroll
        for (int j = 0; j < 8; j++) acc[i][j] = 0.f;

    const float* Aptr = A + (size_t)(bm + arow) * lda + acol;
    const float* Bptr = B + (size_t)brow * ldb + bn + bcol;

    for (int k0 = 0; k0 < K; k0 += BK) {
        float4 av = *(const float4*)Aptr;
        float4 bv = *(const float4*)Bptr;
        As[acol + 0][arow] = av.x;
        As[acol + 1][arow] = av.y;
        As[acol + 2][arow] = av.z;
        As[acol + 3][arow] = av.w;
        *(float4*)&Bs[brow][bcol] = bv;
        __syncthreads();

        Aptr += BK;
        Bptr += (size_t)BK * ldb;

        #pragma unroll
        for (int k = 0; k < BK; k++) {
            float a[8], b[8];
            *(float4*)(a)     = *(const float4*)&As[k][tr];
            *(float4*)(a + 4) = *(const float4*)&As[k][tr + 4];
            *(float4*)(b)     = *(const float4*)&Bs[k][tc];
            *(float4*)(b + 4) = *(const float4*)&Bs[k][tc + 4];
            #pragma unroll
            for (int i = 0; i < 8; i++)
                #pragma unroll
                for (int j = 0; j < 8; j++)
                    acc[i][j] = fmaf(a[i], b[j], acc[i][j]);
        }
        __syncthreads();
    }

    #pragma unroll
    for (int i = 0; i < 8; i++) {
        const size_t row = bm + tr + i;
        #pragma unroll
        for (int j = 0; j < 8; j += 4) {
            const size_t col = bn + tc + j;
            float4 v = make_float4(acc[i][j], acc[i][j+1], acc[i][j+2], acc[i][j+3]);
            if (EPI == 1) {
                v.x += E0[col+0]; v.y += E0[col+1]; v.z += E0[col+2]; v.w += E0[col+3];
                v.x = (v.x > 20.f) ? v.x : log1pf(expf(v.x));
                v.y = (v.y > 20.f) ? v.y : log1pf(expf(v.y));
                v.z = (v.z > 20.f) ? v.z : log1pf(expf(v.z));
                v.w = (v.w > 20.f) ? v.w : log1pf(expf(v.w));
            }
            if (EPI == 2) {
                float4 r = *(const float4*)&E0[row * ldc + col];
                v.x += r.x; v.y += r.y; v.z += r.z; v.w += r.w;
            }
            *(float4*)&C[row * ldc + col] = v;
        }
    }
}

// ---------------------------------------------------------------------------
// SGEMM, 64x64x16 tile, 4x4 microtile, 256 threads (for skinny-N GEMM2)
// Requires M%64==0, N%64==0, K%16==0
// ---------------------------------------------------------------------------
__global__ __launch_bounds__(256) void sgemm64(
    const float* __restrict__ A, int lda,
    const float* __restrict__ B, int ldb,
    float* __restrict__ C, int ldc,
    int K)
{
    constexpr int BM = 64, BN = 64, BK = 16;
    __shared__ float As[BK][BM + 4];
    __shared__ float Bs[BK][BN];

    const int tid = threadIdx.x;
    const int bm = blockIdx.y * BM;
    const int bn = blockIdx.x * BN;

    const int arow = tid >> 2;          // 0..63
    const int acol = (tid & 3) * 4;     // 0..12
    const int brow = tid >> 4;          // 0..15
    const int bcol = (tid & 15) * 4;    // 0..60

    const int tr = (tid >> 4) * 4;
    const int tc = (tid & 15) * 4;

    float acc[4][4];
    #pragma unroll
    for (int i = 0; i < 4; i++)
        #pragma unroll
        for (int j = 0; j < 4; j++) acc[i][j] = 0.f;

    const float* Aptr = A + (size_t)(bm + arow) * lda + acol;
    const float* Bptr = B + (size_t)brow * ldb + bn + bcol;

    for (int k0 = 0; k0 < K; k0 += BK) {
        float4 av = *(const float4*)Aptr;
        float4 bv = *(const float4*)Bptr;
        As[acol + 0][arow] = av.x;
        As[acol + 1][arow] = av.y;
        As[acol + 2][arow] = av.z;
        As[acol + 3][arow] = av.w;
        *(float4*)&Bs[brow][bcol] = bv;
        __syncthreads();

        Aptr += BK;
        Bptr += (size_t)BK * ldb;

        #pragma unroll
        for (int k = 0; k < BK; k++) {
            float a[4], b[4];
            *(float4*)a = *(const float4*)&As[k][tr];
            *(float4*)b = *(const float4*)&Bs[k][tc];
            #pragma unroll
            for (int i = 0; i < 4; i++)
                #pragma unroll
                for (int j = 0; j < 4; j++)
                    acc[i][j] = fmaf(a[i], b[j], acc[i][j]);
        }
        __syncthreads();
    }

    #pragma unroll
    for (int i = 0; i < 4; i++) {
        const size_t row = bm + tr + i;
        float4 v = make_float4(acc[i][0], acc[i][1], acc[i][2], acc[i][3]);
        *(float4*)&C[row * ldc + bn + tc] = v;
    }
}

// ---------------------------------------------------------------------------
// Pad W_xproj [2048,96] -> g_wxpp [2048,128] (zeros in cols 96..127)
// ---------------------------------------------------------------------------
__global__ void pad_wxproj(const float* __restrict__ W)
{
    int idx = blockIdx.x * blockDim.x + threadIdx.x;   // 0 .. 2048*128-1
    if (idx >= DI * NXPP) return;
    int row = idx / NXPP, col = idx % NXPP;
    g_wxpp[idx] = (col < NXP) ? W[row * NXP + col] : 0.f;
}

// ---------------------------------------------------------------------------
// Causal depthwise conv (k=4, left-pad 3) + bias + silu.  xin = g_xz[...,:2048]
// ---------------------------------------------------------------------------
__global__ __launch_bounds__(256) void conv_silu(
    const float* __restrict__ cw, const float* __restrict__ cb)
{
    size_t idx = (size_t)blockIdx.x * blockDim.x + threadIdx.x;
    if (idx >= (size_t)BB * LL * DI) return;
    int d = idx % DI;
    int l = (idx / DI) % LL;
    int b = idx / ((size_t)LL * DI);

    const float* base = g_xz + ((size_t)b * LL) * (2 * DI) + d;
    float acc = cb[d];
    #pragma unroll
    for (int j = 0; j < DCONV; j++) {
        int ls = l - (DCONV - 1) + j;
        if (ls >= 0) acc = fmaf(cw[d * DCONV + j], base[(size_t)ls * (2 * DI)], acc);
    }
    float sig = 1.f / (1.f + __expf(-acc));
    g_u[idx] = acc * sig;
}

// ---------------------------------------------------------------------------
// Selective scan. 4 threads per channel (4 states each), prefetched operands.
// Fuses the +u*D and *silu(z) epilogue. Writes g_y.
// block = 128 threads (32 channels), grid = (DI/32, BB)
// ---------------------------------------------------------------------------
__global__ __launch_bounds__(128) void scan_kernel(
    const float* __restrict__ A_log, const float* __restrict__ Dvec)
{
    const int b  = blockIdx.y;
    const int tid = threadIdx.x;
    const int ch = blockIdx.x * 32 + (tid >> 2);
    const int sg = tid & 3;
    const int n0 = sg * 4;

    float A2[4], h[4] = {0.f, 0.f, 0.f, 0.f};
    #pragma unroll
    for (int j = 0; j < 4; j++)
        A2[j] = -expf(A_log[ch * DS + n0 + j]) * 1.44269504088896f; // * log2(e)
    const float Dv = Dvec[ch];

    const float* dtp = g_dt   + (size_t)b * LL * DI + ch;
    const float* up  = g_u    + (size_t)b * LL * DI + ch;
    const float* zp  = g_xz   + (size_t)b * LL * (2 * DI) + DI + ch;
    const float* bp  = g_xdbl + (size_t)b * LL * NXPP + DR + n0;
    const float* cp  = bp + DS;
    float*       yp  = g_y    + (size_t)b * LL * DI + ch;

    // prefetch t = 0
    float dtv = dtp[0], uv = up[0], zv = zp[0];
    float4 B4 = *(const float4*)bp;
    float4 C4 = *(const float4*)cp;

    for (int t = 0; t < LL; t++) {
        float ndt = 0.f, nu = 0.f, nz = 0.f;
        float4 nB = make_float4(0,0,0,0), nC = nB;
        if (t + 1 < LL) {
            ndt = dtp[(size_t)(t + 1) * DI];
            nu  = up [(size_t)(t + 1) * DI];
            nz  = zp [(size_t)(t + 1) * (2 * DI)];
            nB  = *(const float4*)(bp + (size_t)(t + 1) * NXPP);
            nC  = *(const float4*)(cp + (size_t)(t + 1) * NXPP);
        }

        const float du = dtv * uv;
        const float dA0 = exp2f(dtv * A2[0]);
        const float dA1 = exp2f(dtv * A2[1]);
        const float dA2v = exp2f(dtv * A2[2]);
        const float dA3 = exp2f(dtv * A2[3]);
        h[0] = fmaf(dA0,  h[0], du * B4.x);
        h[1] = fmaf(dA1,  h[1], du * B4.y);
        h[2] = fmaf(dA2v, h[2], du * B4.z);
        h[3] = fmaf(dA3,  h[3], du * B4.w);

        float yv = h[0] * C4.x;
        yv = fmaf(h[1], C4.y, yv);
        yv = fmaf(h[2], C4.z, yv);
        yv = fmaf(h[3], C4.w, yv);
        yv += __shfl_xor_sync(0xffffffffu, yv, 1);
        yv += __shfl_xor_sync(0xffffffffu, yv, 2);

        if (sg == 0) {
            float ys  = fmaf(uv, Dv, yv);
            float sig = 1.f / (1.f + __expf(-zv));
            yp[(size_t)t * DI] = ys * (zv * sig);
        }

        dtv = ndt; uv = nu; zv = nz; B4 = nB; C4 = nC;
    }
}

// ---------------------------------------------------------------------------
// In-place row LayerNorm on d_out (4096 rows x 1024), two-pass, 256 threads
// ---------------------------------------------------------------------------
__global__ __launch_bounds__(256) void ln_kernel(
    float* __restrict__ out, const float* __restrict__ gamma,
    const float* __restrict__ beta)
{
    __shared__ float red[8];
    const int row = blockIdx.x;
    float* p = out + (size_t)row * DM;
    const int tid  = threadIdx.x;
    const int lane = tid & 31;
    const int warp = tid >> 5;

    float v[4], s = 0.f;
    #pragma unroll
    for (int i = 0; i < 4; i++) { v[i] = p[tid + 256 * i]; s += v[i]; }
    #pragma unroll
    for (int o = 16; o > 0; o >>= 1) s += __shfl_xor_sync(0xffffffffu, s, o);
    if (lane == 0) red[warp] = s;
    __syncthreads();
    s = 0.f;
    #pragma unroll
    for (int w = 0; w < 8; w++) s += red[w];
    const float mu = s * (1.f / DM);
    __syncthreads();

    float s2 = 0.f;
    #pragma unroll
    for (int i = 0; i < 4; i++) { float d = v[i] - mu; s2 += d * d; }
    #pragma unroll
    for (int o = 16; o > 0; o >>= 1) s2 += __shfl_xor_sync(0xffffffffu, s2, o);
    if (lane == 0) red[warp] = s2;
    __syncthreads();
    s2 = 0.f;
    #pragma unroll
    for (int w = 0; w < 8; w++) s2 += red[w];
    const float rstd = rsqrtf(s2 * (1.f / DM) + 1e-5f);

    #pragma unroll
    for (int i = 0; i < 4; i++) {
        const int col = tid + 256 * i;
        p[col] = (v[i] - mu) * rstd * gamma[col] + beta[col];
    }
}

// ---------------------------------------------------------------------------
// Launcher
// ---------------------------------------------------------------------------
extern "C" void kernel_launch(void* const* d_in, const int* in_sizes, int n_in,
                              void* d_out, int out_size)
{
    const float* x      = (const float*)d_in[0];   // [2,2048,1024]
    const float* W_in   = (const float*)d_in[1];   // [1024,4096]
    const float* conv_w = (const float*)d_in[2];   // [2048,4]
    const float* conv_b = (const float*)d_in[3];   // [2048]
    const float* W_xprj = (const float*)d_in[4];   // [2048,96]
    const float* W_dt   = (const float*)d_in[5];   // [64,2048]
    const float* b_dt   = (const float*)d_in[6];   // [2048]
    const float* A_log  = (const float*)d_in[7];   // [2048,16]
    const float* Dvec   = (const float*)d_in[8];   // [2048]
    const float* W_out  = (const float*)d_in[9];   // [2048,1024]
    const float* gamma  = (const float*)d_in[10];  // [1024]
    const float* beta   = (const float*)d_in[11];  // [1024]
    float* out = (float*)d_out;                    // [2,2048,1024]

    float* xz   = nullptr; cudaGetSymbolAddress((void**)&xz,   g_xz);
    float* u    = nullptr; cudaGetSymbolAddress((void**)&u,    g_u);
    float* xdbl = nullptr; cudaGetSymbolAddress((void**)&xdbl, g_xdbl);
    float* dt   = nullptr; cudaGetSymbolAddress((void**)&dt,   g_dt);
    float* y    = nullptr; cudaGetSymbolAddress((void**)&y,    g_y);
    float* wxpp = nullptr; cudaGetSymbolAddress((void**)&wxpp, g_wxpp);

    // 0) pad W_xproj
    pad_wxproj<<<(DI * NXPP + 255) / 256, 256>>>(W_xprj);

    // 1) GEMM1: xz = x @ W_in      [4096,1024]x[1024,4096]
    {
        dim3 grid(2 * DI / 128, MROWS / 128);
        sgemm128<0><<<grid, 256>>>(x, DM, W_in, 2 * DI, xz, 2 * DI, DM, nullptr);
    }

    // 2) conv + silu -> u
    {
        size_t n = (size_t)BB * LL * DI;
        conv_silu<<<(unsigned)((n + 255) / 256), 256>>>(conv_w, conv_b);
    }

    // 3) GEMM2: x_dbl = u @ W_xproj(padded)   [4096,2048]x[2048,128]
    {
        dim3 grid(NXPP / 64, MROWS / 64);
        sgemm64<<<grid, 256>>>(u, DI, wxpp, NXPP, xdbl, NXPP, DI);
    }

    // 4) dt = softplus(dt_low @ W_dt + b_dt)  [4096,64]x[64,2048]
    {
        dim3 grid(DI / 128, MROWS / 128);
        sgemm128<1><<<grid, 256>>>(xdbl, NXPP, W_dt, DI, dt, DI, DR, b_dt);
    }

    // 5) selective scan -> y (fused +u*D and *silu(z))
    {
        dim3 grid(DI / 32, BB);
        scan_kernel<<<grid, 128>>>(A_log, Dvec);
    }

    // 6) GEMM3: out = y @ W_out + x          [4096,2048]x[2048,1024]
    {
        dim3 grid(DM / 128, MROWS / 128);
        sgemm128<2><<<grid, 256>>>(y, DI, W_out, DM, out, DM, DI, x);
    }

    // 7) LayerNorm in-place on out
    ln_kernel<<<MROWS, 256>>>(out, gamma, beta);
}

// round 4
// speedup vs baseline: 1.4718x; 1.4718x over previous
#include <cuda_runtime.h>
#include <cuda_bf16.h>
#include <math.h>
#include <stdint.h>
#include <cstdint>

// ---------------------------------------------------------------------------
// Problem constants
// ---------------------------------------------------------------------------
#define BB   2            // batch
#define LL   2048         // seq len
#define DM   1024         // d_model
#define DI   2048         // d_inner
#define DS   16           // d_state
#define DR   64           // dt_rank
#define DCONV 4
#define NXP  96           // dt_rank + 2*d_state
#define NXPP 128          // padded
#define MROWS (BB*LL)     // 4096 "token rows"

// ---------------------------------------------------------------------------
// Scratch (device globals — no allocation allowed)
// ---------------------------------------------------------------------------
__device__ float g_xz   [(size_t)BB*LL*2*DI];   // [b,l, 0:2048]=xin, [2048:4096]=z  (fp32)
__device__ float g_u    [(size_t)BB*LL*DI];     // silu(conv(xin)) fp32 (for scan)
__device__ float g_xdbl [(size_t)BB*LL*NXPP];   // fp32 x_dbl (B,C for scan)
__device__ float g_dt   [(size_t)BB*LL*DI];     // softplus(...) fp32

__device__ __nv_bfloat16 g_xh [(size_t)MROWS*DM];       // x split
__device__ __nv_bfloat16 g_xl [(size_t)MROWS*DM];
__device__ __nv_bfloat16 g_w1h[(size_t)DM*2*DI];        // W_in split
__device__ __nv_bfloat16 g_w1l[(size_t)DM*2*DI];
__device__ __nv_bfloat16 g_uh [(size_t)MROWS*DI];       // u split
__device__ __nv_bfloat16 g_ul [(size_t)MROWS*DI];
__device__ __nv_bfloat16 g_wxh[(size_t)DI*NXPP];        // W_xproj padded split
__device__ __nv_bfloat16 g_wxl[(size_t)DI*NXPP];
__device__ __nv_bfloat16 g_xdh[(size_t)MROWS*NXPP];     // x_dbl split (cols 0..63 used)
__device__ __nv_bfloat16 g_xdl[(size_t)MROWS*NXPP];
__device__ __nv_bfloat16 g_wdh[(size_t)DR*DI];          // W_dt split
__device__ __nv_bfloat16 g_wdl[(size_t)DR*DI];
__device__ __nv_bfloat16 g_yh [(size_t)MROWS*DI];       // y split (scan output)
__device__ __nv_bfloat16 g_yl [(size_t)MROWS*DI];
__device__ __nv_bfloat16 g_woh[(size_t)DI*DM];          // W_out split
__device__ __nv_bfloat16 g_wol[(size_t)DI*DM];

// ---------------------------------------------------------------------------
// PTX helpers
// ---------------------------------------------------------------------------
__device__ __forceinline__ unsigned cvta_s(const void* p) {
    return (unsigned)__cvta_generic_to_shared(p);
}
__device__ __forceinline__ void ldsm4(unsigned* r, unsigned a) {
    asm volatile("ldmatrix.sync.aligned.m8n8.x4.shared.b16 {%0,%1,%2,%3}, [%4];"
        : "=r"(r[0]), "=r"(r[1]), "=r"(r[2]), "=r"(r[3]) : "r"(a));
}
__device__ __forceinline__ void ldsm4t(unsigned* r, unsigned a) {
    asm volatile("ldmatrix.sync.aligned.m8n8.x4.trans.shared.b16 {%0,%1,%2,%3}, [%4];"
        : "=r"(r[0]), "=r"(r[1]), "=r"(r[2]), "=r"(r[3]) : "r"(a));
}
__device__ __forceinline__ void mma16816(float* d, const unsigned* a, const unsigned* b) {
    asm volatile("mma.sync.aligned.m16n8k16.row.col.f32.bf16.bf16.f32 "
        "{%0,%1,%2,%3}, {%4,%5,%6,%7}, {%8,%9}, {%0,%1,%2,%3};"
        : "+f"(d[0]), "+f"(d[1]), "+f"(d[2]), "+f"(d[3])
        : "r"(a[0]), "r"(a[1]), "r"(a[2]), "r"(a[3]), "r"(b[0]), "r"(b[1]));
}

// ---------------------------------------------------------------------------
// Split-bf16 tensor-core GEMM.
//   C[M,N] = Ahi@Bhi + Ahi@Blo + Alo@Bhi   (fp32 accum)
// A row-major [M,lda], B row-major [K,ldb], C row-major [M,ldc].
// CTA tile: BM x 128 x 32, BM = 64*MF. 8 warps (4x2), warp tile (16*MF) x 64.
// EPI: 0 plain fp32; 1 fp32 + bf16 hi/lo (Chi/Clo, same ldc);
//      2 +bias[col] then softplus; 3 +E0[row*ldc+col] residual.
// Requires M%BM==0, N%128==0, K%32==0.
// ---------------------------------------------------------------------------
template<int MF, int EPI>
__global__ __launch_bounds__(256) void gemm_bf16(
    const __nv_bfloat16* __restrict__ Ah, const __nv_bfloat16* __restrict__ Al, int lda,
    const __nv_bfloat16* __restrict__ Bh, const __nv_bfloat16* __restrict__ Bl, int ldb,
    float* __restrict__ C, int ldc, int K,
    const float* __restrict__ E0,
    __nv_bfloat16* __restrict__ Chi, __nv_bfloat16* __restrict__ Clo)
{
    const int BM = 64 * MF;
    const int BN = 128;
    const int BK = 32;
    const int LDA = 40;
    const int LDB = 136;   // padded strides (elements)
    __shared__ __nv_bfloat16 As[2][64 * MF][40];
    __shared__ __nv_bfloat16 Bs[2][32][136];

    const int tid  = threadIdx.x;
    const int lane = tid & 31;
    const int wid  = tid >> 5;
    const int wm   = (wid >> 1) * (16 * MF);
    const int wn   = (wid & 1) * 64;
    const int bm   = blockIdx.y * BM;
    const int bn   = blockIdx.x * BN;

    float acc[MF][8][4];
    #pragma unroll
    for (int i = 0; i < MF; i++) {
        #pragma unroll
        for (int j = 0; j < 8; j++) {
            #pragma unroll
            for (int q = 0; q < 4; q++) acc[i][j][q] = 0.f;
        }
    }

    // ldmatrix smem base addresses
    const unsigned aB0 = cvta_s(&As[0][wm + (lane & 15)][(lane >> 4) << 3]);
    const unsigned aB1 = cvta_s(&As[1][wm + (lane & 15)][(lane >> 4) << 3]);
    const unsigned bB0 = cvta_s(&Bs[0][lane & 15][wn + ((lane >> 4) << 3)]);
    const unsigned bB1 = cvta_s(&Bs[1][lane & 15][wn + ((lane >> 4) << 3)]);

    // gmem staging registers
    uint4 rAh[MF], rAl[MF], rBh[2], rBl[2];

    const int ar = tid >> 2;            // A row within first 64
    const int ac = (tid & 3) * 8;       // A col
    const int br = tid >> 4;            // B row within first 16
    const int bc = (tid & 15) * 8;      // B col

    // ---- prologue load: k0 = 0 ----
    #pragma unroll
    for (int p = 0; p < MF; p++) {
        size_t off = (size_t)(bm + p * 64 + ar) * lda + ac;
        rAh[p] = *(const uint4*)(Ah + off);
        rAl[p] = *(const uint4*)(Al + off);
    }
    #pragma unroll
    for (int p = 0; p < 2; p++) {
        size_t off = (size_t)(p * 16 + br) * ldb + bn + bc;
        rBh[p] = *(const uint4*)(Bh + off);
        rBl[p] = *(const uint4*)(Bl + off);
    }

    for (int k0 = 0; k0 < K; k0 += BK) {
        // ---- store staged tile to smem ----
        #pragma unroll
        for (int p = 0; p < MF; p++) {
            *(uint4*)&As[0][p * 64 + ar][ac] = rAh[p];
            *(uint4*)&As[1][p * 64 + ar][ac] = rAl[p];
        }
        #pragma unroll
        for (int p = 0; p < 2; p++) {
            *(uint4*)&Bs[0][p * 16 + br][bc] = rBh[p];
            *(uint4*)&Bs[1][p * 16 + br][bc] = rBl[p];
        }
        __syncthreads();

        // ---- stage next tile from gmem ----
        if (k0 + BK < K) {
            const int kn = k0 + BK;
            #pragma unroll
            for (int p = 0; p < MF; p++) {
                size_t off = (size_t)(bm + p * 64 + ar) * lda + kn + ac;
                rAh[p] = *(const uint4*)(Ah + off);
                rAl[p] = *(const uint4*)(Al + off);
            }
            #pragma unroll
            for (int p = 0; p < 2; p++) {
                size_t off = (size_t)(kn + p * 16 + br) * ldb + bn + bc;
                rBh[p] = *(const uint4*)(Bh + off);
                rBl[p] = *(const uint4*)(Bl + off);
            }
        }

        // ---- compute on smem tile ----
        #pragma unroll
        for (int s = 0; s < 2; s++) {
            unsigned ahf[MF][4], alf[MF][4];
            #pragma unroll
            for (int mi = 0; mi < MF; mi++) {
                ldsm4(ahf[mi], aB0 + (unsigned)((mi * 16 * LDA + s * 16) * 2));
                ldsm4(alf[mi], aB1 + (unsigned)((mi * 16 * LDA + s * 16) * 2));
            }
            unsigned bhf[8][2], blf[8][2];
            #pragma unroll
            for (int pr = 0; pr < 4; pr++) {
                unsigned t4[4];
                ldsm4t(t4, bB0 + (unsigned)((s * 16 * LDB + pr * 16) * 2));
                bhf[2 * pr][0] = t4[0]; bhf[2 * pr][1] = t4[1];
                bhf[2 * pr + 1][0] = t4[2]; bhf[2 * pr + 1][1] = t4[3];
                ldsm4t(t4, bB1 + (unsigned)((s * 16 * LDB + pr * 16) * 2));
                blf[2 * pr][0] = t4[0]; blf[2 * pr][1] = t4[1];
                blf[2 * pr + 1][0] = t4[2]; blf[2 * pr + 1][1] = t4[3];
            }
            #pragma unroll
            for (int mi = 0; mi < MF; mi++) {
                #pragma unroll
                for (int nj = 0; nj < 8; nj++) {
                    mma16816(acc[mi][nj], ahf[mi], bhf[nj]);
                    mma16816(acc[mi][nj], ahf[mi], blf[nj]);
                    mma16816(acc[mi][nj], alf[mi], bhf[nj]);
                }
            }
        }
        __syncthreads();
    }

    // ---- epilogue ----
    #pragma unroll
    for (int mi = 0; mi < MF; mi++) {
        #pragma unroll
        for (int nj = 0; nj < 8; nj++) {
            const int r0 = bm + wm + mi * 16 + (lane >> 2);
            const int c  = bn + wn + nj * 8 + (lane & 3) * 2;
            #pragma unroll
            for (int hh = 0; hh < 2; hh++) {
                const int r = r0 + hh * 8;
                float vx = acc[mi][nj][2 * hh];
                float vy = acc[mi][nj][2 * hh + 1];
                if (EPI == 2) {
                    vx += E0[c];
                    vy += E0[c + 1];
                    vx = (vx > 20.f) ? vx : log1pf(expf(vx));
                    vy = (vy > 20.f) ? vy : log1pf(expf(vy));
                }
                if (EPI == 3) {
                    const float2 rr = *(const float2*)&E0[(size_t)r * ldc + c];
                    vx += rr.x;
                    vy += rr.y;
                }
                float2 v2; v2.x = vx; v2.y = vy;
                *(float2*)&C[(size_t)r * ldc + c] = v2;
                if (EPI == 1) {
                    __nv_bfloat16 hx = __float2bfloat16(vx);
                    __nv_bfloat16 hy = __float2bfloat16(vy);
                    __nv_bfloat162 hv;
                    hv.x = hx; hv.y = hy;
                    __nv_bfloat162 lv;
                    lv.x = __float2bfloat16(vx - __bfloat162float(hx));
                    lv.y = __float2bfloat16(vy - __bfloat162float(hy));
                    *(__nv_bfloat162*)&Chi[(size_t)r * ldc + c] = hv;
                    *(__nv_bfloat162*)&Clo[(size_t)r * ldc + c] = lv;
                }
            }
        }
    }
}

// ---------------------------------------------------------------------------
// Split fp32 -> bf16 hi/lo (generic)
// ---------------------------------------------------------------------------
__global__ void split_bf16(const float* __restrict__ s,
                           __nv_bfloat16* __restrict__ hi,
                           __nv_bfloat16* __restrict__ lo, int n)
{
    int i = blockIdx.x * blockDim.x + threadIdx.x;
    if (i >= n) return;
    float v = s[i];
    __nv_bfloat16 h = __float2bfloat16(v);
    hi[i] = h;
    lo[i] = __float2bfloat16(v - __bfloat162float(h));
}

// Pad W_xproj [2048,96] -> [2048,128] split
__global__ void pad_split_wxproj(const float* __restrict__ W)
{
    int idx = blockIdx.x * blockDim.x + threadIdx.x;
    if (idx >= DI * NXPP) return;
    int row = idx / NXPP;
    int col = idx % NXPP;
    float v = (col < NXP) ? W[row * NXP + col] : 0.f;
    __nv_bfloat16 h = __float2bfloat16(v);
    g_wxh[idx] = h;
    g_wxl[idx] = __float2bfloat16(v - __bfloat162float(h));
}

// ---------------------------------------------------------------------------
// Causal depthwise conv (k=4) + bias + silu; emits fp32 u and bf16 hi/lo
// ---------------------------------------------------------------------------
__global__ __launch_bounds__(256) void conv_silu(
    const float* __restrict__ cw, const float* __restrict__ cb)
{
    size_t idx = (size_t)blockIdx.x * blockDim.x + threadIdx.x;
    if (idx >= (size_t)BB * LL * DI) return;
    int d = (int)(idx % DI);
    int l = (int)((idx / DI) % LL);
    int b = (int)(idx / ((size_t)LL * DI));

    const float* base = g_xz + ((size_t)b * LL) * (2 * DI) + d;
    float acc = cb[d];
    #pragma unroll
    for (int j = 0; j < DCONV; j++) {
        int ls = l - (DCONV - 1) + j;
        if (ls >= 0) acc = fmaf(cw[d * DCONV + j], base[(size_t)ls * (2 * DI)], acc);
    }
    float sig = 1.f / (1.f + __expf(-acc));
    float v = acc * sig;
    g_u[idx] = v;
    __nv_bfloat16 h = __float2bfloat16(v);
    g_uh[idx] = h;
    g_ul[idx] = __float2bfloat16(v - __bfloat162float(h));
}

// ---------------------------------------------------------------------------
// Selective scan. 4 threads/channel. Emits y as bf16 hi/lo (feeds GEMM3).
// ---------------------------------------------------------------------------
__global__ __launch_bounds__(128) void scan_kernel(
    const float* __restrict__ A_log, const float* __restrict__ Dvec)
{
    const int b   = blockIdx.y;
    const int tid = threadIdx.x;
    const int ch  = blockIdx.x * 32 + (tid >> 2);
    const int sg  = tid & 3;
    const int n0  = sg * 4;

    float Ae[4];
    float hs[4];
    #pragma unroll
    for (int j = 0; j < 4; j++) {
        Ae[j] = -expf(A_log[ch * DS + n0 + j]) * 1.44269504088896f;
        hs[j] = 0.f;
    }
    const float Dv = Dvec[ch];

    const float* dtp = g_dt   + (size_t)b * LL * DI + ch;
    const float* up  = g_u    + (size_t)b * LL * DI + ch;
    const float* zp  = g_xz   + (size_t)b * LL * (2 * DI) + DI + ch;
    const float* bp  = g_xdbl + (size_t)b * LL * NXPP + DR + n0;
    const float* cp  = bp + DS;
    __nv_bfloat16* yph = g_yh + (size_t)b * LL * DI + ch;
    __nv_bfloat16* ypl = g_yl + (size_t)b * LL * DI + ch;

    // prefetch t = 0
    float dtv = dtp[0];
    float uv  = up[0];
    float zv  = zp[0];
    float4 Bv = *(const float4*)bp;
    float4 Cv = *(const float4*)cp;

    for (int t = 0; t < LL; t++) {
        float ndt = 0.f, nuv = 0.f, nzv = 0.f;
        float4 nBv, nCv;
        nBv.x = nBv.y = nBv.z = nBv.w = 0.f;
        nCv = nBv;
        if (t + 1 < LL) {
            ndt = dtp[(size_t)(t + 1) * DI];
            nuv = up [(size_t)(t + 1) * DI];
            nzv = zp [(size_t)(t + 1) * (2 * DI)];
            nBv = *(const float4*)(bp + (size_t)(t + 1) * NXPP);
            nCv = *(const float4*)(cp + (size_t)(t + 1) * NXPP);
        }

        const float du = dtv * uv;
        const float e0 = exp2f(dtv * Ae[0]);
        const float e1 = exp2f(dtv * Ae[1]);
        const float e2 = exp2f(dtv * Ae[2]);
        const float e3 = exp2f(dtv * Ae[3]);
        hs[0] = fmaf(e0, hs[0], du * Bv.x);
        hs[1] = fmaf(e1, hs[1], du * Bv.y);
        hs[2] = fmaf(e2, hs[2], du * Bv.z);
        hs[3] = fmaf(e3, hs[3], du * Bv.w);

        float yv = hs[0] * Cv.x;
        yv = fmaf(hs[1], Cv.y, yv);
        yv = fmaf(hs[2], Cv.z, yv);
        yv = fmaf(hs[3], Cv.w, yv);
        yv += __shfl_xor_sync(0xffffffffu, yv, 1);
        yv += __shfl_xor_sync(0xffffffffu, yv, 2);

        if (sg == 0) {
            float ys  = fmaf(uv, Dv, yv);
            float sig = 1.f / (1.f + __expf(-zv));
            float yo  = ys * (zv * sig);
            __nv_bfloat16 yh16 = __float2bfloat16(yo);
            yph[(size_t)t * DI] = yh16;
            ypl[(size_t)t * DI] = __float2bfloat16(yo - __bfloat162float(yh16));
        }

        dtv = ndt; uv = nuv; zv = nzv; Bv = nBv; Cv = nCv;
    }
}

// ---------------------------------------------------------------------------
// In-place row LayerNorm on d_out (4096 rows x 1024)
// ---------------------------------------------------------------------------
__global__ __launch_bounds__(256) void ln_kernel(
    float* __restrict__ out, const float* __restrict__ gamma,
    const float* __restrict__ beta)
{
    __shared__ float red[8];
    const int row = blockIdx.x;
    float* p = out + (size_t)row * DM;
    const int tid  = threadIdx.x;
    const int lane = tid & 31;
    const int warp = tid >> 5;

    float v[4];
    float s = 0.f;
    #pragma unroll
    for (int i = 0; i < 4; i++) { v[i] = p[tid + 256 * i]; s += v[i]; }
    #pragma unroll
    for (int o = 16; o > 0; o >>= 1) s += __shfl_xor_sync(0xffffffffu, s, o);
    if (lane == 0) red[warp] = s;
    __syncthreads();
    s = 0.f;
    #pragma unroll
    for (int w = 0; w < 8; w++) s += red[w];
    const float mu = s * (1.f / DM);
    __syncthreads();

    float s2 = 0.f;
    #pragma unroll
    for (int i = 0; i < 4; i++) { float d = v[i] - mu; s2 += d * d; }
    #pragma unroll
    for (int o = 16; o > 0; o >>= 1) s2 += __shfl_xor_sync(0xffffffffu, s2, o);
    if (lane == 0) red[warp] = s2;
    __syncthreads();
    s2 = 0.f;
    #pragma unroll
    for (int w = 0; w < 8; w++) s2 += red[w];
    const float rstd = rsqrtf(s2 * (1.f / DM) + 1e-5f);

    #pragma unroll
    for (int i = 0; i < 4; i++) {
        const int col = tid + 256 * i;
        p[col] = (v[i] - mu) * rstd * gamma[col] + beta[col];
    }
}

// ---------------------------------------------------------------------------
// Launcher
// ---------------------------------------------------------------------------
extern "C" void kernel_launch(void* const* d_in, const int* in_sizes, int n_in,
                              void* d_out, int out_size)
{
    const float* x      = (const float*)d_in[0];   // [2,2048,1024]
    const float* W_in   = (const float*)d_in[1];   // [1024,4096]
    const float* conv_w = (const float*)d_in[2];   // [2048,4]
    const float* conv_b = (const float*)d_in[3];   // [2048]
    const float* W_xprj = (const float*)d_in[4];   // [2048,96]
    const float* W_dt   = (const float*)d_in[5];   // [64,2048]
    const float* b_dt   = (const float*)d_in[6];   // [2048]
    const float* A_log  = (const float*)d_in[7];   // [2048,16]
    const float* Dvec   = (const float*)d_in[8];   // [2048]
    const float* W_out  = (const float*)d_in[9];   // [2048,1024]
    const float* gamma  = (const float*)d_in[10];  // [1024]
    const float* beta   = (const float*)d_in[11];  // [1024]
    float* out = (float*)d_out;                    // [2,2048,1024]

    float *xz, *u, *xdbl, *dt;
    cudaGetSymbolAddress((void**)&xz,   g_xz);
    cudaGetSymbolAddress((void**)&u,    g_u);
    cudaGetSymbolAddress((void**)&xdbl, g_xdbl);
    cudaGetSymbolAddress((void**)&dt,   g_dt);
    __nv_bfloat16 *xh, *xl, *w1h, *w1l, *uh, *ul, *wxh, *wxl;
    __nv_bfloat16 *xdh, *xdl, *wdh, *wdl, *yh, *yl, *woh, *wol;
    cudaGetSymbolAddress((void**)&xh,  g_xh);  cudaGetSymbolAddress((void**)&xl,  g_xl);
    cudaGetSymbolAddress((void**)&w1h, g_w1h); cudaGetSymbolAddress((void**)&w1l, g_w1l);
    cudaGetSymbolAddress((void**)&uh,  g_uh);  cudaGetSymbolAddress((void**)&ul,  g_ul);
    cudaGetSymbolAddress((void**)&wxh, g_wxh); cudaGetSymbolAddress((void**)&wxl, g_wxl);
    cudaGetSymbolAddress((void**)&xdh, g_xdh); cudaGetSymbolAddress((void**)&xdl, g_xdl);
    cudaGetSymbolAddress((void**)&wdh, g_wdh); cudaGetSymbolAddress((void**)&wdl, g_wdl);
    cudaGetSymbolAddress((void**)&yh,  g_yh);  cudaGetSymbolAddress((void**)&yl,  g_yl);
    cudaGetSymbolAddress((void**)&woh, g_woh); cudaGetSymbolAddress((void**)&wol, g_wol);

    // 0) conversions
    split_bf16<<<(MROWS * DM + 255) / 256, 256>>>(x, xh, xl, MROWS * DM);
    split_bf16<<<(DM * 2 * DI + 255) / 256, 256>>>(W_in, w1h, w1l, DM * 2 * DI);
    split_bf16<<<(DR * DI + 255) / 256, 256>>>(W_dt, wdh, wdl, DR * DI);
    split_bf16<<<(DI * DM + 255) / 256, 256>>>(W_out, woh, wol, DI * DM);
    pad_split_wxproj<<<(DI * NXPP + 255) / 256, 256>>>(W_xprj);

    // 1) GEMM1: xz = x @ W_in   [4096,1024]x[1024,4096]
    {
        dim3 grid(2 * DI / 128, MROWS / 128);
        gemm_bf16<2, 0><<<grid, 256>>>(xh, xl, DM, w1h, w1l, 2 * DI,
                                       xz, 2 * DI, DM, nullptr, nullptr, nullptr);
    }

    // 2) conv + silu -> u (fp32 + bf16 hi/lo)
    {
        size_t n = (size_t)BB * LL * DI;
        conv_silu<<<(unsigned)((n + 255) / 256), 256>>>(conv_w, conv_b);
    }

    // 3) GEMM2: x_dbl = u @ W_xproj(pad)  [4096,2048]x[2048,128], epi: fp32 + split
    {
        dim3 grid(NXPP / 128, MROWS / 64);
        gemm_bf16<1, 1><<<grid, 256>>>(uh, ul, DI, wxh, wxl, NXPP,
                                       xdbl, NXPP, DI, nullptr, xdh, xdl);
    }

    // 4) dt = softplus(dt_low @ W_dt + b_dt)  [4096,64]x[64,2048]
    {
        dim3 grid(DI / 128, MROWS / 128);
        gemm_bf16<2, 2><<<grid, 256>>>(xdh, xdl, NXPP, wdh, wdl, DI,
                                       dt, DI, DR, b_dt, nullptr, nullptr);
    }

    // 5) selective scan -> y (bf16 hi/lo)
    {
        dim3 grid(DI / 32, BB);
        scan_kernel<<<grid, 128>>>(A_log, Dvec);
    }

    // 6) GEMM3: out = y @ W_out + x   [4096,2048]x[2048,1024]
    {
        dim3 grid(DM / 128, MROWS / 128);
        gemm_bf16<2, 3><<<grid, 256>>>(yh, yl, DI, woh, wol, DM,
                                       out, DM, DI, x, nullptr, nullptr);
    }

    // 7) LayerNorm in-place
    ln_kernel<<<MROWS, 256>>>(out, gamma, beta);
}

// round 5
// speedup vs baseline: 2.2750x; 1.5458x over previous
#include <cuda_runtime.h>
#include <cuda_bf16.h>
#include <math.h>
#include <stdint.h>
#include <cstdint>

// ---------------------------------------------------------------------------
// Problem constants
// ---------------------------------------------------------------------------
#define BB   2            // batch
#define LL   2048         // seq len
#define DM   1024         // d_model
#define DI   2048         // d_inner
#define DS   16           // d_state
#define DR   64           // dt_rank
#define DCONV 4
#define NXP  96           // dt_rank + 2*d_state
#define NXPP 128          // padded
#define MROWS (BB*LL)     // 4096 "token rows"
#define SEG  16           // scan segments
#define SLEN (LL/SEG)     // 128 steps per segment
#define LOG2E 1.44269504088896f

// ---------------------------------------------------------------------------
// Scratch (device globals — no allocation allowed)
// ---------------------------------------------------------------------------
__device__ float g_xz   [(size_t)BB*LL*2*DI];   // [b,l, 0:2048]=xin, [2048:4096]=z
__device__ float g_u    [(size_t)BB*LL*DI];     // silu(conv(xin)) fp32
__device__ float g_xdbl [(size_t)BB*LL*NXPP];   // fp32 x_dbl (B,C for scan)
__device__ float g_dt   [(size_t)BB*LL*DI];     // softplus(...) fp32
__device__ float g_P    [(size_t)BB*SEG*DI*DS]; // per-segment decay
__device__ float g_q    [(size_t)BB*SEG*DI*DS]; // per-segment h from 0
__device__ float g_hin  [(size_t)BB*SEG*DI*DS]; // h at segment entry

__device__ __nv_bfloat16 g_xh [(size_t)MROWS*DM];
__device__ __nv_bfloat16 g_xl [(size_t)MROWS*DM];
__device__ __nv_bfloat16 g_w1h[(size_t)DM*2*DI];
__device__ __nv_bfloat16 g_w1l[(size_t)DM*2*DI];
__device__ __nv_bfloat16 g_uh [(size_t)MROWS*DI];
__device__ __nv_bfloat16 g_ul [(size_t)MROWS*DI];
__device__ __nv_bfloat16 g_wxh[(size_t)DI*NXPP];
__device__ __nv_bfloat16 g_wxl[(size_t)DI*NXPP];
__device__ __nv_bfloat16 g_xdh[(size_t)MROWS*NXPP];
__device__ __nv_bfloat16 g_xdl[(size_t)MROWS*NXPP];
__device__ __nv_bfloat16 g_wdh[(size_t)DR*DI];
__device__ __nv_bfloat16 g_wdl[(size_t)DR*DI];
__device__ __nv_bfloat16 g_yh [(size_t)MROWS*DI];
__device__ __nv_bfloat16 g_yl [(size_t)MROWS*DI];
__device__ __nv_bfloat16 g_woh[(size_t)DI*DM];
__device__ __nv_bfloat16 g_wol[(size_t)DI*DM];

// ---------------------------------------------------------------------------
// PTX helpers
// ---------------------------------------------------------------------------
__device__ __forceinline__ unsigned cvta_s(const void* p) {
    return (unsigned)__cvta_generic_to_shared(p);
}
__device__ __forceinline__ void ldsm4(unsigned* r, unsigned a) {
    asm volatile("ldmatrix.sync.aligned.m8n8.x4.shared.b16 {%0,%1,%2,%3}, [%4];"
        : "=r"(r[0]), "=r"(r[1]), "=r"(r[2]), "=r"(r[3]) : "r"(a));
}
__device__ __forceinline__ void ldsm4t(unsigned* r, unsigned a) {
    asm volatile("ldmatrix.sync.aligned.m8n8.x4.trans.shared.b16 {%0,%1,%2,%3}, [%4];"
        : "=r"(r[0]), "=r"(r[1]), "=r"(r[2]), "=r"(r[3]) : "r"(a));
}
__device__ __forceinline__ void mma16816(float* d, const unsigned* a, const unsigned* b) {
    asm volatile("mma.sync.aligned.m16n8k16.row.col.f32.bf16.bf16.f32 "
        "{%0,%1,%2,%3}, {%4,%5,%6,%7}, {%8,%9}, {%0,%1,%2,%3};"
        : "+f"(d[0]), "+f"(d[1]), "+f"(d[2]), "+f"(d[3])
        : "r"(a[0]), "r"(a[1]), "r"(a[2]), "r"(a[3]), "r"(b[0]), "r"(b[1]));
}
__device__ __forceinline__ void cpa16(void* s, const void* g) {
    unsigned sa = cvta_s(s);
    asm volatile("cp.async.cg.shared.global [%0], [%1], 16;" :: "r"(sa), "l"(g));
}
__device__ __forceinline__ void cpcommit() {
    asm volatile("cp.async.commit_group;");
}
template<int N>
__device__ __forceinline__ void cpwait() {
    asm volatile("cp.async.wait_group %0;" :: "n"(N));
}

// ---------------------------------------------------------------------------
// Split-bf16 tensor-core GEMM with cp.async 2-stage pipeline.
//   C[M,N] = Ahi@Bhi + Ahi@Blo + Alo@Bhi   (fp32 accum)
// CTA tile BMx128x32, BM = 64*MF. 8 warps (4x2), warp tile (16*MF)x64.
// EPI: 0 plain fp32; 1 fp32 + bf16 hi/lo; 2 +bias softplus; 3 +residual.
// Dynamic smem: 2 stages of [Ah BM*40][Al BM*40][Bh 32*136][Bl 32*136] bf16.
// ---------------------------------------------------------------------------
template<int MF, int EPI>
__global__ __launch_bounds__(256) void gemm_bf16(
    const __nv_bfloat16* __restrict__ Ah, const __nv_bfloat16* __restrict__ Al, int lda,
    const __nv_bfloat16* __restrict__ Bh, const __nv_bfloat16* __restrict__ Bl, int ldb,
    float* __restrict__ C, int ldc, int K,
    const float* __restrict__ E0,
    __nv_bfloat16* __restrict__ Chi, __nv_bfloat16* __restrict__ Clo)
{
    const int BM = 64 * MF;
    const int LDA = 40;
    const int LDB = 136;
    const int A_SZ = BM * LDA;          // elements
    const int B_SZ = 32 * LDB;
    const int STAGE = 2 * A_SZ + 2 * B_SZ;

    extern __shared__ __nv_bfloat16 smem[];

    const int tid  = threadIdx.x;
    const int lane = tid & 31;
    const int wid  = tid >> 5;
    const int wm   = (wid >> 1) * (16 * MF);
    const int wn   = (wid & 1) * 64;
    const int bm   = blockIdx.y * BM;
    const int bn   = blockIdx.x * 128;

    // per-stage smem pointers
    __nv_bfloat16* sAh[2]; __nv_bfloat16* sAl[2];
    __nv_bfloat16* sBh[2]; __nv_bfloat16* sBl[2];
    #pragma unroll
    for (int s = 0; s < 2; s++) {
        sAh[s] = smem + s * STAGE;
        sAl[s] = sAh[s] + A_SZ;
        sBh[s] = sAl[s] + A_SZ;
        sBl[s] = sBh[s] + B_SZ;
    }

    float acc[MF][8][4];
    #pragma unroll
    for (int i = 0; i < MF; i++) {
        #pragma unroll
        for (int j = 0; j < 8; j++) {
            #pragma unroll
            for (int q = 0; q < 4; q++) acc[i][j][q] = 0.f;
        }
    }

    // ldmatrix base addresses per stage
    unsigned aBh[2], aBl[2], bBh[2], bBl[2];
    #pragma unroll
    for (int s = 0; s < 2; s++) {
        aBh[s] = cvta_s(sAh[s] + (wm + (lane & 15)) * LDA + ((lane >> 4) << 3));
        aBl[s] = cvta_s(sAl[s] + (wm + (lane & 15)) * LDA + ((lane >> 4) << 3));
        bBh[s] = cvta_s(sBh[s] + (lane & 15) * LDB + wn + ((lane >> 4) << 3));
        bBl[s] = cvta_s(sBl[s] + (lane & 15) * LDB + wn + ((lane >> 4) << 3));
    }

    const int ar = tid >> 2;            // A row within a 64-row group
    const int ac = (tid & 3) * 8;       // A col chunk
    const int br = tid >> 4;            // B row within a 16-row group
    const int bc = (tid & 15) * 8;      // B col chunk

    const int T = K / 32;

    // ---- issue stage for tile t ----
    // (macro-free inline: done twice, prologue + steady state)
    #define ISSUE_TILE(t_)                                                          \
    {                                                                               \
        const int st_ = (t_) & 1;                                                   \
        const int k0_ = (t_) * 32;                                                  \
        _Pragma("unroll")                                                           \
        for (int p = 0; p < MF; p++) {                                              \
            const int row = p * 64 + ar;                                            \
            cpa16(sAh[st_] + row * LDA + ac, Ah + (size_t)(bm + row) * lda + k0_ + ac); \
            cpa16(sAl[st_] + row * LDA + ac, Al + (size_t)(bm + row) * lda + k0_ + ac); \
        }                                                                           \
        _Pragma("unroll")                                                           \
        for (int p = 0; p < 2; p++) {                                               \
            const int row = p * 16 + br;                                            \
            cpa16(sBh[st_] + row * LDB + bc, Bh + (size_t)(k0_ + row) * ldb + bn + bc); \
            cpa16(sBl[st_] + row * LDB + bc, Bl + (size_t)(k0_ + row) * ldb + bn + bc); \
        }                                                                           \
        cpcommit();                                                                 \
    }

    ISSUE_TILE(0);

    for (int t = 0; t < T; t++) {
        if (t + 1 < T) {
            ISSUE_TILE(t + 1);
            cpwait<1>();
        } else {
            cpwait<0>();
        }
        __syncthreads();

        const int st = t & 1;
        #pragma unroll
        for (int s = 0; s < 2; s++) {
            unsigned ahf[MF][4], alf[MF][4];
            #pragma unroll
            for (int mi = 0; mi < MF; mi++) {
                ldsm4(ahf[mi], aBh[st] + (unsigned)((mi * 16 * LDA + s * 16) * 2));
                ldsm4(alf[mi], aBl[st] + (unsigned)((mi * 16 * LDA + s * 16) * 2));
            }
            unsigned bhf[8][2], blf[8][2];
            #pragma unroll
            for (int pr = 0; pr < 4; pr++) {
                unsigned t4[4];
                ldsm4t(t4, bBh[st] + (unsigned)((s * 16 * LDB + pr * 16) * 2));
                bhf[2 * pr][0] = t4[0]; bhf[2 * pr][1] = t4[1];
                bhf[2 * pr + 1][0] = t4[2]; bhf[2 * pr + 1][1] = t4[3];
                ldsm4t(t4, bBl[st] + (unsigned)((s * 16 * LDB + pr * 16) * 2));
                blf[2 * pr][0] = t4[0]; blf[2 * pr][1] = t4[1];
                blf[2 * pr + 1][0] = t4[2]; blf[2 * pr + 1][1] = t4[3];
            }
            #pragma unroll
            for (int mi = 0; mi < MF; mi++) {
                #pragma unroll
                for (int nj = 0; nj < 8; nj++) {
                    mma16816(acc[mi][nj], ahf[mi], bhf[nj]);
                    mma16816(acc[mi][nj], ahf[mi], blf[nj]);
                    mma16816(acc[mi][nj], alf[mi], bhf[nj]);
                }
            }
        }
        __syncthreads();
    }
    #undef ISSUE_TILE

    // ---- epilogue ----
    #pragma unroll
    for (int mi = 0; mi < MF; mi++) {
        #pragma unroll
        for (int nj = 0; nj < 8; nj++) {
            const int r0 = bm + wm + mi * 16 + (lane >> 2);
            const int c  = bn + wn + nj * 8 + (lane & 3) * 2;
            #pragma unroll
            for (int hh = 0; hh < 2; hh++) {
                const int r = r0 + hh * 8;
                float vx = acc[mi][nj][2 * hh];
                float vy = acc[mi][nj][2 * hh + 1];
                if (EPI == 2) {
                    vx += E0[c];
                    vy += E0[c + 1];
                    vx = (vx > 20.f) ? vx : log1pf(expf(vx));
                    vy = (vy > 20.f) ? vy : log1pf(expf(vy));
                }
                if (EPI == 3) {
                    const float2 rr = *(const float2*)&E0[(size_t)r * ldc + c];
                    vx += rr.x;
                    vy += rr.y;
                }
                float2 v2; v2.x = vx; v2.y = vy;
                *(float2*)&C[(size_t)r * ldc + c] = v2;
                if (EPI == 1) {
                    __nv_bfloat16 hx = __float2bfloat16(vx);
                    __nv_bfloat16 hy = __float2bfloat16(vy);
                    __nv_bfloat162 hv; hv.x = hx; hv.y = hy;
                    __nv_bfloat162 lv;
                    lv.x = __float2bfloat16(vx - __bfloat162float(hx));
                    lv.y = __float2bfloat16(vy - __bfloat162float(hy));
                    *(__nv_bfloat162*)&Chi[(size_t)r * ldc + c] = hv;
                    *(__nv_bfloat162*)&Clo[(size_t)r * ldc + c] = lv;
                }
            }
        }
    }
}

// ---------------------------------------------------------------------------
// Split fp32 -> bf16 hi/lo
// ---------------------------------------------------------------------------
__global__ void split_bf16(const float* __restrict__ s,
                           __nv_bfloat16* __restrict__ hi,
                           __nv_bfloat16* __restrict__ lo, int n)
{
    int i = blockIdx.x * blockDim.x + threadIdx.x;
    if (i >= n) return;
    float v = s[i];
    __nv_bfloat16 h = __float2bfloat16(v);
    hi[i] = h;
    lo[i] = __float2bfloat16(v - __bfloat162float(h));
}

__global__ void pad_split_wxproj(const float* __restrict__ W)
{
    int idx = blockIdx.x * blockDim.x + threadIdx.x;
    if (idx >= DI * NXPP) return;
    int row = idx / NXPP;
    int col = idx % NXPP;
    float v = (col < NXP) ? W[row * NXP + col] : 0.f;
    __nv_bfloat16 h = __float2bfloat16(v);
    g_wxh[idx] = h;
    g_wxl[idx] = __float2bfloat16(v - __bfloat162float(h));
}

// ---------------------------------------------------------------------------
// Causal depthwise conv (k=4) + bias + silu; emits fp32 u and bf16 hi/lo
// ---------------------------------------------------------------------------
__global__ __launch_bounds__(256) void conv_silu(
    const float* __restrict__ cw, const float* __restrict__ cb)
{
    size_t idx = (size_t)blockIdx.x * blockDim.x + threadIdx.x;
    if (idx >= (size_t)BB * LL * DI) return;
    int d = (int)(idx % DI);
    int l = (int)((idx / DI) % LL);
    int b = (int)(idx / ((size_t)LL * DI));

    const float* base = g_xz + ((size_t)b * LL) * (2 * DI) + d;
    float acc = cb[d];
    #pragma unroll
    for (int j = 0; j < DCONV; j++) {
        int ls = l - (DCONV - 1) + j;
        if (ls >= 0) acc = fmaf(cw[d * DCONV + j], base[(size_t)ls * (2 * DI)], acc);
    }
    float sig = 1.f / (1.f + __expf(-acc));
    float v = acc * sig;
    g_u[idx] = v;
    __nv_bfloat16 h = __float2bfloat16(v);
    g_uh[idx] = h;
    g_ul[idx] = __float2bfloat16(v - __bfloat162float(h));
}

// ---------------------------------------------------------------------------
// Segmented selective scan, pass 1: per-segment (P, q) with h0 = 0.
// block: 128 threads = 32 channels x 4 state-quads. grid (DI/32, SEG, BB).
// ---------------------------------------------------------------------------
__global__ __launch_bounds__(128) void scan_pass1(const float* __restrict__ A_log)
{
    __shared__ float sdt[SLEN][32];
    __shared__ float su [SLEN][32];
    __shared__ float sB [SLEN][16];

    const int b   = blockIdx.z;
    const int seg = blockIdx.y;
    const int chB = blockIdx.x * 32;
    const int tid = threadIdx.x;
    const size_t rowBase = (size_t)b * LL + (size_t)seg * SLEN;

    for (int i = tid; i < SLEN * 32; i += 128) {
        int t = i >> 5, c = i & 31;
        sdt[t][c] = g_dt[(rowBase + t) * DI + chB + c];
        su [t][c] = g_u [(rowBase + t) * DI + chB + c];
    }
    for (int i = tid; i < SLEN * 16; i += 128) {
        int t = i >> 4, c = i & 15;
        sB[t][c] = g_xdbl[(rowBase + t) * NXPP + DR + c];
    }
    __syncthreads();

    const int chl = tid >> 2;
    const int ch  = chB + chl;
    const int n0  = (tid & 3) * 4;

    float Ae[4], h[4];
    #pragma unroll
    for (int j = 0; j < 4; j++) {
        Ae[j] = -expf(A_log[ch * DS + n0 + j]) * LOG2E;
        h[j] = 0.f;
    }
    float sumdt = 0.f;

    for (int t = 0; t < SLEN; t++) {
        const float dtv = sdt[t][chl];
        const float uv  = su[t][chl];
        const float du  = dtv * uv;
        sumdt += dtv;
        float4 B4 = *(const float4*)&sB[t][n0];
        h[0] = fmaf(exp2f(dtv * Ae[0]), h[0], du * B4.x);
        h[1] = fmaf(exp2f(dtv * Ae[1]), h[1], du * B4.y);
        h[2] = fmaf(exp2f(dtv * Ae[2]), h[2], du * B4.z);
        h[3] = fmaf(exp2f(dtv * Ae[3]), h[3], du * B4.w);
    }

    const size_t o = (((size_t)b * SEG + seg) * DI + ch) * DS + n0;
    float4 P4, q4;
    P4.x = exp2f(sumdt * Ae[0]); P4.y = exp2f(sumdt * Ae[1]);
    P4.z = exp2f(sumdt * Ae[2]); P4.w = exp2f(sumdt * Ae[3]);
    q4.x = h[0]; q4.y = h[1]; q4.z = h[2]; q4.w = h[3];
    *(float4*)&g_P[o] = P4;
    *(float4*)&g_q[o] = q4;
}

// ---------------------------------------------------------------------------
// Pass 2: sequential combine across the 16 segments (per (b,ch,state)).
// ---------------------------------------------------------------------------
__global__ void scan_combine()
{
    int idx = blockIdx.x * blockDim.x + threadIdx.x;   // over BB*DI*DS
    if (idx >= BB * DI * DS) return;
    int n  = idx % DS;
    int ch = (idx / DS) % DI;
    int b  = idx / (DS * DI);
    float h = 0.f;
    for (int s = 0; s < SEG; s++) {
        size_t o = (((size_t)b * SEG + s) * DI + ch) * DS + n;
        g_hin[o] = h;
        h = g_P[o] * h + g_q[o];
    }
}

// ---------------------------------------------------------------------------
// Pass 3: rescan each segment from h_in, emit y (bf16 hi/lo, fused epilogue).
// Dynamic smem: sdt/su/sz [SLEN][32] + sB/sC [SLEN][16] = 64 KB.
// ---------------------------------------------------------------------------
__global__ __launch_bounds__(128) void scan_pass3(
    const float* __restrict__ A_log, const float* __restrict__ Dvec)
{
    extern __shared__ float sm3[];
    float (*sdt)[32] = (float(*)[32])sm3;
    float (*su )[32] = (float(*)[32])(sm3 + SLEN * 32);
    float (*sz )[32] = (float(*)[32])(sm3 + 2 * SLEN * 32);
    float (*sB )[16] = (float(*)[16])(sm3 + 3 * SLEN * 32);
    float (*sC )[16] = (float(*)[16])(sm3 + 3 * SLEN * 32 + SLEN * 16);

    const int b   = blockIdx.z;
    const int seg = blockIdx.y;
    const int chB = blockIdx.x * 32;
    const int tid = threadIdx.x;
    const size_t rowBase = (size_t)b * LL + (size_t)seg * SLEN;

    for (int i = tid; i < SLEN * 32; i += 128) {
        int t = i >> 5, c = i & 31;
        sdt[t][c] = g_dt[(rowBase + t) * DI + chB + c];
        su [t][c] = g_u [(rowBase + t) * DI + chB + c];
        sz [t][c] = g_xz[(rowBase + t) * (2 * DI) + DI + chB + c];
    }
    for (int i = tid; i < SLEN * 16; i += 128) {
        int t = i >> 4, c = i & 15;
        sB[t][c] = g_xdbl[(rowBase + t) * NXPP + DR + c];
        sC[t][c] = g_xdbl[(rowBase + t) * NXPP + DR + DS + c];
    }
    __syncthreads();

    const int chl = tid >> 2;
    const int ch  = chB + chl;
    const int sg  = tid & 3;
    const int n0  = sg * 4;

    float Ae[4], h[4];
    #pragma unroll
    for (int j = 0; j < 4; j++)
        Ae[j] = -expf(A_log[ch * DS + n0 + j]) * LOG2E;
    {
        const size_t o = (((size_t)b * SEG + seg) * DI + ch) * DS + n0;
        float4 h4 = *(const float4*)&g_hin[o];
        h[0] = h4.x; h[1] = h4.y; h[2] = h4.z; h[3] = h4.w;
    }
    const float Dv = Dvec[ch];

    __nv_bfloat16* yph = g_yh + rowBase * DI + ch;
    __nv_bfloat16* ypl = g_yl + rowBase * DI + ch;

    for (int t = 0; t < SLEN; t++) {
        const float dtv = sdt[t][chl];
        const float uv  = su[t][chl];
        const float du  = dtv * uv;
        float4 B4 = *(const float4*)&sB[t][n0];
        float4 C4 = *(const float4*)&sC[t][n0];
        h[0] = fmaf(exp2f(dtv * Ae[0]), h[0], du * B4.x);
        h[1] = fmaf(exp2f(dtv * Ae[1]), h[1], du * B4.y);
        h[2] = fmaf(exp2f(dtv * Ae[2]), h[2], du * B4.z);
        h[3] = fmaf(exp2f(dtv * Ae[3]), h[3], du * B4.w);

        float yv = h[0] * C4.x;
        yv = fmaf(h[1], C4.y, yv);
        yv = fmaf(h[2], C4.z, yv);
        yv = fmaf(h[3], C4.w, yv);
        yv += __shfl_xor_sync(0xffffffffu, yv, 1);
        yv += __shfl_xor_sync(0xffffffffu, yv, 2);

        if (sg == 0) {
            const float zv  = sz[t][chl];
            const float ys  = fmaf(uv, Dv, yv);
            const float sig = 1.f / (1.f + __expf(-zv));
            const float yo  = ys * (zv * sig);
            __nv_bfloat16 yh16 = __float2bfloat16(yo);
            yph[(size_t)t * DI] = yh16;
            ypl[(size_t)t * DI] = __float2bfloat16(yo - __bfloat162float(yh16));
        }
    }
}

// ---------------------------------------------------------------------------
// In-place row LayerNorm on d_out (4096 rows x 1024)
// ---------------------------------------------------------------------------
__global__ __launch_bounds__(256) void ln_kernel(
    float* __restrict__ out, const float* __restrict__ gamma,
    const float* __restrict__ beta)
{
    __shared__ float red[8];
    const int row = blockIdx.x;
    float* p = out + (size_t)row * DM;
    const int tid  = threadIdx.x;
    const int lane = tid & 31;
    const int warp = tid >> 5;

    float v[4];
    float s = 0.f;
    #pragma unroll
    for (int i = 0; i < 4; i++) { v[i] = p[tid + 256 * i]; s += v[i]; }
    #pragma unroll
    for (int o = 16; o > 0; o >>= 1) s += __shfl_xor_sync(0xffffffffu, s, o);
    if (lane == 0) red[warp] = s;
    __syncthreads();
    s = 0.f;
    #pragma unroll
    for (int w = 0; w < 8; w++) s += red[w];
    const float mu = s * (1.f / DM);
    __syncthreads();

    float s2 = 0.f;
    #pragma unroll
    for (int i = 0; i < 4; i++) { float d = v[i] - mu; s2 += d * d; }
    #pragma unroll
    for (int o = 16; o > 0; o >>= 1) s2 += __shfl_xor_sync(0xffffffffu, s2, o);
    if (lane == 0) red[warp] = s2;
    __syncthreads();
    s2 = 0.f;
    #pragma unroll
    for (int w = 0; w < 8; w++) s2 += red[w];
    const float rstd = rsqrtf(s2 * (1.f / DM) + 1e-5f);

    #pragma unroll
    for (int i = 0; i < 4; i++) {
        const int col = tid + 256 * i;
        p[col] = (v[i] - mu) * rstd * gamma[col] + beta[col];
    }
}

// ---------------------------------------------------------------------------
// Launcher
// ---------------------------------------------------------------------------
extern "C" void kernel_launch(void* const* d_in, const int* in_sizes, int n_in,
                              void* d_out, int out_size)
{
    const float* x      = (const float*)d_in[0];
    const float* W_in   = (const float*)d_in[1];
    const float* conv_w = (const float*)d_in[2];
    const float* conv_b = (const float*)d_in[3];
    const float* W_xprj = (const float*)d_in[4];
    const float* W_dt   = (const float*)d_in[5];
    const float* b_dt   = (const float*)d_in[6];
    const float* A_log  = (const float*)d_in[7];
    const float* Dvec   = (const float*)d_in[8];
    const float* W_out  = (const float*)d_in[9];
    const float* gamma  = (const float*)d_in[10];
    const float* beta   = (const float*)d_in[11];
    float* out = (float*)d_out;

    float *xz, *u, *xdbl, *dt;
    cudaGetSymbolAddress((void**)&xz,   g_xz);
    cudaGetSymbolAddress((void**)&u,    g_u);
    cudaGetSymbolAddress((void**)&xdbl, g_xdbl);
    cudaGetSymbolAddress((void**)&dt,   g_dt);
    __nv_bfloat16 *xh, *xl, *w1h, *w1l, *uh, *ul, *wxh, *wxl;
    __nv_bfloat16 *xdh, *xdl, *wdh, *wdl, *yh, *yl, *woh, *wol;
    cudaGetSymbolAddress((void**)&xh,  g_xh);  cudaGetSymbolAddress((void**)&xl,  g_xl);
    cudaGetSymbolAddress((void**)&w1h, g_w1h); cudaGetSymbolAddress((void**)&w1l, g_w1l);
    cudaGetSymbolAddress((void**)&uh,  g_uh);  cudaGetSymbolAddress((void**)&ul,  g_ul);
    cudaGetSymbolAddress((void**)&wxh, g_wxh); cudaGetSymbolAddress((void**)&wxl, g_wxl);
    cudaGetSymbolAddress((void**)&xdh, g_xdh); cudaGetSymbolAddress((void**)&xdl, g_xdl);
    cudaGetSymbolAddress((void**)&wdh, g_wdh); cudaGetSymbolAddress((void**)&wdl, g_wdl);
    cudaGetSymbolAddress((void**)&yh,  g_yh);  cudaGetSymbolAddress((void**)&yl,  g_yl);
    cudaGetSymbolAddress((void**)&woh, g_woh); cudaGetSymbolAddress((void**)&wol, g_wol);

    // dynamic smem sizes (bytes) per GEMM instantiation
    const int SM_MF2 = 2 * (2 * 128 * 40 + 2 * 32 * 136) * 2;   // 75776
    const int SM_MF1 = 2 * (2 * 64 * 40 + 2 * 32 * 136) * 2;    // 55296
    const int SM_P3  = (3 * SLEN * 32 + 2 * SLEN * 16) * 4;     // 65536
    cudaFuncSetAttribute(gemm_bf16<2,0>, cudaFuncAttributeMaxDynamicSharedMemorySize, SM_MF2);
    cudaFuncSetAttribute(gemm_bf16<1,1>, cudaFuncAttributeMaxDynamicSharedMemorySize, SM_MF1);
    cudaFuncSetAttribute(gemm_bf16<2,2>, cudaFuncAttributeMaxDynamicSharedMemorySize, SM_MF2);
    cudaFuncSetAttribute(gemm_bf16<2,3>, cudaFuncAttributeMaxDynamicSharedMemorySize, SM_MF2);
    cudaFuncSetAttribute(scan_pass3,     cudaFuncAttributeMaxDynamicSharedMemorySize, SM_P3);

    // 0) conversions
    split_bf16<<<(MROWS * DM + 255) / 256, 256>>>(x, xh, xl, MROWS * DM);
    split_bf16<<<(DM * 2 * DI + 255) / 256, 256>>>(W_in, w1h, w1l, DM * 2 * DI);
    split_bf16<<<(DR * DI + 255) / 256, 256>>>(W_dt, wdh, wdl, DR * DI);
    split_bf16<<<(DI * DM + 255) / 256, 256>>>(W_out, woh, wol, DI * DM);
    pad_split_wxproj<<<(DI * NXPP + 255) / 256, 256>>>(W_xprj);

    // 1) GEMM1: xz = x @ W_in
    {
        dim3 grid(2 * DI / 128, MROWS / 128);
        gemm_bf16<2, 0><<<grid, 256, SM_MF2>>>(xh, xl, DM, w1h, w1l, 2 * DI,
                                               xz, 2 * DI, DM, nullptr, nullptr, nullptr);
    }

    // 2) conv + silu -> u
    {
        size_t n = (size_t)BB * LL * DI;
        conv_silu<<<(unsigned)((n + 255) / 256), 256>>>(conv_w, conv_b);
    }

    // 3) GEMM2: x_dbl = u @ W_xproj(pad)
    {
        dim3 grid(NXPP / 128, MROWS / 64);
        gemm_bf16<1, 1><<<grid, 256, SM_MF1>>>(uh, ul, DI, wxh, wxl, NXPP,
                                               xdbl, NXPP, DI, nullptr, xdh, xdl);
    }

    // 4) dt = softplus(dt_low @ W_dt + b_dt)
    {
        dim3 grid(DI / 128, MROWS / 128);
        gemm_bf16<2, 2><<<grid, 256, SM_MF2>>>(xdh, xdl, NXPP, wdh, wdl, DI,
                                               dt, DI, DR, b_dt, nullptr, nullptr);
    }

    // 5) segmented selective scan -> y (bf16 hi/lo)
    {
        dim3 grid(DI / 32, SEG, BB);
        scan_pass1<<<grid, 128>>>(A_log);
        scan_combine<<<(BB * DI * DS + 255) / 256, 256>>>();
        scan_pass3<<<grid, 128, SM_P3>>>(A_log, Dvec);
    }

    // 6) GEMM3: out = y @ W_out + x
    {
        dim3 grid(DM / 128, MROWS / 128);
        gemm_bf16<2, 3><<<grid, 256, SM_MF2>>>(yh, yl, DI, woh, wol, DM,
                                               out, DM, DI, x, nullptr, nullptr);
    }

    // 7) LayerNorm in-place
    ln_kernel<<<MROWS, 256>>>(out, gamma, beta);
}

// round 8
// speedup vs baseline: 3.4469x; 1.5151x over previous
#include <cuda_runtime.h>
#include <cuda_bf16.h>
#include <math.h>
#include <stdint.h>
#include <cstdint>

// ---------------------------------------------------------------------------
// Problem constants
// ---------------------------------------------------------------------------
#define BB   2
#define LL   2048
#define DM   1024
#define DI   2048
#define DS   16
#define DR   64
#define DCONV 4
#define NXP  96
#define NXPP 128
#define MROWS (BB*LL)
#define SEG  16
#define SLEN (LL/SEG)
#define LOG2E 1.44269504088896f

// ---------------------------------------------------------------------------
// Scratch (device globals — no allocation allowed)
// ---------------------------------------------------------------------------
__device__ float g_xz   [(size_t)BB*LL*2*DI];
__device__ float g_u    [(size_t)BB*LL*DI];
__device__ float g_xdbl [(size_t)BB*LL*NXPP];
__device__ float g_dt   [(size_t)BB*LL*DI];
__device__ float g_P    [(size_t)BB*SEG*DI*DS];
__device__ float g_q    [(size_t)BB*SEG*DI*DS];
__device__ float g_hin  [(size_t)BB*SEG*DI*DS];

__device__ __nv_bfloat16 g_xh [(size_t)MROWS*DM];    // x (1-term)
__device__ __nv_bfloat16 g_w1h[(size_t)DM*2*DI];     // W_in (1-term)
__device__ __nv_bfloat16 g_uh [(size_t)MROWS*DI];    // u hi
__device__ __nv_bfloat16 g_ul [(size_t)MROWS*DI];    // u lo (GEMM2 3-term)
__device__ __nv_bfloat16 g_wxh[(size_t)DI*NXPP];     // W_xproj padded hi
__device__ __nv_bfloat16 g_wxl[(size_t)DI*NXPP];     // lo
__device__ __nv_bfloat16 g_xdh[(size_t)MROWS*NXPP];  // x_dbl hi
__device__ __nv_bfloat16 g_xdl[(size_t)MROWS*NXPP];  // lo
__device__ __nv_bfloat16 g_wdh[(size_t)DR*DI];       // W_dt hi
__device__ __nv_bfloat16 g_wdl[(size_t)DR*DI];       // lo
__device__ __nv_bfloat16 g_yh [(size_t)MROWS*DI];    // y (1-term)
__device__ __nv_bfloat16 g_woh[(size_t)DI*DM];       // W_out (1-term)

// ---------------------------------------------------------------------------
// PTX helpers
// ---------------------------------------------------------------------------
__device__ __forceinline__ unsigned cvta_s(const void* p) {
    return (unsigned)__cvta_generic_to_shared(p);
}
__device__ __forceinline__ void ldsm4(unsigned* r, unsigned a) {
    asm volatile("ldmatrix.sync.aligned.m8n8.x4.shared.b16 {%0,%1,%2,%3}, [%4];"
        : "=r"(r[0]), "=r"(r[1]), "=r"(r[2]), "=r"(r[3]) : "r"(a));
}
__device__ __forceinline__ void ldsm4t(unsigned* r, unsigned a) {
    asm volatile("ldmatrix.sync.aligned.m8n8.x4.trans.shared.b16 {%0,%1,%2,%3}, [%4];"
        : "=r"(r[0]), "=r"(r[1]), "=r"(r[2]), "=r"(r[3]) : "r"(a));
}
__device__ __forceinline__ void mma16816(float* d, const unsigned* a, const unsigned* b) {
    asm volatile("mma.sync.aligned.m16n8k16.row.col.f32.bf16.bf16.f32 "
        "{%0,%1,%2,%3}, {%4,%5,%6,%7}, {%8,%9}, {%0,%1,%2,%3};"
        : "+f"(d[0]), "+f"(d[1]), "+f"(d[2]), "+f"(d[3])
        : "r"(a[0]), "r"(a[1]), "r"(a[2]), "r"(a[3]), "r"(b[0]), "r"(b[1]));
}
__device__ __forceinline__ void cpa16(void* s, const void* g) {
    unsigned sa = cvta_s(s);
    asm volatile("cp.async.cg.shared.global [%0], [%1], 16;" :: "r"(sa), "l"(g));
}
__device__ __forceinline__ void cpcommit() {
    asm volatile("cp.async.commit_group;");
}
template<int N>
__device__ __forceinline__ void cpwait() {
    asm volatile("cp.async.wait_group %0;" :: "n"(N));
}

// ---------------------------------------------------------------------------
// bf16 tensor-core GEMM, cp.async 2-stage pipeline.
// NT=1: C = Ah@Bh.   NT=3: C = Ah@Bh + Ah@Bl + Al@Bh (error-compensated).
// A row-major [M,lda], B row-major [K,ldb], C row-major [M,ldc].
// CTA tile BMx128x32, BM = 64*MF. 8 warps (4x2), warp tile (16*MF)x64.
// EPI: 0 plain fp32; 1 fp32 + bf16 hi/lo; 2 +bias softplus; 3 +residual.
// ---------------------------------------------------------------------------
template<int MF, int EPI, int NT>
__global__ __launch_bounds__(256) void gemm_bf16(
    const __nv_bfloat16* __restrict__ Ah, const __nv_bfloat16* __restrict__ Al, int lda,
    const __nv_bfloat16* __restrict__ Bh, const __nv_bfloat16* __restrict__ Bl, int ldb,
    float* __restrict__ C, int ldc, int K,
    const float* __restrict__ E0,
    __nv_bfloat16* __restrict__ Chi, __nv_bfloat16* __restrict__ Clo)
{
    const int BM = 64 * MF;
    const int LDA = 40;
    const int LDB = 136;
    const int A_SZ = BM * LDA;
    const int B_SZ = 32 * LDB;
    const int NL = (NT == 3) ? 2 : 1;
    const int STAGE = NL * (A_SZ + B_SZ);

    extern __shared__ __nv_bfloat16 smem[];

    const int tid  = threadIdx.x;
    const int lane = tid & 31;
    const int wid  = tid >> 5;
    const int wm   = (wid >> 1) * (16 * MF);
    const int wn   = (wid & 1) * 64;
    const int bm   = blockIdx.y * BM;
    const int bn   = blockIdx.x * 128;

    __nv_bfloat16* sAh[2]; __nv_bfloat16* sAl[2];
    __nv_bfloat16* sBh[2]; __nv_bfloat16* sBl[2];
    #pragma unroll
    for (int s = 0; s < 2; s++) {
        sAh[s] = smem + s * STAGE;
        sAl[s] = sAh[s] + A_SZ;                 // only valid when NT==3
        sBh[s] = sAh[s] + NL * A_SZ;
        sBl[s] = sBh[s] + B_SZ;                 // only valid when NT==3
    }

    float acc[MF][8][4];
    #pragma unroll
    for (int i = 0; i < MF; i++) {
        #pragma unroll
        for (int j = 0; j < 8; j++) {
            #pragma unroll
            for (int q = 0; q < 4; q++) acc[i][j][q] = 0.f;
        }
    }

    unsigned aBh[2], aBl[2], bBh[2], bBl[2];
    #pragma unroll
    for (int s = 0; s < 2; s++) {
        aBh[s] = cvta_s(sAh[s] + (wm + (lane & 15)) * LDA + ((lane >> 4) << 3));
        bBh[s] = cvta_s(sBh[s] + (lane & 15) * LDB + wn + ((lane >> 4) << 3));
        if (NT == 3) {
            aBl[s] = cvta_s(sAl[s] + (wm + (lane & 15)) * LDA + ((lane >> 4) << 3));
            bBl[s] = cvta_s(sBl[s] + (lane & 15) * LDB + wn + ((lane >> 4) << 3));
        }
    }

    const int ar = tid >> 2;
    const int ac = (tid & 3) * 8;
    const int br = tid >> 4;
    const int bc = (tid & 15) * 8;

    const int T = K / 32;

    #define ISSUE_TILE(t_)                                                          \
    {                                                                               \
        const int st_ = (t_) & 1;                                                   \
        const int k0_ = (t_) * 32;                                                  \
        _Pragma("unroll")                                                           \
        for (int p = 0; p < MF; p++) {                                              \
            const int row = p * 64 + ar;                                            \
            cpa16(sAh[st_] + row * LDA + ac, Ah + (size_t)(bm + row) * lda + k0_ + ac); \
            if (NT == 3)                                                            \
                cpa16(sAl[st_] + row * LDA + ac, Al + (size_t)(bm + row) * lda + k0_ + ac); \
        }                                                                           \
        _Pragma("unroll")                                                           \
        for (int p = 0; p < 2; p++) {                                               \
            const int row = p * 16 + br;                                            \
            cpa16(sBh[st_] + row * LDB + bc, Bh + (size_t)(k0_ + row) * ldb + bn + bc); \
            if (NT == 3)                                                            \
                cpa16(sBl[st_] + row * LDB + bc, Bl + (size_t)(k0_ + row) * ldb + bn + bc); \
        }                                                                           \
        cpcommit();                                                                 \
    }

    ISSUE_TILE(0);

    for (int t = 0; t < T; t++) {
        if (t + 1 < T) {
            ISSUE_TILE(t + 1);
            cpwait<1>();
        } else {
            cpwait<0>();
        }
        __syncthreads();

        const int st = t & 1;
        #pragma unroll
        for (int s = 0; s < 2; s++) {
            unsigned ahf[MF][4], alf[MF][4];
            #pragma unroll
            for (int mi = 0; mi < MF; mi++) {
                ldsm4(ahf[mi], aBh[st] + (unsigned)((mi * 16 * LDA + s * 16) * 2));
                if (NT == 3)
                    ldsm4(alf[mi], aBl[st] + (unsigned)((mi * 16 * LDA + s * 16) * 2));
            }
            unsigned bhf[8][2], blf[8][2];
            #pragma unroll
            for (int pr = 0; pr < 4; pr++) {
                unsigned t4[4];
                ldsm4t(t4, bBh[st] + (unsigned)((s * 16 * LDB + pr * 16) * 2));
                bhf[2 * pr][0] = t4[0]; bhf[2 * pr][1] = t4[1];
                bhf[2 * pr + 1][0] = t4[2]; bhf[2 * pr + 1][1] = t4[3];
                if (NT == 3) {
                    ldsm4t(t4, bBl[st] + (unsigned)((s * 16 * LDB + pr * 16) * 2));
                    blf[2 * pr][0] = t4[0]; blf[2 * pr][1] = t4[1];
                    blf[2 * pr + 1][0] = t4[2]; blf[2 * pr + 1][1] = t4[3];
                }
            }
            #pragma unroll
            for (int mi = 0; mi < MF; mi++) {
                #pragma unroll
                for (int nj = 0; nj < 8; nj++) {
                    mma16816(acc[mi][nj], ahf[mi], bhf[nj]);
                    if (NT == 3) {
                        mma16816(acc[mi][nj], ahf[mi], blf[nj]);
                        mma16816(acc[mi][nj], alf[mi], bhf[nj]);
                    }
                }
            }
        }
        __syncthreads();
    }
    #undef ISSUE_TILE

    // ---- epilogue ----
    #pragma unroll
    for (int mi = 0; mi < MF; mi++) {
        #pragma unroll
        for (int nj = 0; nj < 8; nj++) {
            const int r0 = bm + wm + mi * 16 + (lane >> 2);
            const int c  = bn + wn + nj * 8 + (lane & 3) * 2;
            #pragma unroll
            for (int hh = 0; hh < 2; hh++) {
                const int r = r0 + hh * 8;
                float vx = acc[mi][nj][2 * hh];
                float vy = acc[mi][nj][2 * hh + 1];
                if (EPI == 2) {
                    vx += E0[c];
                    vy += E0[c + 1];
                    vx = (vx > 20.f) ? vx : log1pf(expf(vx));
                    vy = (vy > 20.f) ? vy : log1pf(expf(vy));
                }
                if (EPI == 3) {
                    const float2 rr = *(const float2*)&E0[(size_t)r * ldc + c];
                    vx += rr.x;
                    vy += rr.y;
                }
                float2 v2; v2.x = vx; v2.y = vy;
                *(float2*)&C[(size_t)r * ldc + c] = v2;
                if (EPI == 1) {
                    __nv_bfloat16 hx = __float2bfloat16(vx);
                    __nv_bfloat16 hy = __float2bfloat16(vy);
                    __nv_bfloat162 hv; hv.x = hx; hv.y = hy;
                    __nv_bfloat162 lv;
                    lv.x = __float2bfloat16(vx - __bfloat162float(hx));
                    lv.y = __float2bfloat16(vy - __bfloat162float(hy));
                    *(__nv_bfloat162*)&Chi[(size_t)r * ldc + c] = hv;
                    *(__nv_bfloat162*)&Clo[(size_t)r * ldc + c] = lv;
                }
            }
        }
    }
}

// ---------------------------------------------------------------------------
// Convert fp32 -> bf16 (hi only), vectorized
// ---------------------------------------------------------------------------
__global__ void cvt_bf16(const float* __restrict__ s,
                         __nv_bfloat16* __restrict__ hi, int n)
{
    int i = (blockIdx.x * blockDim.x + threadIdx.x) * 4;
    if (i >= n) return;
    float4 v = *(const float4*)(s + i);
    __nv_bfloat162 hA; hA.x = __float2bfloat16(v.x); hA.y = __float2bfloat16(v.y);
    __nv_bfloat162 hB; hB.x = __float2bfloat16(v.z); hB.y = __float2bfloat16(v.w);
    *(__nv_bfloat162*)(hi + i)     = hA;
    *(__nv_bfloat162*)(hi + i + 2) = hB;
}

// Split fp32 -> bf16 hi/lo
__global__ void split_bf16(const float* __restrict__ s,
                           __nv_bfloat16* __restrict__ hi,
                           __nv_bfloat16* __restrict__ lo, int n)
{
    int i = blockIdx.x * blockDim.x + threadIdx.x;
    if (i >= n) return;
    float v = s[i];
    __nv_bfloat16 h = __float2bfloat16(v);
    hi[i] = h;
    lo[i] = __float2bfloat16(v - __bfloat162float(h));
}

__global__ void pad_split_wxproj(const float* __restrict__ W)
{
    int idx = blockIdx.x * blockDim.x + threadIdx.x;
    if (idx >= DI * NXPP) return;
    int row = idx / NXPP;
    int col = idx % NXPP;
    float v = (col < NXP) ? W[row * NXP + col] : 0.f;
    __nv_bfloat16 h = __float2bfloat16(v);
    g_wxh[idx] = h;
    g_wxl[idx] = __float2bfloat16(v - __bfloat162float(h));
}

// ---------------------------------------------------------------------------
// Causal depthwise conv (k=4) + bias + silu; emits fp32 u and bf16 hi/lo
// ---------------------------------------------------------------------------
__global__ __launch_bounds__(256) void conv_silu(
    const float* __restrict__ cw, const float* __restrict__ cb)
{
    size_t idx = (size_t)blockIdx.x * blockDim.x + threadIdx.x;
    if (idx >= (size_t)BB * LL * DI) return;
    int d = (int)(idx % DI);
    int l = (int)((idx / DI) % LL);
    int b = (int)(idx / ((size_t)LL * DI));

    const float* base = g_xz + ((size_t)b * LL) * (2 * DI) + d;
    float acc = cb[d];
    #pragma unroll
    for (int j = 0; j < DCONV; j++) {
        int ls = l - (DCONV - 1) + j;
        if (ls >= 0) acc = fmaf(cw[d * DCONV + j], base[(size_t)ls * (2 * DI)], acc);
    }
    float sig = 1.f / (1.f + __expf(-acc));
    float v = acc * sig;
    g_u[idx] = v;
    __nv_bfloat16 h = __float2bfloat16(v);
    g_uh[idx] = h;
    g_ul[idx] = __float2bfloat16(v - __bfloat162float(h));
}

// ---------------------------------------------------------------------------
// Segmented selective scan, pass 1
// ---------------------------------------------------------------------------
__global__ __launch_bounds__(128) void scan_pass1(const float* __restrict__ A_log)
{
    __shared__ float sdt[SLEN][32];
    __shared__ float su [SLEN][32];
    __shared__ float sB [SLEN][16];

    const int b   = blockIdx.z;
    const int seg = blockIdx.y;
    const int chB = blockIdx.x * 32;
    const int tid = threadIdx.x;
    const size_t rowBase = (size_t)b * LL + (size_t)seg * SLEN;

    for (int i = tid; i < SLEN * 32; i += 128) {
        int t = i >> 5, c = i & 31;
        sdt[t][c] = g_dt[(rowBase + t) * DI + chB + c];
        su [t][c] = g_u [(rowBase + t) * DI + chB + c];
    }
    for (int i = tid; i < SLEN * 16; i += 128) {
        int t = i >> 4, c = i & 15;
        sB[t][c] = g_xdbl[(rowBase + t) * NXPP + DR + c];
    }
    __syncthreads();

    const int chl = tid >> 2;
    const int ch  = chB + chl;
    const int n0  = (tid & 3) * 4;

    float Ae[4], h[4];
    #pragma unroll
    for (int j = 0; j < 4; j++) {
        Ae[j] = -expf(A_log[ch * DS + n0 + j]) * LOG2E;
        h[j] = 0.f;
    }
    float sumdt = 0.f;

    for (int t = 0; t < SLEN; t++) {
        const float dtv = sdt[t][chl];
        const float uv  = su[t][chl];
        const float du  = dtv * uv;
        sumdt += dtv;
        float4 B4 = *(const float4*)&sB[t][n0];
        h[0] = fmaf(exp2f(dtv * Ae[0]), h[0], du * B4.x);
        h[1] = fmaf(exp2f(dtv * Ae[1]), h[1], du * B4.y);
        h[2] = fmaf(exp2f(dtv * Ae[2]), h[2], du * B4.z);
        h[3] = fmaf(exp2f(dtv * Ae[3]), h[3], du * B4.w);
    }

    const size_t o = (((size_t)b * SEG + seg) * DI + ch) * DS + n0;
    float4 P4, q4;
    P4.x = exp2f(sumdt * Ae[0]); P4.y = exp2f(sumdt * Ae[1]);
    P4.z = exp2f(sumdt * Ae[2]); P4.w = exp2f(sumdt * Ae[3]);
    q4.x = h[0]; q4.y = h[1]; q4.z = h[2]; q4.w = h[3];
    *(float4*)&g_P[o] = P4;
    *(float4*)&g_q[o] = q4;
}

// ---------------------------------------------------------------------------
// Pass 2: sequential combine across segments
// ---------------------------------------------------------------------------
__global__ void scan_combine()
{
    int idx = blockIdx.x * blockDim.x + threadIdx.x;
    if (idx >= BB * DI * DS) return;
    int n  = idx % DS;
    int ch = (idx / DS) % DI;
    int b  = idx / (DS * DI);
    float h = 0.f;
    for (int s = 0; s < SEG; s++) {
        size_t o = (((size_t)b * SEG + s) * DI + ch) * DS + n;
        g_hin[o] = h;
        h = g_P[o] * h + g_q[o];
    }
}

// ---------------------------------------------------------------------------
// Pass 3: rescan from h_in, emit y (bf16, 1-term)
// ---------------------------------------------------------------------------
__global__ __launch_bounds__(128) void scan_pass3(
    const float* __restrict__ A_log, const float* __restrict__ Dvec)
{
    extern __shared__ float sm3[];
    float (*sdt)[32] = (float(*)[32])sm3;
    float (*su )[32] = (float(*)[32])(sm3 + SLEN * 32);
    float (*sz )[32] = (float(*)[32])(sm3 + 2 * SLEN * 32);
    float (*sB )[16] = (float(*)[16])(sm3 + 3 * SLEN * 32);
    float (*sC )[16] = (float(*)[16])(sm3 + 3 * SLEN * 32 + SLEN * 16);

    const int b   = blockIdx.z;
    const int seg = blockIdx.y;
    const int chB = blockIdx.x * 32;
    const int tid = threadIdx.x;
    const size_t rowBase = (size_t)b * LL + (size_t)seg * SLEN;

    for (int i = tid; i < SLEN * 32; i += 128) {
        int t = i >> 5, c = i & 31;
        sdt[t][c] = g_dt[(rowBase + t) * DI + chB + c];
        su [t][c] = g_u [(rowBase + t) * DI + chB + c];
        sz [t][c] = g_xz[(rowBase + t) * (2 * DI) + DI + chB + c];
    }
    for (int i = tid; i < SLEN * 16; i += 128) {
        int t = i >> 4, c = i & 15;
        sB[t][c] = g_xdbl[(rowBase + t) * NXPP + DR + c];
        sC[t][c] = g_xdbl[(rowBase + t) * NXPP + DR + DS + c];
    }
    __syncthreads();

    const int chl = tid >> 2;
    const int ch  = chB + chl;
    const int sg  = tid & 3;
    const int n0  = sg * 4;

    float Ae[4], h[4];
    #pragma unroll
    for (int j = 0; j < 4; j++)
        Ae[j] = -expf(A_log[ch * DS + n0 + j]) * LOG2E;
    {
        const size_t o = (((size_t)b * SEG + seg) * DI + ch) * DS + n0;
        float4 h4 = *(const float4*)&g_hin[o];
        h[0] = h4.x; h[1] = h4.y; h[2] = h4.z; h[3] = h4.w;
    }
    const float Dv = Dvec[ch];

    __nv_bfloat16* yph = g_yh + rowBase * DI + ch;

    for (int t = 0; t < SLEN; t++) {
        const float dtv = sdt[t][chl];
        const float uv  = su[t][chl];
        const float du  = dtv * uv;
        float4 B4 = *(const float4*)&sB[t][n0];
        float4 C4 = *(const float4*)&sC[t][n0];
        h[0] = fmaf(exp2f(dtv * Ae[0]), h[0], du * B4.x);
        h[1] = fmaf(exp2f(dtv * Ae[1]), h[1], du * B4.y);
        h[2] = fmaf(exp2f(dtv * Ae[2]), h[2], du * B4.z);
        h[3] = fmaf(exp2f(dtv * Ae[3]), h[3], du * B4.w);

        float yv = h[0] * C4.x;
        yv = fmaf(h[1], C4.y, yv);
        yv = fmaf(h[2], C4.z, yv);
        yv = fmaf(h[3], C4.w, yv);
        yv += __shfl_xor_sync(0xffffffffu, yv, 1);
        yv += __shfl_xor_sync(0xffffffffu, yv, 2);

        if (sg == 0) {
            const float zv  = sz[t][chl];
            const float ys  = fmaf(uv, Dv, yv);
            const float sig = 1.f / (1.f + __expf(-zv));
            const float yo  = ys * (zv * sig);
            yph[(size_t)t * DI] = __float2bfloat16(yo);
        }
    }
}

// ---------------------------------------------------------------------------
// In-place row LayerNorm on d_out (4096 rows x 1024)
// ---------------------------------------------------------------------------
__global__ __launch_bounds__(256) void ln_kernel(
    float* __restrict__ out, const float* __restrict__ gamma,
    const float* __restrict__ beta)
{
    __shared__ float red[8];
    const int row = blockIdx.x;
    float* p = out + (size_t)row * DM;
    const int tid  = threadIdx.x;
    const int lane = tid & 31;
    const int warp = tid >> 5;

    float v[4];
    float s = 0.f;
    #pragma unroll
    for (int i = 0; i < 4; i++) { v[i] = p[tid + 256 * i]; s += v[i]; }
    #pragma unroll
    for (int o = 16; o > 0; o >>= 1) s += __shfl_xor_sync(0xffffffffu, s, o);
    if (lane == 0) red[warp] = s;
    __syncthreads();
    s = 0.f;
    #pragma unroll
    for (int w = 0; w < 8; w++) s += red[w];
    const float mu = s * (1.f / DM);
    __syncthreads();

    float s2 = 0.f;
    #pragma unroll
    for (int i = 0; i < 4; i++) { float d = v[i] - mu; s2 += d * d; }
    #pragma unroll
    for (int o = 16; o > 0; o >>= 1) s2 += __shfl_xor_sync(0xffffffffu, s2, o);
    if (lane == 0) red[warp] = s2;
    __syncthreads();
    s2 = 0.f;
    #pragma unroll
    for (int w = 0; w < 8; w++) s2 += red[w];
    const float rstd = rsqrtf(s2 * (1.f / DM) + 1e-5f);

    #pragma unroll
    for (int i = 0; i < 4; i++) {
        const int col = tid + 256 * i;
        p[col] = (v[i] - mu) * rstd * gamma[col] + beta[col];
    }
}

// ---------------------------------------------------------------------------
// Launcher
// ---------------------------------------------------------------------------
extern "C" void kernel_launch(void* const* d_in, const int* in_sizes, int n_in,
                              void* d_out, int out_size)
{
    const float* x      = (const float*)d_in[0];
    const float* W_in   = (const float*)d_in[1];
    const float* conv_w = (const float*)d_in[2];
    const float* conv_b = (const float*)d_in[3];
    const float* W_xprj = (const float*)d_in[4];
    const float* W_dt   = (const float*)d_in[5];
    const float* b_dt   = (const float*)d_in[6];
    const float* A_log  = (const float*)d_in[7];
    const float* Dvec   = (const float*)d_in[8];
    const float* W_out  = (const float*)d_in[9];
    const float* gamma  = (const float*)d_in[10];
    const float* beta   = (const float*)d_in[11];
    float* out = (float*)d_out;

    float *xz, *u, *xdbl, *dt;
    cudaGetSymbolAddress((void**)&xz,   g_xz);
    cudaGetSymbolAddress((void**)&u,    g_u);
    cudaGetSymbolAddress((void**)&xdbl, g_xdbl);
    cudaGetSymbolAddress((void**)&dt,   g_dt);
    __nv_bfloat16 *xh, *w1h, *uh, *ul, *wxh, *wxl;
    __nv_bfloat16 *xdh, *xdl, *wdh, *wdl, *yh, *woh;
    cudaGetSymbolAddress((void**)&xh,  g_xh);
    cudaGetSymbolAddress((void**)&w1h, g_w1h);
    cudaGetSymbolAddress((void**)&uh,  g_uh);  cudaGetSymbolAddress((void**)&ul,  g_ul);
    cudaGetSymbolAddress((void**)&wxh, g_wxh); cudaGetSymbolAddress((void**)&wxl, g_wxl);
    cudaGetSymbolAddress((void**)&xdh, g_xdh); cudaGetSymbolAddress((void**)&xdl, g_xdl);
    cudaGetSymbolAddress((void**)&wdh, g_wdh); cudaGetSymbolAddress((void**)&wdl, g_wdl);
    cudaGetSymbolAddress((void**)&yh,  g_yh);
    cudaGetSymbolAddress((void**)&woh, g_woh);

    // dynamic smem sizes (bytes)
    const int SM1 = 2 * (128 * 40 + 32 * 136) * 2;               // 37888 (NT=1, MF=2)
    const int SM2 = 2 * (2 * 64 * 40 + 2 * 32 * 136) * 2;        // 55296 (NT=3, MF=1)
    const int SM4 = 2 * (2 * 128 * 40 + 2 * 32 * 136) * 2;       // 75776 (NT=3, MF=2)
    const int SM_P3 = (3 * SLEN * 32 + 2 * SLEN * 16) * 4;       // 65536
    cudaFuncSetAttribute(gemm_bf16<2,0,1>, cudaFuncAttributeMaxDynamicSharedMemorySize, SM1);
    cudaFuncSetAttribute(gemm_bf16<1,1,3>, cudaFuncAttributeMaxDynamicSharedMemorySize, SM2);
    cudaFuncSetAttribute(gemm_bf16<2,2,3>, cudaFuncAttributeMaxDynamicSharedMemorySize, SM4);
    cudaFuncSetAttribute(gemm_bf16<2,3,1>, cudaFuncAttributeMaxDynamicSharedMemorySize, SM1);
    cudaFuncSetAttribute(scan_pass3,       cudaFuncAttributeMaxDynamicSharedMemorySize, SM_P3);

    // 0) conversions
    cvt_bf16<<<(MROWS * DM / 4 + 255) / 256, 256>>>(x, xh, MROWS * DM);
    cvt_bf16<<<(DM * 2 * DI / 4 + 255) / 256, 256>>>(W_in, w1h, DM * 2 * DI);
    cvt_bf16<<<(DI * DM / 4 + 255) / 256, 256>>>(W_out, woh, DI * DM);
    split_bf16<<<(DR * DI + 255) / 256, 256>>>(W_dt, wdh, wdl, DR * DI);
    pad_split_wxproj<<<(DI * NXPP + 255) / 256, 256>>>(W_xprj);

    // 1) GEMM1: xz = x @ W_in   (1-term bf16)
    {
        dim3 grid(2 * DI / 128, MROWS / 128);
        gemm_bf16<2, 0, 1><<<grid, 256, SM1>>>(xh, nullptr, DM, w1h, nullptr, 2 * DI,
                                               xz, 2 * DI, DM, nullptr, nullptr, nullptr);
    }

    // 2) conv + silu -> u
    {
        size_t n = (size_t)BB * LL * DI;
        conv_silu<<<(unsigned)((n + 255) / 256), 256>>>(conv_w, conv_b);
    }

    // 3) GEMM2: x_dbl = u @ W_xproj(pad)  (3-term)
    {
        dim3 grid(NXPP / 128, MROWS / 64);
        gemm_bf16<1, 1, 3><<<grid, 256, SM2>>>(uh, ul, DI, wxh, wxl, NXPP,
                                               xdbl, NXPP, DI, nullptr, xdh, xdl);
    }

    // 4) dt = softplus(dt_low @ W_dt + b_dt)  (3-term)
    {
        dim3 grid(DI / 128, MROWS / 128);
        gemm_bf16<2, 2, 3><<<grid, 256, SM4>>>(xdh, xdl, NXPP, wdh, wdl, DI,
                                               dt, DI, DR, b_dt, nullptr, nullptr);
    }

    // 5) segmented selective scan -> y (bf16)
    {
        dim3 grid(DI / 32, SEG, BB);
        scan_pass1<<<grid, 128>>>(A_log);
        scan_combine<<<(BB * DI * DS + 255) / 256, 256>>>();
        scan_pass3<<<grid, 128, SM_P3>>>(A_log, Dvec);
    }

    // 6) GEMM3: out = y @ W_out + x  (1-term)
    {
        dim3 grid(DM / 128, MROWS / 128);
        gemm_bf16<2, 3, 1><<<grid, 256, SM1>>>(yh, nullptr, DI, woh, nullptr, DM,
                                               out, DM, DI, x, nullptr, nullptr);
    }

    // 7) LayerNorm in-place
    ln_kernel<<<MROWS, 256>>>(out, gamma, beta);
}

// round 9
// speedup vs baseline: 3.9767x; 1.1537x over previous
#include <cuda_runtime.h>
#include <cuda_bf16.h>
#include <math.h>
#include <stdint.h>
#include <cstdint>

// ---------------------------------------------------------------------------
// Problem constants
// ---------------------------------------------------------------------------
#define BB   2
#define LL   2048
#define DM   1024
#define DI   2048
#define DS   16
#define DR   64
#define DCONV 4
#define NXP  96
#define NXPP 128
#define MROWS (BB*LL)
#define SEG  16
#define SLEN (LL/SEG)
#define LOG2E 1.44269504088896f

// ---------------------------------------------------------------------------
// Scratch (device globals — no allocation allowed)
// ---------------------------------------------------------------------------
__device__ float g_xdbl [(size_t)BB*LL*NXPP];        // fp32 x_dbl (B,C for scan)
__device__ float g_P    [(size_t)BB*SEG*DI*DS];
__device__ float g_q    [(size_t)BB*SEG*DI*DS];
__device__ float g_hin  [(size_t)BB*SEG*DI*DS];

__device__ __nv_bfloat16 g_xh  [(size_t)MROWS*DM];   // x bf16 (GEMM1 A)
__device__ __nv_bfloat16 g_w1h [(size_t)DM*2*DI];    // W_in bf16
__device__ __nv_bfloat16 g_xzh [(size_t)MROWS*2*DI]; // xz bf16: [0:DI]=xin, [DI:2DI]=z
__device__ __nv_bfloat16 g_uh  [(size_t)MROWS*DI];   // u bf16
__device__ __nv_bfloat16 g_wxh [(size_t)DI*NXPP];    // W_xproj padded bf16
__device__ __nv_bfloat16 g_xdh [(size_t)MROWS*NXPP]; // x_dbl bf16 (GEMM4 A)
__device__ __nv_bfloat16 g_wdh [(size_t)DR*DI];      // W_dt bf16
__device__ __nv_bfloat16 g_dth [(size_t)MROWS*DI];   // dt bf16
__device__ __nv_bfloat16 g_yh  [(size_t)MROWS*DI];   // y bf16
__device__ __nv_bfloat16 g_woh [(size_t)DI*DM];      // W_out bf16

// ---------------------------------------------------------------------------
// PTX helpers
// ---------------------------------------------------------------------------
__device__ __forceinline__ unsigned cvta_s(const void* p) {
    return (unsigned)__cvta_generic_to_shared(p);
}
__device__ __forceinline__ void ldsm4(unsigned* r, unsigned a) {
    asm volatile("ldmatrix.sync.aligned.m8n8.x4.shared.b16 {%0,%1,%2,%3}, [%4];"
        : "=r"(r[0]), "=r"(r[1]), "=r"(r[2]), "=r"(r[3]) : "r"(a));
}
__device__ __forceinline__ void ldsm4t(unsigned* r, unsigned a) {
    asm volatile("ldmatrix.sync.aligned.m8n8.x4.trans.shared.b16 {%0,%1,%2,%3}, [%4];"
        : "=r"(r[0]), "=r"(r[1]), "=r"(r[2]), "=r"(r[3]) : "r"(a));
}
__device__ __forceinline__ void mma16816(float* d, const unsigned* a, const unsigned* b) {
    asm volatile("mma.sync.aligned.m16n8k16.row.col.f32.bf16.bf16.f32 "
        "{%0,%1,%2,%3}, {%4,%5,%6,%7}, {%8,%9}, {%0,%1,%2,%3};"
        : "+f"(d[0]), "+f"(d[1]), "+f"(d[2]), "+f"(d[3])
        : "r"(a[0]), "r"(a[1]), "r"(a[2]), "r"(a[3]), "r"(b[0]), "r"(b[1]));
}
__device__ __forceinline__ void cpa16(void* s, const void* g) {
    unsigned sa = cvta_s(s);
    asm volatile("cp.async.cg.shared.global [%0], [%1], 16;" :: "r"(sa), "l"(g));
}
__device__ __forceinline__ void cpcommit() {
    asm volatile("cp.async.commit_group;");
}
template<int N>
__device__ __forceinline__ void cpwait() {
    asm volatile("cp.async.wait_group %0;" :: "n"(N));
}

// ---------------------------------------------------------------------------
// bf16 tensor-core GEMM, cp.async 2-stage pipeline, 1-term bf16.
// A row-major [M,lda], B row-major [K,ldb].
// CTA tile BMx128x32, BM = 64*MF. 8 warps (4x2), warp tile (16*MF)x64.
// EPI: 1 fp32 C + bf16 Chi; 2 +bias[col] softplus -> bf16 Chi;
//      3 +E0 residual -> fp32 C; 4 bf16 Chi only.
// ---------------------------------------------------------------------------
template<int MF, int EPI>
__global__ __launch_bounds__(256) void gemm_bf16(
    const __nv_bfloat16* __restrict__ A, int lda,
    const __nv_bfloat16* __restrict__ B, int ldb,
    float* __restrict__ C, int ldc, int K,
    const float* __restrict__ E0,
    __nv_bfloat16* __restrict__ Chi)
{
    const int BM = 64 * MF;
    const int LDA = 40;
    const int LDB = 136;
    const int A_SZ = BM * LDA;
    const int B_SZ = 32 * LDB;
    const int STAGE = A_SZ + B_SZ;

    extern __shared__ __nv_bfloat16 smem[];

    const int tid  = threadIdx.x;
    const int lane = tid & 31;
    const int wid  = tid >> 5;
    const int wm   = (wid >> 1) * (16 * MF);
    const int wn   = (wid & 1) * 64;
    const int bm   = blockIdx.y * BM;
    const int bn   = blockIdx.x * 128;

    __nv_bfloat16* sA[2];
    __nv_bfloat16* sB[2];
    #pragma unroll
    for (int s = 0; s < 2; s++) {
        sA[s] = smem + s * STAGE;
        sB[s] = sA[s] + A_SZ;
    }

    float acc[MF][8][4];
    #pragma unroll
    for (int i = 0; i < MF; i++) {
        #pragma unroll
        for (int j = 0; j < 8; j++) {
            #pragma unroll
            for (int q = 0; q < 4; q++) acc[i][j][q] = 0.f;
        }
    }

    unsigned aB[2], bB[2];
    #pragma unroll
    for (int s = 0; s < 2; s++) {
        aB[s] = cvta_s(sA[s] + (wm + (lane & 15)) * LDA + ((lane >> 4) << 3));
        bB[s] = cvta_s(sB[s] + (lane & 15) * LDB + wn + ((lane >> 4) << 3));
    }

    const int ar = tid >> 2;
    const int ac = (tid & 3) * 8;
    const int br = tid >> 4;
    const int bc = (tid & 15) * 8;

    const int T = K / 32;

    #define ISSUE_TILE(t_)                                                          \
    {                                                                               \
        const int st_ = (t_) & 1;                                                   \
        const int k0_ = (t_) * 32;                                                  \
        _Pragma("unroll")                                                           \
        for (int p = 0; p < MF; p++) {                                              \
            const int row = p * 64 + ar;                                            \
            cpa16(sA[st_] + row * LDA + ac, A + (size_t)(bm + row) * lda + k0_ + ac); \
        }                                                                           \
        _Pragma("unroll")                                                           \
        for (int p = 0; p < 2; p++) {                                               \
            const int row = p * 16 + br;                                            \
            cpa16(sB[st_] + row * LDB + bc, B + (size_t)(k0_ + row) * ldb + bn + bc); \
        }                                                                           \
        cpcommit();                                                                 \
    }

    ISSUE_TILE(0);

    for (int t = 0; t < T; t++) {
        if (t + 1 < T) {
            ISSUE_TILE(t + 1);
            cpwait<1>();
        } else {
            cpwait<0>();
        }
        __syncthreads();

        const int st = t & 1;
        #pragma unroll
        for (int s = 0; s < 2; s++) {
            unsigned af[MF][4];
            #pragma unroll
            for (int mi = 0; mi < MF; mi++)
                ldsm4(af[mi], aB[st] + (unsigned)((mi * 16 * LDA + s * 16) * 2));
            unsigned bf[8][2];
            #pragma unroll
            for (int pr = 0; pr < 4; pr++) {
                unsigned t4[4];
                ldsm4t(t4, bB[st] + (unsigned)((s * 16 * LDB + pr * 16) * 2));
                bf[2 * pr][0] = t4[0]; bf[2 * pr][1] = t4[1];
                bf[2 * pr + 1][0] = t4[2]; bf[2 * pr + 1][1] = t4[3];
            }
            #pragma unroll
            for (int mi = 0; mi < MF; mi++) {
                #pragma unroll
                for (int nj = 0; nj < 8; nj++)
                    mma16816(acc[mi][nj], af[mi], bf[nj]);
            }
        }
        __syncthreads();
    }
    #undef ISSUE_TILE

    // ---- epilogue ----
    #pragma unroll
    for (int mi = 0; mi < MF; mi++) {
        #pragma unroll
        for (int nj = 0; nj < 8; nj++) {
            const int r0 = bm + wm + mi * 16 + (lane >> 2);
            const int c  = bn + wn + nj * 8 + (lane & 3) * 2;
            #pragma unroll
            for (int hh = 0; hh < 2; hh++) {
                const int r = r0 + hh * 8;
                float vx = acc[mi][nj][2 * hh];
                float vy = acc[mi][nj][2 * hh + 1];
                if (EPI == 2) {
                    vx += E0[c];
                    vy += E0[c + 1];
                    vx = (vx > 20.f) ? vx : log1pf(expf(vx));
                    vy = (vy > 20.f) ? vy : log1pf(expf(vy));
                }
                if (EPI == 3) {
                    const float2 rr = *(const float2*)&E0[(size_t)r * ldc + c];
                    vx += rr.x;
                    vy += rr.y;
                }
                if (EPI == 1 || EPI == 3) {
                    float2 v2; v2.x = vx; v2.y = vy;
                    *(float2*)&C[(size_t)r * ldc + c] = v2;
                }
                if (EPI == 1 || EPI == 2 || EPI == 4) {
                    __nv_bfloat162 hv;
                    hv.x = __float2bfloat16(vx);
                    hv.y = __float2bfloat16(vy);
                    *(__nv_bfloat162*)&Chi[(size_t)r * ldc + c] = hv;
                }
            }
        }
    }
}

// ---------------------------------------------------------------------------
// Convert fp32 -> bf16, vectorized (n % 4 == 0)
// ---------------------------------------------------------------------------
__global__ void cvt_bf16(const float* __restrict__ s,
                         __nv_bfloat16* __restrict__ hi, int n)
{
    int i = (blockIdx.x * blockDim.x + threadIdx.x) * 4;
    if (i >= n) return;
    float4 v = *(const float4*)(s + i);
    __nv_bfloat162 hA; hA.x = __float2bfloat16(v.x); hA.y = __float2bfloat16(v.y);
    __nv_bfloat162 hB; hB.x = __float2bfloat16(v.z); hB.y = __float2bfloat16(v.w);
    *(__nv_bfloat162*)(hi + i)     = hA;
    *(__nv_bfloat162*)(hi + i + 2) = hB;
}

__global__ void pad_cvt_wxproj(const float* __restrict__ W)
{
    int idx = blockIdx.x * blockDim.x + threadIdx.x;
    if (idx >= DI * NXPP) return;
    int row = idx / NXPP;
    int col = idx % NXPP;
    float v = (col < NXP) ? W[row * NXP + col] : 0.f;
    g_wxh[idx] = __float2bfloat16(v);
}

// ---------------------------------------------------------------------------
// Causal depthwise conv (k=4) + bias + silu; bf16 in (g_xzh), bf16 out (g_uh)
// ---------------------------------------------------------------------------
__global__ __launch_bounds__(256) void conv_silu(
    const float* __restrict__ cw, const float* __restrict__ cb)
{
    size_t idx = (size_t)blockIdx.x * blockDim.x + threadIdx.x;
    if (idx >= (size_t)BB * LL * DI) return;
    int d = (int)(idx % DI);
    int l = (int)((idx / DI) % LL);
    int b = (int)(idx / ((size_t)LL * DI));

    const __nv_bfloat16* base = g_xzh + ((size_t)b * LL) * (2 * DI) + d;
    float acc = cb[d];
    #pragma unroll
    for (int j = 0; j < DCONV; j++) {
        int ls = l - (DCONV - 1) + j;
        if (ls >= 0)
            acc = fmaf(cw[d * DCONV + j],
                       __bfloat162float(base[(size_t)ls * (2 * DI)]), acc);
    }
    float sig = 1.f / (1.f + __expf(-acc));
    g_uh[idx] = __float2bfloat16(acc * sig);
}

// ---------------------------------------------------------------------------
// Segmented selective scan, pass 1 (bf16 dt/u in, fp32 compute)
// ---------------------------------------------------------------------------
__global__ __launch_bounds__(128) void scan_pass1(const float* __restrict__ A_log)
{
    __shared__ float sdt[SLEN][32];
    __shared__ float su [SLEN][32];
    __shared__ float sB [SLEN][16];

    const int b   = blockIdx.z;
    const int seg = blockIdx.y;
    const int chB = blockIdx.x * 32;
    const int tid = threadIdx.x;
    const size_t rowBase = (size_t)b * LL + (size_t)seg * SLEN;

    for (int i = tid; i < SLEN * 32; i += 128) {
        int t = i >> 5, c = i & 31;
        sdt[t][c] = __bfloat162float(g_dth[(rowBase + t) * DI + chB + c]);
        su [t][c] = __bfloat162float(g_uh [(rowBase + t) * DI + chB + c]);
    }
    for (int i = tid; i < SLEN * 16; i += 128) {
        int t = i >> 4, c = i & 15;
        sB[t][c] = g_xdbl[(rowBase + t) * NXPP + DR + c];
    }
    __syncthreads();

    const int chl = tid >> 2;
    const int ch  = chB + chl;
    const int n0  = (tid & 3) * 4;

    float Ae[4], h[4];
    #pragma unroll
    for (int j = 0; j < 4; j++) {
        Ae[j] = -expf(A_log[ch * DS + n0 + j]) * LOG2E;
        h[j] = 0.f;
    }
    float sumdt = 0.f;

    for (int t = 0; t < SLEN; t++) {
        const float dtv = sdt[t][chl];
        const float uv  = su[t][chl];
        const float du  = dtv * uv;
        sumdt += dtv;
        float4 B4 = *(const float4*)&sB[t][n0];
        h[0] = fmaf(exp2f(dtv * Ae[0]), h[0], du * B4.x);
        h[1] = fmaf(exp2f(dtv * Ae[1]), h[1], du * B4.y);
        h[2] = fmaf(exp2f(dtv * Ae[2]), h[2], du * B4.z);
        h[3] = fmaf(exp2f(dtv * Ae[3]), h[3], du * B4.w);
    }

    const size_t o = (((size_t)b * SEG + seg) * DI + ch) * DS + n0;
    float4 P4, q4;
    P4.x = exp2f(sumdt * Ae[0]); P4.y = exp2f(sumdt * Ae[1]);
    P4.z = exp2f(sumdt * Ae[2]); P4.w = exp2f(sumdt * Ae[3]);
    q4.x = h[0]; q4.y = h[1]; q4.z = h[2]; q4.w = h[3];
    *(float4*)&g_P[o] = P4;
    *(float4*)&g_q[o] = q4;
}

// ---------------------------------------------------------------------------
// Pass 2: sequential combine across segments
// ---------------------------------------------------------------------------
__global__ void scan_combine()
{
    int idx = blockIdx.x * blockDim.x + threadIdx.x;
    if (idx >= BB * DI * DS) return;
    int n  = idx % DS;
    int ch = (idx / DS) % DI;
    int b  = idx / (DS * DI);
    float h = 0.f;
    for (int s = 0; s < SEG; s++) {
        size_t o = (((size_t)b * SEG + s) * DI + ch) * DS + n;
        g_hin[o] = h;
        h = g_P[o] * h + g_q[o];
    }
}

// ---------------------------------------------------------------------------
// Pass 3: rescan from h_in, emit y (bf16)
// ---------------------------------------------------------------------------
__global__ __launch_bounds__(128) void scan_pass3(
    const float* __restrict__ A_log, const float* __restrict__ Dvec)
{
    extern __shared__ float sm3[];
    float (*sdt)[32] = (float(*)[32])sm3;
    float (*su )[32] = (float(*)[32])(sm3 + SLEN * 32);
    float (*sz )[32] = (float(*)[32])(sm3 + 2 * SLEN * 32);
    float (*sB )[16] = (float(*)[16])(sm3 + 3 * SLEN * 32);
    float (*sC )[16] = (float(*)[16])(sm3 + 3 * SLEN * 32 + SLEN * 16);

    const int b   = blockIdx.z;
    const int seg = blockIdx.y;
    const int chB = blockIdx.x * 32;
    const int tid = threadIdx.x;
    const size_t rowBase = (size_t)b * LL + (size_t)seg * SLEN;

    for (int i = tid; i < SLEN * 32; i += 128) {
        int t = i >> 5, c = i & 31;
        sdt[t][c] = __bfloat162float(g_dth[(rowBase + t) * DI + chB + c]);
        su [t][c] = __bfloat162float(g_uh [(rowBase + t) * DI + chB + c]);
        sz [t][c] = __bfloat162float(g_xzh[(rowBase + t) * (2 * DI) + DI + chB + c]);
    }
    for (int i = tid; i < SLEN * 16; i += 128) {
        int t = i >> 4, c = i & 15;
        sB[t][c] = g_xdbl[(rowBase + t) * NXPP + DR + c];
        sC[t][c] = g_xdbl[(rowBase + t) * NXPP + DR + DS + c];
    }
    __syncthreads();

    const int chl = tid >> 2;
    const int ch  = chB + chl;
    const int sg  = tid & 3;
    const int n0  = sg * 4;

    float Ae[4], h[4];
    #pragma unroll
    for (int j = 0; j < 4; j++)
        Ae[j] = -expf(A_log[ch * DS + n0 + j]) * LOG2E;
    {
        const size_t o = (((size_t)b * SEG + seg) * DI + ch) * DS + n0;
        float4 h4 = *(const float4*)&g_hin[o];
        h[0] = h4.x; h[1] = h4.y; h[2] = h4.z; h[3] = h4.w;
    }
    const float Dv = Dvec[ch];

    __nv_bfloat16* yph = g_yh + rowBase * DI + ch;

    for (int t = 0; t < SLEN; t++) {
        const float dtv = sdt[t][chl];
        const float uv  = su[t][chl];
        const float du  = dtv * uv;
        float4 B4 = *(const float4*)&sB[t][n0];
        float4 C4 = *(const float4*)&sC[t][n0];
        h[0] = fmaf(exp2f(dtv * Ae[0]), h[0], du * B4.x);
        h[1] = fmaf(exp2f(dtv * Ae[1]), h[1], du * B4.y);
        h[2] = fmaf(exp2f(dtv * Ae[2]), h[2], du * B4.z);
        h[3] = fmaf(exp2f(dtv * Ae[3]), h[3], du * B4.w);

        float yv = h[0] * C4.x;
        yv = fmaf(h[1], C4.y, yv);
        yv = fmaf(h[2], C4.z, yv);
        yv = fmaf(h[3], C4.w, yv);
        yv += __shfl_xor_sync(0xffffffffu, yv, 1);
        yv += __shfl_xor_sync(0xffffffffu, yv, 2);

        if (sg == 0) {
            const float zv  = sz[t][chl];
            const float ys  = fmaf(uv, Dv, yv);
            const float sig = 1.f / (1.f + __expf(-zv));
            const float yo  = ys * (zv * sig);
            yph[(size_t)t * DI] = __float2bfloat16(yo);
        }
    }
}

// ---------------------------------------------------------------------------
// In-place row LayerNorm on d_out (4096 rows x 1024)
// ---------------------------------------------------------------------------
__global__ __launch_bounds__(256) void ln_kernel(
    float* __restrict__ out, const float* __restrict__ gamma,
    const float* __restrict__ beta)
{
    __shared__ float red[8];
    const int row = blockIdx.x;
    float* p = out + (size_t)row * DM;
    const int tid  = threadIdx.x;
    const int lane = tid & 31;
    const int warp = tid >> 5;

    float v[4];
    float s = 0.f;
    #pragma unroll
    for (int i = 0; i < 4; i++) { v[i] = p[tid + 256 * i]; s += v[i]; }
    #pragma unroll
    for (int o = 16; o > 0; o >>= 1) s += __shfl_xor_sync(0xffffffffu, s, o);
    if (lane == 0) red[warp] = s;
    __syncthreads();
    s = 0.f;
    #pragma unroll
    for (int w = 0; w < 8; w++) s += red[w];
    const float mu = s * (1.f / DM);
    __syncthreads();

    float s2 = 0.f;
    #pragma unroll
    for (int i = 0; i < 4; i++) { float d = v[i] - mu; s2 += d * d; }
    #pragma unroll
    for (int o = 16; o > 0; o >>= 1) s2 += __shfl_xor_sync(0xffffffffu, s2, o);
    if (lane == 0) red[warp] = s2;
    __syncthreads();
    s2 = 0.f;
    #pragma unroll
    for (int w = 0; w < 8; w++) s2 += red[w];
    const float rstd = rsqrtf(s2 * (1.f / DM) + 1e-5f);

    #pragma unroll
    for (int i = 0; i < 4; i++) {
        const int col = tid + 256 * i;
        p[col] = (v[i] - mu) * rstd * gamma[col] + beta[col];
    }
}

// ---------------------------------------------------------------------------
// Launcher
// ---------------------------------------------------------------------------
extern "C" void kernel_launch(void* const* d_in, const int* in_sizes, int n_in,
                              void* d_out, int out_size)
{
    const float* x      = (const float*)d_in[0];
    const float* W_in   = (const float*)d_in[1];
    const float* conv_w = (const float*)d_in[2];
    const float* conv_b = (const float*)d_in[3];
    const float* W_xprj = (const float*)d_in[4];
    const float* W_dt   = (const float*)d_in[5];
    const float* b_dt   = (const float*)d_in[6];
    const float* A_log  = (const float*)d_in[7];
    const float* Dvec   = (const float*)d_in[8];
    const float* W_out  = (const float*)d_in[9];
    const float* gamma  = (const float*)d_in[10];
    const float* beta   = (const float*)d_in[11];
    float* out = (float*)d_out;

    float *xdbl;
    cudaGetSymbolAddress((void**)&xdbl, g_xdbl);
    __nv_bfloat16 *xh, *w1h, *xzh, *uh, *wxh, *xdh, *wdh, *dth, *yh, *woh;
    cudaGetSymbolAddress((void**)&xh,  g_xh);
    cudaGetSymbolAddress((void**)&w1h, g_w1h);
    cudaGetSymbolAddress((void**)&xzh, g_xzh);
    cudaGetSymbolAddress((void**)&uh,  g_uh);
    cudaGetSymbolAddress((void**)&wxh, g_wxh);
    cudaGetSymbolAddress((void**)&xdh, g_xdh);
    cudaGetSymbolAddress((void**)&wdh, g_wdh);
    cudaGetSymbolAddress((void**)&dth, g_dth);
    cudaGetSymbolAddress((void**)&yh,  g_yh);
    cudaGetSymbolAddress((void**)&woh, g_woh);

    // dynamic smem sizes (bytes)
    const int SM_MF2 = 2 * (128 * 40 + 32 * 136) * 2;            // 37888
    const int SM_MF1 = 2 * (64 * 40 + 32 * 136) * 2;             // 27648
    const int SM_P3  = (3 * SLEN * 32 + 2 * SLEN * 16) * 4;      // 65536
    cudaFuncSetAttribute(gemm_bf16<2,4>, cudaFuncAttributeMaxDynamicSharedMemorySize, SM_MF2);
    cudaFuncSetAttribute(gemm_bf16<1,1>, cudaFuncAttributeMaxDynamicSharedMemorySize, SM_MF1);
    cudaFuncSetAttribute(gemm_bf16<2,2>, cudaFuncAttributeMaxDynamicSharedMemorySize, SM_MF2);
    cudaFuncSetAttribute(gemm_bf16<2,3>, cudaFuncAttributeMaxDynamicSharedMemorySize, SM_MF2);
    cudaFuncSetAttribute(scan_pass3,     cudaFuncAttributeMaxDynamicSharedMemorySize, SM_P3);

    // 0) conversions
    cvt_bf16<<<(MROWS * DM / 4 + 255) / 256, 256>>>(x, xh, MROWS * DM);
    cvt_bf16<<<(DM * 2 * DI / 4 + 255) / 256, 256>>>(W_in, w1h, DM * 2 * DI);
    cvt_bf16<<<(DI * DM / 4 + 255) / 256, 256>>>(W_out, woh, DI * DM);
    cvt_bf16<<<(DR * DI / 4 + 255) / 256, 256>>>(W_dt, wdh, DR * DI);
    pad_cvt_wxproj<<<(DI * NXPP + 255) / 256, 256>>>(W_xprj);

    // 1) GEMM1: xz = x @ W_in -> bf16  (M=4096, N=4096, K=1024)
    {
        dim3 grid(2 * DI / 128, MROWS / 128);
        gemm_bf16<2, 4><<<grid, 256, SM_MF2>>>(xh, DM, w1h, 2 * DI,
                                               nullptr, 2 * DI, DM, nullptr, xzh);
    }

    // 2) conv + silu -> u (bf16)
    {
        size_t n = (size_t)BB * LL * DI;
        conv_silu<<<(unsigned)((n + 255) / 256), 256>>>(conv_w, conv_b);
    }

    // 3) GEMM2: x_dbl = u @ W_xproj(pad) -> fp32 + bf16  (M=4096, N=128, K=2048)
    {
        dim3 grid(NXPP / 128, MROWS / 64);
        gemm_bf16<1, 1><<<grid, 256, SM_MF1>>>(uh, DI, wxh, NXPP,
                                               xdbl, NXPP, DI, nullptr, xdh);
    }

    // 4) GEMM4: dt = softplus(dt_low @ W_dt + b_dt) -> bf16  (M=4096, N=2048, K=64)
    {
        dim3 grid(DI / 128, MROWS / 128);
        gemm_bf16<2, 2><<<grid, 256, SM_MF2>>>(xdh, NXPP, wdh, DI,
                                               nullptr, DI, DR, b_dt, dth);
    }

    // 5) segmented selective scan -> y (bf16)
    {
        dim3 grid(DI / 32, SEG, BB);
        scan_pass1<<<grid, 128>>>(A_log);
        scan_combine<<<(BB * DI * DS + 255) / 256, 256>>>();
        scan_pass3<<<grid, 128, SM_P3>>>(A_log, Dvec);
    }

    // 6) GEMM3: out = y @ W_out + x  (M=4096, N=1024, K=2048; fp32 residual)
    {
        dim3 grid(DM / 128, MROWS / 128);
        gemm_bf16<2, 3><<<grid, 256, SM_MF2>>>(yh, DI, woh, DM,
                                               out, DM, DI, x, nullptr);
    }

    // 7) LayerNorm in-place
    ln_kernel<<<MROWS, 256>>>(out, gamma, beta);
}

// round 10
// speedup vs baseline: 4.8605x; 1.2222x over previous
#include <cuda_runtime.h>
#include <cuda_bf16.h>
#include <math.h>
#include <stdint.h>
#include <cstdint>

// ---------------------------------------------------------------------------
// Problem constants
// ---------------------------------------------------------------------------
#define BB   2
#define LL   2048
#define DM   1024
#define DI   2048
#define DS   16
#define DR   64
#define DCONV 4
#define NXP  96
#define NXPP 128
#define MROWS (BB*LL)
#define SEG  16
#define SLEN (LL/SEG)
#define LOG2E 1.44269504088896f

// ---------------------------------------------------------------------------
// Scratch (device globals — no allocation allowed)
// ---------------------------------------------------------------------------
__device__ float g_xdbl [(size_t)BB*LL*NXPP];        // fp32 x_dbl (B,C for scan)
__device__ float g_P    [(size_t)BB*SEG*DI*DS];
__device__ float g_q    [(size_t)BB*SEG*DI*DS];
__device__ float g_hin  [(size_t)BB*SEG*DI*DS];

__device__ __nv_bfloat16 g_xh  [(size_t)MROWS*DM];   // x bf16 (GEMM1 A)
__device__ __nv_bfloat16 g_w1h [(size_t)DM*2*DI];    // W_in bf16
__device__ __nv_bfloat16 g_xzh [(size_t)MROWS*2*DI]; // xz bf16: [0:DI]=xin, [DI:2DI]=z
__device__ __nv_bfloat16 g_uh  [(size_t)MROWS*DI];   // u bf16
__device__ __nv_bfloat16 g_wxh [(size_t)DI*NXPP];    // W_xproj padded bf16
__device__ __nv_bfloat16 g_xdh [(size_t)MROWS*NXPP]; // x_dbl bf16 (GEMM4 A)
__device__ __nv_bfloat16 g_wdh [(size_t)DR*DI];      // W_dt bf16
__device__ __nv_bfloat16 g_dth [(size_t)MROWS*DI];   // dt bf16
__device__ __nv_bfloat16 g_yh  [(size_t)MROWS*DI];   // y bf16
__device__ __nv_bfloat16 g_woh [(size_t)DI*DM];      // W_out bf16

// ---------------------------------------------------------------------------
// PTX helpers
// ---------------------------------------------------------------------------
__device__ __forceinline__ unsigned cvta_s(const void* p) {
    return (unsigned)__cvta_generic_to_shared(p);
}
__device__ __forceinline__ void ldsm4(unsigned* r, unsigned a) {
    asm volatile("ldmatrix.sync.aligned.m8n8.x4.shared.b16 {%0,%1,%2,%3}, [%4];"
        : "=r"(r[0]), "=r"(r[1]), "=r"(r[2]), "=r"(r[3]) : "r"(a));
}
__device__ __forceinline__ void ldsm4t(unsigned* r, unsigned a) {
    asm volatile("ldmatrix.sync.aligned.m8n8.x4.trans.shared.b16 {%0,%1,%2,%3}, [%4];"
        : "=r"(r[0]), "=r"(r[1]), "=r"(r[2]), "=r"(r[3]) : "r"(a));
}
__device__ __forceinline__ void mma16816(float* d, const unsigned* a, const unsigned* b) {
    asm volatile("mma.sync.aligned.m16n8k16.row.col.f32.bf16.bf16.f32 "
        "{%0,%1,%2,%3}, {%4,%5,%6,%7}, {%8,%9}, {%0,%1,%2,%3};"
        : "+f"(d[0]), "+f"(d[1]), "+f"(d[2]), "+f"(d[3])
        : "r"(a[0]), "r"(a[1]), "r"(a[2]), "r"(a[3]), "r"(b[0]), "r"(b[1]));
}
__device__ __forceinline__ void cpa16(void* s, const void* g) {
    unsigned sa = cvta_s(s);
    asm volatile("cp.async.cg.shared.global [%0], [%1], 16;" :: "r"(sa), "l"(g));
}
__device__ __forceinline__ void cpcommit() {
    asm volatile("cp.async.commit_group;");
}
template<int N>
__device__ __forceinline__ void cpwait() {
    asm volatile("cp.async.wait_group %0;" :: "n"(N));
}

// ---------------------------------------------------------------------------
// bf16 tensor-core GEMM, cp.async 3-stage pipeline, ONE sync per K-tile.
// A row-major [M,lda], B row-major [K,ldb].
// CTA tile BMx128x32, BM = 64*MF. 8 warps (4x2), warp tile (16*MF)x64.
// EPI: 1 fp32 C + bf16 Chi; 2 +bias[col] softplus -> bf16 Chi;
//      3 +E0 residual -> fp32 C; 4 bf16 Chi only.
// ---------------------------------------------------------------------------
template<int MF, int EPI>
__global__ __launch_bounds__(256) void gemm_bf16(
    const __nv_bfloat16* __restrict__ A, int lda,
    const __nv_bfloat16* __restrict__ B, int ldb,
    float* __restrict__ C, int ldc, int K,
    const float* __restrict__ E0,
    __nv_bfloat16* __restrict__ Chi)
{
    const int BM = 64 * MF;
    const int LDA = 40;
    const int LDB = 136;
    const int A_SZ = BM * LDA;
    const int B_SZ = 32 * LDB;
    const int STAGE = A_SZ + B_SZ;

    extern __shared__ __nv_bfloat16 smem[];

    const int tid  = threadIdx.x;
    const int lane = tid & 31;
    const int wid  = tid >> 5;
    const int wm   = (wid >> 1) * (16 * MF);
    const int wn   = (wid & 1) * 64;
    const int bm   = blockIdx.y * BM;
    const int bn   = blockIdx.x * 128;

    __nv_bfloat16* sA[3];
    __nv_bfloat16* sB[3];
    #pragma unroll
    for (int s = 0; s < 3; s++) {
        sA[s] = smem + s * STAGE;
        sB[s] = sA[s] + A_SZ;
    }

    float acc[MF][8][4];
    #pragma unroll
    for (int i = 0; i < MF; i++) {
        #pragma unroll
        for (int j = 0; j < 8; j++) {
            #pragma unroll
            for (int q = 0; q < 4; q++) acc[i][j][q] = 0.f;
        }
    }

    unsigned aB[3], bB[3];
    #pragma unroll
    for (int s = 0; s < 3; s++) {
        aB[s] = cvta_s(sA[s] + (wm + (lane & 15)) * LDA + ((lane >> 4) << 3));
        bB[s] = cvta_s(sB[s] + (lane & 15) * LDB + wn + ((lane >> 4) << 3));
    }

    const int ar = tid >> 2;
    const int ac = (tid & 3) * 8;
    const int br = tid >> 4;
    const int bc = (tid & 15) * 8;

    const int T = K / 32;

    #define ISSUE_TILE(t_)                                                          \
    {                                                                               \
        const int st_ = (t_) % 3;                                                   \
        const int k0_ = (t_) * 32;                                                  \
        _Pragma("unroll")                                                           \
        for (int p = 0; p < MF; p++) {                                              \
            const int row = p * 64 + ar;                                            \
            cpa16(sA[st_] + row * LDA + ac, A + (size_t)(bm + row) * lda + k0_ + ac); \
        }                                                                           \
        _Pragma("unroll")                                                           \
        for (int p = 0; p < 2; p++) {                                               \
            const int row = p * 16 + br;                                            \
            cpa16(sB[st_] + row * LDB + bc, B + (size_t)(k0_ + row) * ldb + bn + bc); \
        }                                                                           \
        cpcommit();                                                                 \
    }

    ISSUE_TILE(0);
    if (T > 1) ISSUE_TILE(1);

    for (int t = 0; t < T; t++) {
        if (t + 2 < T) {
            cpwait<1>();            // tile t complete (t+1 may be pending)
        } else {
            cpwait<0>();            // tail: drain everything
        }
        __syncthreads();            // data visible + stage (t+2)%3 consumed by all
        if (t + 2 < T) ISSUE_TILE(t + 2);

        const int st = t % 3;
        #pragma unroll
        for (int s = 0; s < 2; s++) {
            unsigned af[MF][4];
            #pragma unroll
            for (int mi = 0; mi < MF; mi++)
                ldsm4(af[mi], aB[st] + (unsigned)((mi * 16 * LDA + s * 16) * 2));
            unsigned bf[8][2];
            #pragma unroll
            for (int pr = 0; pr < 4; pr++) {
                unsigned t4[4];
                ldsm4t(t4, bB[st] + (unsigned)((s * 16 * LDB + pr * 16) * 2));
                bf[2 * pr][0] = t4[0]; bf[2 * pr][1] = t4[1];
                bf[2 * pr + 1][0] = t4[2]; bf[2 * pr + 1][1] = t4[3];
            }
            #pragma unroll
            for (int mi = 0; mi < MF; mi++) {
                #pragma unroll
                for (int nj = 0; nj < 8; nj++)
                    mma16816(acc[mi][nj], af[mi], bf[nj]);
            }
        }
    }
    #undef ISSUE_TILE

    // ---- epilogue ----
    #pragma unroll
    for (int mi = 0; mi < MF; mi++) {
        #pragma unroll
        for (int nj = 0; nj < 8; nj++) {
            const int r0 = bm + wm + mi * 16 + (lane >> 2);
            const int c  = bn + wn + nj * 8 + (lane & 3) * 2;
            #pragma unroll
            for (int hh = 0; hh < 2; hh++) {
                const int r = r0 + hh * 8;
                float vx = acc[mi][nj][2 * hh];
                float vy = acc[mi][nj][2 * hh + 1];
                if (EPI == 2) {
                    vx += E0[c];
                    vy += E0[c + 1];
                    vx = (vx > 20.f) ? vx : log1pf(expf(vx));
                    vy = (vy > 20.f) ? vy : log1pf(expf(vy));
                }
                if (EPI == 3) {
                    const float2 rr = *(const float2*)&E0[(size_t)r * ldc + c];
                    vx += rr.x;
                    vy += rr.y;
                }
                if (EPI == 1 || EPI == 3) {
                    float2 v2; v2.x = vx; v2.y = vy;
                    *(float2*)&C[(size_t)r * ldc + c] = v2;
                }
                if (EPI == 1 || EPI == 2 || EPI == 4) {
                    __nv_bfloat162 hv;
                    hv.x = __float2bfloat16(vx);
                    hv.y = __float2bfloat16(vy);
                    *(__nv_bfloat162*)&Chi[(size_t)r * ldc + c] = hv;
                }
            }
        }
    }
}

// ---------------------------------------------------------------------------
// Fused conversions: x, W_in, W_out, W_dt in one launch (each n % 4 == 0)
// ---------------------------------------------------------------------------
__global__ void cvt_all(
    const float* __restrict__ s0, __nv_bfloat16* __restrict__ d0, int n0,
    const float* __restrict__ s1, __nv_bfloat16* __restrict__ d1, int n1,
    const float* __restrict__ s2, __nv_bfloat16* __restrict__ d2, int n2,
    const float* __restrict__ s3, __nv_bfloat16* __restrict__ d3, int n3)
{
    int i = (blockIdx.x * blockDim.x + threadIdx.x) * 4;
    const float* s; __nv_bfloat16* d;
    if (i < n0)                { s = s0 + i;               d = d0 + i; }
    else if (i < n0 + n1)      { s = s1 + (i - n0);        d = d1 + (i - n0); }
    else if (i < n0 + n1 + n2) { s = s2 + (i - n0 - n1);   d = d2 + (i - n0 - n1); }
    else if (i < n0 + n1 + n2 + n3) { s = s3 + (i - n0 - n1 - n2); d = d3 + (i - n0 - n1 - n2); }
    else return;
    float4 v = *(const float4*)s;
    __nv_bfloat162 hA; hA.x = __float2bfloat16(v.x); hA.y = __float2bfloat16(v.y);
    __nv_bfloat162 hB; hB.x = __float2bfloat16(v.z); hB.y = __float2bfloat16(v.w);
    *(__nv_bfloat162*)(d)     = hA;
    *(__nv_bfloat162*)(d + 2) = hB;
}

__global__ void pad_cvt_wxproj(const float* __restrict__ W)
{
    int idx = blockIdx.x * blockDim.x + threadIdx.x;
    if (idx >= DI * NXPP) return;
    int row = idx / NXPP;
    int col = idx % NXPP;
    float v = (col < NXP) ? W[row * NXP + col] : 0.f;
    g_wxh[idx] = __float2bfloat16(v);
}

// ---------------------------------------------------------------------------
// Causal depthwise conv (k=4) + bias + silu; 2 channels/thread (bf162 path)
// ---------------------------------------------------------------------------
__global__ __launch_bounds__(256) void conv_silu(
    const float* __restrict__ cw, const float* __restrict__ cb)
{
    size_t idx = (size_t)blockIdx.x * blockDim.x + threadIdx.x;   // over BB*LL*DI/2
    if (idx >= (size_t)BB * LL * DI / 2) return;
    const int d2 = (int)(idx % (DI / 2)) * 2;
    const int l  = (int)((idx / (DI / 2)) % LL);
    const int b  = (int)(idx / ((size_t)LL * (DI / 2)));

    const __nv_bfloat162* base = (const __nv_bfloat162*)
        (g_xzh + ((size_t)b * LL) * (2 * DI) + d2);
    float a0 = cb[d2];
    float a1 = cb[d2 + 1];
    #pragma unroll
    for (int j = 0; j < DCONV; j++) {
        int ls = l - (DCONV - 1) + j;
        if (ls >= 0) {
            __nv_bfloat162 xv = base[(size_t)ls * DI];   // stride 2*DI bf16 = DI bf162
            a0 = fmaf(cw[d2 * DCONV + j],       __bfloat162float(xv.x), a0);
            a1 = fmaf(cw[(d2 + 1) * DCONV + j], __bfloat162float(xv.y), a1);
        }
    }
    const float s0 = 1.f / (1.f + __expf(-a0));
    const float s1 = 1.f / (1.f + __expf(-a1));
    __nv_bfloat162 o;
    o.x = __float2bfloat16(a0 * s0);
    o.y = __float2bfloat16(a1 * s1);
    *(__nv_bfloat162*)(g_uh + ((size_t)b * LL + l) * DI + d2) = o;
}

// ---------------------------------------------------------------------------
// Segmented selective scan, pass 1 (bf16 smem staging, fp32 compute)
// ---------------------------------------------------------------------------
__global__ __launch_bounds__(128) void scan_pass1(const float* __restrict__ A_log)
{
    __shared__ __nv_bfloat16 sdt[SLEN][32];
    __shared__ __nv_bfloat16 su [SLEN][32];
    __shared__ float         sB [SLEN][16];

    const int b   = blockIdx.z;
    const int seg = blockIdx.y;
    const int chB = blockIdx.x * 32;
    const int tid = threadIdx.x;
    const size_t rowBase = (size_t)b * LL + (size_t)seg * SLEN;

    for (int i = tid; i < SLEN * 32; i += 128) {
        int t = i >> 5, c = i & 31;
        sdt[t][c] = g_dth[(rowBase + t) * DI + chB + c];
        su [t][c] = g_uh [(rowBase + t) * DI + chB + c];
    }
    for (int i = tid; i < SLEN * 16; i += 128) {
        int t = i >> 4, c = i & 15;
        sB[t][c] = g_xdbl[(rowBase + t) * NXPP + DR + c];
    }
    __syncthreads();

    const int chl = tid >> 2;
    const int ch  = chB + chl;
    const int n0  = (tid & 3) * 4;

    float Ae[4], h[4];
    #pragma unroll
    for (int j = 0; j < 4; j++) {
        Ae[j] = -expf(A_log[ch * DS + n0 + j]) * LOG2E;
        h[j] = 0.f;
    }
    float sumdt = 0.f;

    for (int t = 0; t < SLEN; t++) {
        const float dtv = __bfloat162float(sdt[t][chl]);
        const float uv  = __bfloat162float(su[t][chl]);
        const float du  = dtv * uv;
        sumdt += dtv;
        float4 B4 = *(const float4*)&sB[t][n0];
        h[0] = fmaf(exp2f(dtv * Ae[0]), h[0], du * B4.x);
        h[1] = fmaf(exp2f(dtv * Ae[1]), h[1], du * B4.y);
        h[2] = fmaf(exp2f(dtv * Ae[2]), h[2], du * B4.z);
        h[3] = fmaf(exp2f(dtv * Ae[3]), h[3], du * B4.w);
    }

    const size_t o = (((size_t)b * SEG + seg) * DI + ch) * DS + n0;
    float4 P4, q4;
    P4.x = exp2f(sumdt * Ae[0]); P4.y = exp2f(sumdt * Ae[1]);
    P4.z = exp2f(sumdt * Ae[2]); P4.w = exp2f(sumdt * Ae[3]);
    q4.x = h[0]; q4.y = h[1]; q4.z = h[2]; q4.w = h[3];
    *(float4*)&g_P[o] = P4;
    *(float4*)&g_q[o] = q4;
}

// ---------------------------------------------------------------------------
// Pass 2: sequential combine across segments
// ---------------------------------------------------------------------------
__global__ void scan_combine()
{
    int idx = blockIdx.x * blockDim.x + threadIdx.x;
    if (idx >= BB * DI * DS) return;
    int n  = idx % DS;
    int ch = (idx / DS) % DI;
    int b  = idx / (DS * DI);
    float h = 0.f;
    for (int s = 0; s < SEG; s++) {
        size_t o = (((size_t)b * SEG + s) * DI + ch) * DS + n;
        g_hin[o] = h;
        h = g_P[o] * h + g_q[o];
    }
}

// ---------------------------------------------------------------------------
// Pass 3: rescan from h_in, emit y (bf16). bf16 smem staging (40 KB dyn).
// ---------------------------------------------------------------------------
__global__ __launch_bounds__(128) void scan_pass3(
    const float* __restrict__ A_log, const float* __restrict__ Dvec)
{
    extern __shared__ char sm3raw[];
    __nv_bfloat16 (*sdt)[32] = (__nv_bfloat16(*)[32])(sm3raw);
    __nv_bfloat16 (*su )[32] = (__nv_bfloat16(*)[32])(sm3raw + 8192);
    __nv_bfloat16 (*sz )[32] = (__nv_bfloat16(*)[32])(sm3raw + 16384);
    float         (*sB )[16] = (float(*)[16])        (sm3raw + 24576);
    float         (*sC )[16] = (float(*)[16])        (sm3raw + 32768);

    const int b   = blockIdx.z;
    const int seg = blockIdx.y;
    const int chB = blockIdx.x * 32;
    const int tid = threadIdx.x;
    const size_t rowBase = (size_t)b * LL + (size_t)seg * SLEN;

    for (int i = tid; i < SLEN * 32; i += 128) {
        int t = i >> 5, c = i & 31;
        sdt[t][c] = g_dth[(rowBase + t) * DI + chB + c];
        su [t][c] = g_uh [(rowBase + t) * DI + chB + c];
        sz [t][c] = g_xzh[(rowBase + t) * (2 * DI) + DI + chB + c];
    }
    for (int i = tid; i < SLEN * 16; i += 128) {
        int t = i >> 4, c = i & 15;
        sB[t][c] = g_xdbl[(rowBase + t) * NXPP + DR + c];
        sC[t][c] = g_xdbl[(rowBase + t) * NXPP + DR + DS + c];
    }
    __syncthreads();

    const int chl = tid >> 2;
    const int ch  = chB + chl;
    const int sg  = tid & 3;
    const int n0  = sg * 4;

    float Ae[4], h[4];
    #pragma unroll
    for (int j = 0; j < 4; j++)
        Ae[j] = -expf(A_log[ch * DS + n0 + j]) * LOG2E;
    {
        const size_t o = (((size_t)b * SEG + seg) * DI + ch) * DS + n0;
        float4 h4 = *(const float4*)&g_hin[o];
        h[0] = h4.x; h[1] = h4.y; h[2] = h4.z; h[3] = h4.w;
    }
    const float Dv = Dvec[ch];

    __nv_bfloat16* yph = g_yh + rowBase * DI + ch;

    for (int t = 0; t < SLEN; t++) {
        const float dtv = __bfloat162float(sdt[t][chl]);
        const float uv  = __bfloat162float(su[t][chl]);
        const float du  = dtv * uv;
        float4 B4 = *(const float4*)&sB[t][n0];
        float4 C4 = *(const float4*)&sC[t][n0];
        h[0] = fmaf(exp2f(dtv * Ae[0]), h[0], du * B4.x);
        h[1] = fmaf(exp2f(dtv * Ae[1]), h[1], du * B4.y);
        h[2] = fmaf(exp2f(dtv * Ae[2]), h[2], du * B4.z);
        h[3] = fmaf(exp2f(dtv * Ae[3]), h[3], du * B4.w);

        float yv = h[0] * C4.x;
        yv = fmaf(h[1], C4.y, yv);
        yv = fmaf(h[2], C4.z, yv);
        yv = fmaf(h[3], C4.w, yv);
        yv += __shfl_xor_sync(0xffffffffu, yv, 1);
        yv += __shfl_xor_sync(0xffffffffu, yv, 2);

        if (sg == 0) {
            const float zv  = __bfloat162float(sz[t][chl]);
            const float ys  = fmaf(uv, Dv, yv);
            const float sig = 1.f / (1.f + __expf(-zv));
            const float yo  = ys * (zv * sig);
            yph[(size_t)t * DI] = __float2bfloat16(yo);
        }
    }
}

// ---------------------------------------------------------------------------
// In-place row LayerNorm on d_out (4096 rows x 1024)
// ---------------------------------------------------------------------------
__global__ __launch_bounds__(256) void ln_kernel(
    float* __restrict__ out, const float* __restrict__ gamma,
    const float* __restrict__ beta)
{
    __shared__ float red[8];
    const int row = blockIdx.x;
    float* p = out + (size_t)row * DM;
    const int tid  = threadIdx.x;
    const int lane = tid & 31;
    const int warp = tid >> 5;

    float v[4];
    float s = 0.f;
    #pragma unroll
    for (int i = 0; i < 4; i++) { v[i] = p[tid + 256 * i]; s += v[i]; }
    #pragma unroll
    for (int o = 16; o > 0; o >>= 1) s += __shfl_xor_sync(0xffffffffu, s, o);
    if (lane == 0) red[warp] = s;
    __syncthreads();
    s = 0.f;
    #pragma unroll
    for (int w = 0; w < 8; w++) s += red[w];
    const float mu = s * (1.f / DM);
    __syncthreads();

    float s2 = 0.f;
    #pragma unroll
    for (int i = 0; i < 4; i++) { float d = v[i] - mu; s2 += d * d; }
    #pragma unroll
    for (int o = 16; o > 0; o >>= 1) s2 += __shfl_xor_sync(0xffffffffu, s2, o);
    if (lane == 0) red[warp] = s2;
    __syncthreads();
    s2 = 0.f;
    #pragma unroll
    for (int w = 0; w < 8; w++) s2 += red[w];
    const float rstd = rsqrtf(s2 * (1.f / DM) + 1e-5f);

    #pragma unroll
    for (int i = 0; i < 4; i++) {
        const int col = tid + 256 * i;
        p[col] = (v[i] - mu) * rstd * gamma[col] + beta[col];
    }
}

// ---------------------------------------------------------------------------
// Launcher
// ---------------------------------------------------------------------------
extern "C" void kernel_launch(void* const* d_in, const int* in_sizes, int n_in,
                              void* d_out, int out_size)
{
    const float* x      = (const float*)d_in[0];
    const float* W_in   = (const float*)d_in[1];
    const float* conv_w = (const float*)d_in[2];
    const float* conv_b = (const float*)d_in[3];
    const float* W_xprj = (const float*)d_in[4];
    const float* W_dt   = (const float*)d_in[5];
    const float* b_dt   = (const float*)d_in[6];
    const float* A_log  = (const float*)d_in[7];
    const float* Dvec   = (const float*)d_in[8];
    const float* W_out  = (const float*)d_in[9];
    const float* gamma  = (const float*)d_in[10];
    const float* beta   = (const float*)d_in[11];
    float* out = (float*)d_out;

    float *xdbl;
    cudaGetSymbolAddress((void**)&xdbl, g_xdbl);
    __nv_bfloat16 *xh, *w1h, *xzh, *uh, *wxh, *xdh, *wdh, *dth, *yh, *woh;
    cudaGetSymbolAddress((void**)&xh,  g_xh);
    cudaGetSymbolAddress((void**)&w1h, g_w1h);
    cudaGetSymbolAddress((void**)&xzh, g_xzh);
    cudaGetSymbolAddress((void**)&uh,  g_uh);
    cudaGetSymbolAddress((void**)&wxh, g_wxh);
    cudaGetSymbolAddress((void**)&xdh, g_xdh);
    cudaGetSymbolAddress((void**)&wdh, g_wdh);
    cudaGetSymbolAddress((void**)&dth, g_dth);
    cudaGetSymbolAddress((void**)&yh,  g_yh);
    cudaGetSymbolAddress((void**)&woh, g_woh);

    // dynamic smem sizes (bytes)
    const int SM_MF2 = 3 * (128 * 40 + 32 * 136) * 2;            // 56832
    const int SM_MF1 = 3 * (64 * 40 + 32 * 136) * 2;             // 41472
    const int SM_P3  = 40960;
    cudaFuncSetAttribute(gemm_bf16<2,4>, cudaFuncAttributeMaxDynamicSharedMemorySize, SM_MF2);
    cudaFuncSetAttribute(gemm_bf16<1,1>, cudaFuncAttributeMaxDynamicSharedMemorySize, SM_MF1);
    cudaFuncSetAttribute(gemm_bf16<2,2>, cudaFuncAttributeMaxDynamicSharedMemorySize, SM_MF2);
    cudaFuncSetAttribute(gemm_bf16<2,3>, cudaFuncAttributeMaxDynamicSharedMemorySize, SM_MF2);
    cudaFuncSetAttribute(scan_pass3,     cudaFuncAttributeMaxDynamicSharedMemorySize, SM_P3);

    // 0) conversions (one fused launch + pad)
    {
        const int n0 = MROWS * DM;         // x
        const int n1 = DM * 2 * DI;        // W_in
        const int n2 = DI * DM;            // W_out
        const int n3 = DR * DI;            // W_dt
        const int total4 = (n0 + n1 + n2 + n3) / 4;
        cvt_all<<<(total4 + 255) / 256, 256>>>(x, xh, n0, W_in, w1h, n1,
                                               W_out, woh, n2, W_dt, wdh, n3);
        pad_cvt_wxproj<<<(DI * NXPP + 255) / 256, 256>>>(W_xprj);
    }

    // 1) GEMM1: xz = x @ W_in -> bf16  (M=4096, N=4096, K=1024)
    {
        dim3 grid(2 * DI / 128, MROWS / 128);
        gemm_bf16<2, 4><<<grid, 256, SM_MF2>>>(xh, DM, w1h, 2 * DI,
                                               nullptr, 2 * DI, DM, nullptr, xzh);
    }

    // 2) conv + silu -> u (bf16)
    {
        size_t n = (size_t)BB * LL * DI / 2;
        conv_silu<<<(unsigned)((n + 255) / 256), 256>>>(conv_w, conv_b);
    }

    // 3) GEMM2: x_dbl = u @ W_xproj(pad) -> fp32 + bf16  (M=4096, N=128, K=2048)
    {
        dim3 grid(NXPP / 128, MROWS / 64);
        gemm_bf16<1, 1><<<grid, 256, SM_MF1>>>(uh, DI, wxh, NXPP,
                                               xdbl, NXPP, DI, nullptr, xdh);
    }

    // 4) GEMM4: dt = softplus(dt_low @ W_dt + b_dt) -> bf16  (M=4096, N=2048, K=64)
    {
        dim3 grid(DI / 128, MROWS / 128);
        gemm_bf16<2, 2><<<grid, 256, SM_MF2>>>(xdh, NXPP, wdh, DI,
                                               nullptr, DI, DR, b_dt, dth);
    }

    // 5) segmented selective scan -> y (bf16)
    {
        dim3 grid(DI / 32, SEG, BB);
        scan_pass1<<<grid, 128>>>(A_log);
        scan_combine<<<(BB * DI * DS + 255) / 256, 256>>>();
        scan_pass3<<<grid, 128, SM_P3>>>(A_log, Dvec);
    }

    // 6) GEMM3: out = y @ W_out + x  (M=4096, N=1024, K=2048; fp32 residual)
    {
        dim3 grid(DM / 128, MROWS / 128);
        gemm_bf16<2, 3><<<grid, 256, SM_MF2>>>(yh, DI, woh, DM,
                                               out, DM, DI, x, nullptr);
    }

    // 7) LayerNorm in-place
    ln_kernel<<<MROWS, 256>>>(out, gamma, beta);
}

// round 11
// speedup vs baseline: 5.3758x; 1.1060x over previous
#include <cuda_runtime.h>
#include <cuda_bf16.h>
#include <math.h>
#include <stdint.h>
#include <cstdint>

// ---------------------------------------------------------------------------
// Problem constants
// ---------------------------------------------------------------------------
#define BB   2
#define LL   2048
#define DM   1024
#define DI   2048
#define DS   16
#define DR   64
#define DCONV 4
#define NXP  96
#define NXPP 128
#define MROWS (BB*LL)
#define SEG  16
#define SLEN (LL/SEG)
#define CTL  8                      // conv timesteps per thread
#define LOG2E 1.44269504088896f

// ---------------------------------------------------------------------------
// Scratch (device globals — no allocation allowed)
// ---------------------------------------------------------------------------
__device__ float g_xdbl [(size_t)BB*LL*NXPP];        // fp32 x_dbl (B,C for scan)
__device__ float g_P    [(size_t)BB*SEG*DI*DS];      // scan decay; ALSO GEMM2 split-K partials
__device__ float g_q    [(size_t)BB*SEG*DI*DS];
__device__ float g_hin  [(size_t)BB*SEG*DI*DS];

__device__ __nv_bfloat16 g_xh  [(size_t)MROWS*DM];   // x bf16 (GEMM1 A)
__device__ __nv_bfloat16 g_w1h [(size_t)DM*2*DI];    // W_in bf16
__device__ __nv_bfloat16 g_xzh [(size_t)MROWS*2*DI]; // xz bf16: [0:DI]=xin, [DI:2DI]=z
__device__ __nv_bfloat16 g_uh  [(size_t)MROWS*DI];   // u bf16
__device__ __nv_bfloat16 g_wxh [(size_t)DI*NXPP];    // W_xproj padded bf16
__device__ __nv_bfloat16 g_xdh [(size_t)MROWS*NXPP]; // x_dbl bf16 (GEMM4 A)
__device__ __nv_bfloat16 g_wdh [(size_t)DR*DI];      // W_dt bf16
__device__ __nv_bfloat16 g_dth [(size_t)MROWS*DI];   // dt bf16
__device__ __nv_bfloat16 g_yh  [(size_t)MROWS*DI];   // y bf16
__device__ __nv_bfloat16 g_woh [(size_t)DI*DM];      // W_out bf16

// ---------------------------------------------------------------------------
// PTX helpers
// ---------------------------------------------------------------------------
__device__ __forceinline__ unsigned cvta_s(const void* p) {
    return (unsigned)__cvta_generic_to_shared(p);
}
__device__ __forceinline__ void ldsm4(unsigned* r, unsigned a) {
    asm volatile("ldmatrix.sync.aligned.m8n8.x4.shared.b16 {%0,%1,%2,%3}, [%4];"
        : "=r"(r[0]), "=r"(r[1]), "=r"(r[2]), "=r"(r[3]) : "r"(a));
}
__device__ __forceinline__ void ldsm4t(unsigned* r, unsigned a) {
    asm volatile("ldmatrix.sync.aligned.m8n8.x4.trans.shared.b16 {%0,%1,%2,%3}, [%4];"
        : "=r"(r[0]), "=r"(r[1]), "=r"(r[2]), "=r"(r[3]) : "r"(a));
}
__device__ __forceinline__ void mma16816(float* d, const unsigned* a, const unsigned* b) {
    asm volatile("mma.sync.aligned.m16n8k16.row.col.f32.bf16.bf16.f32 "
        "{%0,%1,%2,%3}, {%4,%5,%6,%7}, {%8,%9}, {%0,%1,%2,%3};"
        : "+f"(d[0]), "+f"(d[1]), "+f"(d[2]), "+f"(d[3])
        : "r"(a[0]), "r"(a[1]), "r"(a[2]), "r"(a[3]), "r"(b[0]), "r"(b[1]));
}
__device__ __forceinline__ void cpa16(void* s, const void* g) {
    unsigned sa = cvta_s(s);
    asm volatile("cp.async.cg.shared.global [%0], [%1], 16;" :: "r"(sa), "l"(g));
}
__device__ __forceinline__ void cpcommit() {
    asm volatile("cp.async.commit_group;");
}
template<int N>
__device__ __forceinline__ void cpwait() {
    asm volatile("cp.async.wait_group %0;" :: "n"(N));
}

// ---------------------------------------------------------------------------
// bf16 tensor-core GEMM, cp.async 3-stage pipeline, ONE sync per K-tile.
// A row-major [M,lda], B row-major [Ktotal,ldb].
// K param = K-chunk per z-slice; kbase = blockIdx.z * K; C += z*partStride.
// CTA tile BMx128x32, BM = 64*MF. 8 warps (4x2), warp tile (16*MF)x64.
// EPI: 0 plain fp32 C; 2 +bias[col] softplus -> bf16 Chi;
//      3 +E0 residual -> fp32 C; 4 bf16 Chi only.
// ---------------------------------------------------------------------------
template<int MF, int EPI>
__global__ __launch_bounds__(256) void gemm_bf16(
    const __nv_bfloat16* __restrict__ A, int lda,
    const __nv_bfloat16* __restrict__ B, int ldb,
    float* __restrict__ C, int ldc, int K,
    const float* __restrict__ E0,
    __nv_bfloat16* __restrict__ Chi,
    size_t partStride)
{
    const int BM = 64 * MF;
    const int LDA = 40;
    const int LDB = 136;
    const int A_SZ = BM * LDA;
    const int B_SZ = 32 * LDB;
    const int STAGE = A_SZ + B_SZ;

    extern __shared__ __nv_bfloat16 smem[];

    const int tid  = threadIdx.x;
    const int lane = tid & 31;
    const int wid  = tid >> 5;
    const int wm   = (wid >> 1) * (16 * MF);
    const int wn   = (wid & 1) * 64;
    const int bm   = blockIdx.y * BM;
    const int bn   = blockIdx.x * 128;
    const int kbase = blockIdx.z * K;
    C += (size_t)blockIdx.z * partStride;

    __nv_bfloat16* sA[3];
    __nv_bfloat16* sB[3];
    #pragma unroll
    for (int s = 0; s < 3; s++) {
        sA[s] = smem + s * STAGE;
        sB[s] = sA[s] + A_SZ;
    }

    float acc[MF][8][4];
    #pragma unroll
    for (int i = 0; i < MF; i++) {
        #pragma unroll
        for (int j = 0; j < 8; j++) {
            #pragma unroll
            for (int q = 0; q < 4; q++) acc[i][j][q] = 0.f;
        }
    }

    unsigned aB[3], bB[3];
    #pragma unroll
    for (int s = 0; s < 3; s++) {
        aB[s] = cvta_s(sA[s] + (wm + (lane & 15)) * LDA + ((lane >> 4) << 3));
        bB[s] = cvta_s(sB[s] + (lane & 15) * LDB + wn + ((lane >> 4) << 3));
    }

    const int ar = tid >> 2;
    const int ac = (tid & 3) * 8;
    const int br = tid >> 4;
    const int bc = (tid & 15) * 8;

    const int T = K / 32;

    #define ISSUE_TILE(t_)                                                          \
    {                                                                               \
        const int st_ = (t_) % 3;                                                   \
        const int k0_ = kbase + (t_) * 32;                                          \
        _Pragma("unroll")                                                           \
        for (int p = 0; p < MF; p++) {                                              \
            const int row = p * 64 + ar;                                            \
            cpa16(sA[st_] + row * LDA + ac, A + (size_t)(bm + row) * lda + k0_ + ac); \
        }                                                                           \
        _Pragma("unroll")                                                           \
        for (int p = 0; p < 2; p++) {                                               \
            const int row = p * 16 + br;                                            \
            cpa16(sB[st_] + row * LDB + bc, B + (size_t)(k0_ + row) * ldb + bn + bc); \
        }                                                                           \
        cpcommit();                                                                 \
    }

    ISSUE_TILE(0);
    if (T > 1) ISSUE_TILE(1);

    for (int t = 0; t < T; t++) {
        if (t + 2 < T) {
            cpwait<1>();
        } else {
            cpwait<0>();
        }
        __syncthreads();
        if (t + 2 < T) ISSUE_TILE(t + 2);

        const int st = t % 3;
        #pragma unroll
        for (int s = 0; s < 2; s++) {
            unsigned af[MF][4];
            #pragma unroll
            for (int mi = 0; mi < MF; mi++)
                ldsm4(af[mi], aB[st] + (unsigned)((mi * 16 * LDA + s * 16) * 2));
            unsigned bf[8][2];
            #pragma unroll
            for (int pr = 0; pr < 4; pr++) {
                unsigned t4[4];
                ldsm4t(t4, bB[st] + (unsigned)((s * 16 * LDB + pr * 16) * 2));
                bf[2 * pr][0] = t4[0]; bf[2 * pr][1] = t4[1];
                bf[2 * pr + 1][0] = t4[2]; bf[2 * pr + 1][1] = t4[3];
            }
            #pragma unroll
            for (int mi = 0; mi < MF; mi++) {
                #pragma unroll
                for (int nj = 0; nj < 8; nj++)
                    mma16816(acc[mi][nj], af[mi], bf[nj]);
            }
        }
    }
    #undef ISSUE_TILE

    // ---- epilogue ----
    #pragma unroll
    for (int mi = 0; mi < MF; mi++) {
        #pragma unroll
        for (int nj = 0; nj < 8; nj++) {
            const int r0 = bm + wm + mi * 16 + (lane >> 2);
            const int c  = bn + wn + nj * 8 + (lane & 3) * 2;
            #pragma unroll
            for (int hh = 0; hh < 2; hh++) {
                const int r = r0 + hh * 8;
                float vx = acc[mi][nj][2 * hh];
                float vy = acc[mi][nj][2 * hh + 1];
                if (EPI == 2) {
                    vx += E0[c];
                    vy += E0[c + 1];
                    vx = (vx > 20.f) ? vx : log1pf(expf(vx));
                    vy = (vy > 20.f) ? vy : log1pf(expf(vy));
                }
                if (EPI == 3) {
                    const float2 rr = *(const float2*)&E0[(size_t)r * ldc + c];
                    vx += rr.x;
                    vy += rr.y;
                }
                if (EPI == 0 || EPI == 3) {
                    float2 v2; v2.x = vx; v2.y = vy;
                    *(float2*)&C[(size_t)r * ldc + c] = v2;
                }
                if (EPI == 2 || EPI == 4) {
                    __nv_bfloat162 hv;
                    hv.x = __float2bfloat16(vx);
                    hv.y = __float2bfloat16(vy);
                    *(__nv_bfloat162*)&Chi[(size_t)r * ldc + c] = hv;
                }
            }
        }
    }
}

// ---------------------------------------------------------------------------
// GEMM2 split-K reduce: xdbl = p0 + p1 (fp32), xdh = bf16(xdbl).
// p0/p1 live in g_P (chunk stride MROWS*NXPP).
// ---------------------------------------------------------------------------
__global__ void reduce_xdbl()
{
    const int i = (blockIdx.x * blockDim.x + threadIdx.x) * 4;
    if (i >= MROWS * NXPP) return;
    float4 a = *(const float4*)&g_P[i];
    float4 b = *(const float4*)&g_P[(size_t)MROWS * NXPP + i];
    float4 v;
    v.x = a.x + b.x; v.y = a.y + b.y; v.z = a.z + b.z; v.w = a.w + b.w;
    *(float4*)&g_xdbl[i] = v;
    __nv_bfloat162 h0; h0.x = __float2bfloat16(v.x); h0.y = __float2bfloat16(v.y);
    __nv_bfloat162 h1; h1.x = __float2bfloat16(v.z); h1.y = __float2bfloat16(v.w);
    *(__nv_bfloat162*)&g_xdh[i]     = h0;
    *(__nv_bfloat162*)&g_xdh[i + 2] = h1;
}

// ---------------------------------------------------------------------------
// Fused conversions: x, W_in, W_out, W_dt in one launch (each n % 4 == 0)
// ---------------------------------------------------------------------------
__global__ void cvt_all(
    const float* __restrict__ s0, __nv_bfloat16* __restrict__ d0, int n0,
    const float* __restrict__ s1, __nv_bfloat16* __restrict__ d1, int n1,
    const float* __restrict__ s2, __nv_bfloat16* __restrict__ d2, int n2,
    const float* __restrict__ s3, __nv_bfloat16* __restrict__ d3, int n3)
{
    int i = (blockIdx.x * blockDim.x + threadIdx.x) * 4;
    const float* s; __nv_bfloat16* d;
    if (i < n0)                { s = s0 + i;               d = d0 + i; }
    else if (i < n0 + n1)      { s = s1 + (i - n0);        d = d1 + (i - n0); }
    else if (i < n0 + n1 + n2) { s = s2 + (i - n0 - n1);   d = d2 + (i - n0 - n1); }
    else if (i < n0 + n1 + n2 + n3) { s = s3 + (i - n0 - n1 - n2); d = d3 + (i - n0 - n1 - n2); }
    else return;
    float4 v = *(const float4*)s;
    __nv_bfloat162 hA; hA.x = __float2bfloat16(v.x); hA.y = __float2bfloat16(v.y);
    __nv_bfloat162 hB; hB.x = __float2bfloat16(v.z); hB.y = __float2bfloat16(v.w);
    *(__nv_bfloat162*)(d)     = hA;
    *(__nv_bfloat162*)(d + 2) = hB;
}

__global__ void pad_cvt_wxproj(const float* __restrict__ W)
{
    int idx = blockIdx.x * blockDim.x + threadIdx.x;
    if (idx >= DI * NXPP) return;
    int row = idx / NXPP;
    int col = idx % NXPP;
    float v = (col < NXP) ? W[row * NXP + col] : 0.f;
    g_wxh[idx] = __float2bfloat16(v);
}

// ---------------------------------------------------------------------------
// Causal depthwise conv (k=4) + bias + silu, register-tiled:
// each thread computes CTL=8 consecutive timesteps for 2 channels.
// Loads CTL+3 values instead of 4*CTL -> ~3x less L1 traffic.
// ---------------------------------------------------------------------------
__global__ __launch_bounds__(256) void conv_silu(
    const float* __restrict__ cw, const float* __restrict__ cb)
{
    const size_t total = (size_t)BB * (LL / CTL) * (DI / 2);
    size_t idx = (size_t)blockIdx.x * blockDim.x + threadIdx.x;
    if (idx >= total) return;
    const int d2 = (int)(idx % (DI / 2)) * 2;
    const int lt = (int)((idx / (DI / 2)) % (LL / CTL));
    const int b  = (int)(idx / ((size_t)(LL / CTL) * (DI / 2)));
    const int l0 = lt * CTL;

    // weights & bias for the two channels
    float w0[DCONV], w1[DCONV];
    #pragma unroll
    for (int j = 0; j < DCONV; j++) {
        w0[j] = cw[d2 * DCONV + j];
        w1[j] = cw[(d2 + 1) * DCONV + j];
    }
    const float b0 = cb[d2];
    const float b1 = cb[d2 + 1];

    // load CTL + 3 inputs (halo of 3 on the left)
    const __nv_bfloat162* base = (const __nv_bfloat162*)
        (g_xzh + ((size_t)b * LL) * (2 * DI) + d2);
    float x0[CTL + 3], x1[CTL + 3];
    #pragma unroll
    for (int j = 0; j < CTL + 3; j++) {
        const int ls = l0 - 3 + j;
        if (ls >= 0) {
            __nv_bfloat162 xv = base[(size_t)ls * DI];   // row stride = DI bf162
            x0[j] = __bfloat162float(xv.x);
            x1[j] = __bfloat162float(xv.y);
        } else {
            x0[j] = 0.f;
            x1[j] = 0.f;
        }
    }

    __nv_bfloat162* up = (__nv_bfloat162*)(g_uh + ((size_t)b * LL + l0) * DI + d2);
    #pragma unroll
    for (int t = 0; t < CTL; t++) {
        float a0 = b0, a1 = b1;
        #pragma unroll
        for (int j = 0; j < DCONV; j++) {
            a0 = fmaf(w0[j], x0[t + j], a0);
            a1 = fmaf(w1[j], x1[t + j], a1);
        }
        const float s0 = 1.f / (1.f + __expf(-a0));
        const float s1 = 1.f / (1.f + __expf(-a1));
        __nv_bfloat162 o;
        o.x = __float2bfloat16(a0 * s0);
        o.y = __float2bfloat16(a1 * s1);
        up[(size_t)t * (DI / 2)] = o;
    }
}

// ---------------------------------------------------------------------------
// Segmented selective scan, pass 1 (bf16 smem staging, fp32 compute)
// ---------------------------------------------------------------------------
__global__ __launch_bounds__(128) void scan_pass1(const float* __restrict__ A_log)
{
    __shared__ __nv_bfloat16 sdt[SLEN][32];
    __shared__ __nv_bfloat16 su [SLEN][32];
    __shared__ float         sB [SLEN][16];

    const int b   = blockIdx.z;
    const int seg = blockIdx.y;
    const int chB = blockIdx.x * 32;
    const int tid = threadIdx.x;
    const size_t rowBase = (size_t)b * LL + (size_t)seg * SLEN;

    for (int i = tid; i < SLEN * 32; i += 128) {
        int t = i >> 5, c = i & 31;
        sdt[t][c] = g_dth[(rowBase + t) * DI + chB + c];
        su [t][c] = g_uh [(rowBase + t) * DI + chB + c];
    }
    for (int i = tid; i < SLEN * 16; i += 128) {
        int t = i >> 4, c = i & 15;
        sB[t][c] = g_xdbl[(rowBase + t) * NXPP + DR + c];
    }
    __syncthreads();

    const int chl = tid >> 2;
    const int ch  = chB + chl;
    const int n0  = (tid & 3) * 4;

    float Ae[4], h[4];
    #pragma unroll
    for (int j = 0; j < 4; j++) {
        Ae[j] = -expf(A_log[ch * DS + n0 + j]) * LOG2E;
        h[j] = 0.f;
    }
    float sumdt = 0.f;

    for (int t = 0; t < SLEN; t++) {
        const float dtv = __bfloat162float(sdt[t][chl]);
        const float uv  = __bfloat162float(su[t][chl]);
        const float du  = dtv * uv;
        sumdt += dtv;
        float4 B4 = *(const float4*)&sB[t][n0];
        h[0] = fmaf(exp2f(dtv * Ae[0]), h[0], du * B4.x);
        h[1] = fmaf(exp2f(dtv * Ae[1]), h[1], du * B4.y);
        h[2] = fmaf(exp2f(dtv * Ae[2]), h[2], du * B4.z);
        h[3] = fmaf(exp2f(dtv * Ae[3]), h[3], du * B4.w);
    }

    const size_t o = (((size_t)b * SEG + seg) * DI + ch) * DS + n0;
    float4 P4, q4;
    P4.x = exp2f(sumdt * Ae[0]); P4.y = exp2f(sumdt * Ae[1]);
    P4.z = exp2f(sumdt * Ae[2]); P4.w = exp2f(sumdt * Ae[3]);
    q4.x = h[0]; q4.y = h[1]; q4.z = h[2]; q4.w = h[3];
    *(float4*)&g_P[o] = P4;
    *(float4*)&g_q[o] = q4;
}

// ---------------------------------------------------------------------------
// Pass 2: sequential combine across segments
// ---------------------------------------------------------------------------
__global__ void scan_combine()
{
    int idx = blockIdx.x * blockDim.x + threadIdx.x;
    if (idx >= BB * DI * DS) return;
    int n  = idx % DS;
    int ch = (idx / DS) % DI;
    int b  = idx / (DS * DI);
    float h = 0.f;
    for (int s = 0; s < SEG; s++) {
        size_t o = (((size_t)b * SEG + s) * DI + ch) * DS + n;
        g_hin[o] = h;
        h = g_P[o] * h + g_q[o];
    }
}

// ---------------------------------------------------------------------------
// Pass 3: rescan from h_in, emit y (bf16). bf16 smem staging (40 KB dyn).
// ---------------------------------------------------------------------------
__global__ __launch_bounds__(128) void scan_pass3(
    const float* __restrict__ A_log, const float* __restrict__ Dvec)
{
    extern __shared__ char sm3raw[];
    __nv_bfloat16 (*sdt)[32] = (__nv_bfloat16(*)[32])(sm3raw);
    __nv_bfloat16 (*su )[32] = (__nv_bfloat16(*)[32])(sm3raw + 8192);
    __nv_bfloat16 (*sz )[32] = (__nv_bfloat16(*)[32])(sm3raw + 16384);
    float         (*sB )[16] = (float(*)[16])        (sm3raw + 24576);
    float         (*sC )[16] = (float(*)[16])        (sm3raw + 32768);

    const int b   = blockIdx.z;
    const int seg = blockIdx.y;
    const int chB = blockIdx.x * 32;
    const int tid = threadIdx.x;
    const size_t rowBase = (size_t)b * LL + (size_t)seg * SLEN;

    for (int i = tid; i < SLEN * 32; i += 128) {
        int t = i >> 5, c = i & 31;
        sdt[t][c] = g_dth[(rowBase + t) * DI + chB + c];
        su [t][c] = g_uh [(rowBase + t) * DI + chB + c];
        sz [t][c] = g_xzh[(rowBase + t) * (2 * DI) + DI + chB + c];
    }
    for (int i = tid; i < SLEN * 16; i += 128) {
        int t = i >> 4, c = i & 15;
        sB[t][c] = g_xdbl[(rowBase + t) * NXPP + DR + c];
        sC[t][c] = g_xdbl[(rowBase + t) * NXPP + DR + DS + c];
    }
    __syncthreads();

    const int chl = tid >> 2;
    const int ch  = chB + chl;
    const int sg  = tid & 3;
    const int n0  = sg * 4;

    float Ae[4], h[4];
    #pragma unroll
    for (int j = 0; j < 4; j++)
        Ae[j] = -expf(A_log[ch * DS + n0 + j]) * LOG2E;
    {
        const size_t o = (((size_t)b * SEG + seg) * DI + ch) * DS + n0;
        float4 h4 = *(const float4*)&g_hin[o];
        h[0] = h4.x; h[1] = h4.y; h[2] = h4.z; h[3] = h4.w;
    }
    const float Dv = Dvec[ch];

    __nv_bfloat16* yph = g_yh + rowBase * DI + ch;

    for (int t = 0; t < SLEN; t++) {
        const float dtv = __bfloat162float(sdt[t][chl]);
        const float uv  = __bfloat162float(su[t][chl]);
        const float du  = dtv * uv;
        float4 B4 = *(const float4*)&sB[t][n0];
        float4 C4 = *(const float4*)&sC[t][n0];
        h[0] = fmaf(exp2f(dtv * Ae[0]), h[0], du * B4.x);
        h[1] = fmaf(exp2f(dtv * Ae[1]), h[1], du * B4.y);
        h[2] = fmaf(exp2f(dtv * Ae[2]), h[2], du * B4.z);
        h[3] = fmaf(exp2f(dtv * Ae[3]), h[3], du * B4.w);

        float yv = h[0] * C4.x;
        yv = fmaf(h[1], C4.y, yv);
        yv = fmaf(h[2], C4.z, yv);
        yv = fmaf(h[3], C4.w, yv);
        yv += __shfl_xor_sync(0xffffffffu, yv, 1);
        yv += __shfl_xor_sync(0xffffffffu, yv, 2);

        if (sg == 0) {
            const float zv  = __bfloat162float(sz[t][chl]);
            const float ys  = fmaf(uv, Dv, yv);
            const float sig = 1.f / (1.f + __expf(-zv));
            const float yo  = ys * (zv * sig);
            yph[(size_t)t * DI] = __float2bfloat16(yo);
        }
    }
}

// ---------------------------------------------------------------------------
// In-place row LayerNorm on d_out (4096 rows x 1024)
// ---------------------------------------------------------------------------
__global__ __launch_bounds__(256) void ln_kernel(
    float* __restrict__ out, const float* __restrict__ gamma,
    const float* __restrict__ beta)
{
    __shared__ float red[8];
    const int row = blockIdx.x;
    float* p = out + (size_t)row * DM;
    const int tid  = threadIdx.x;
    const int lane = tid & 31;
    const int warp = tid >> 5;

    float v[4];
    float s = 0.f;
    #pragma unroll
    for (int i = 0; i < 4; i++) { v[i] = p[tid + 256 * i]; s += v[i]; }
    #pragma unroll
    for (int o = 16; o > 0; o >>= 1) s += __shfl_xor_sync(0xffffffffu, s, o);
    if (lane == 0) red[warp] = s;
    __syncthreads();
    s = 0.f;
    #pragma unroll
    for (int w = 0; w < 8; w++) s += red[w];
    const float mu = s * (1.f / DM);
    __syncthreads();

    float s2 = 0.f;
    #pragma unroll
    for (int i = 0; i < 4; i++) { float d = v[i] - mu; s2 += d * d; }
    #pragma unroll
    for (int o = 16; o > 0; o >>= 1) s2 += __shfl_xor_sync(0xffffffffu, s2, o);
    if (lane == 0) red[warp] = s2;
    __syncthreads();
    s2 = 0.f;
    #pragma unroll
    for (int w = 0; w < 8; w++) s2 += red[w];
    const float rstd = rsqrtf(s2 * (1.f / DM) + 1e-5f);

    #pragma unroll
    for (int i = 0; i < 4; i++) {
        const int col = tid + 256 * i;
        p[col] = (v[i] - mu) * rstd * gamma[col] + beta[col];
    }
}

// ---------------------------------------------------------------------------
// Launcher
// ---------------------------------------------------------------------------
extern "C" void kernel_launch(void* const* d_in, const int* in_sizes, int n_in,
                              void* d_out, int out_size)
{
    const float* x      = (const float*)d_in[0];
    const float* W_in   = (const float*)d_in[1];
    const float* conv_w = (const float*)d_in[2];
    const float* conv_b = (const float*)d_in[3];
    const float* W_xprj = (const float*)d_in[4];
    const float* W_dt   = (const float*)d_in[5];
    const float* b_dt   = (const float*)d_in[6];
    const float* A_log  = (const float*)d_in[7];
    const float* Dvec   = (const float*)d_in[8];
    const float* W_out  = (const float*)d_in[9];
    const float* gamma  = (const float*)d_in[10];
    const float* beta   = (const float*)d_in[11];
    float* out = (float*)d_out;

    float *P;
    cudaGetSymbolAddress((void**)&P, g_P);
    __nv_bfloat16 *xh, *w1h, *xzh, *uh, *wxh, *xdh, *wdh, *dth, *yh, *woh;
    cudaGetSymbolAddress((void**)&xh,  g_xh);
    cudaGetSymbolAddress((void**)&w1h, g_w1h);
    cudaGetSymbolAddress((void**)&xzh, g_xzh);
    cudaGetSymbolAddress((void**)&uh,  g_uh);
    cudaGetSymbolAddress((void**)&wxh, g_wxh);
    cudaGetSymbolAddress((void**)&xdh, g_xdh);
    cudaGetSymbolAddress((void**)&wdh, g_wdh);
    cudaGetSymbolAddress((void**)&dth, g_dth);
    cudaGetSymbolAddress((void**)&yh,  g_yh);
    cudaGetSymbolAddress((void**)&woh, g_woh);

    // dynamic smem sizes (bytes)
    const int SM_MF2 = 3 * (128 * 40 + 32 * 136) * 2;            // 56832
    const int SM_MF1 = 3 * (64 * 40 + 32 * 136) * 2;             // 41472
    const int SM_P3  = 40960;
    cudaFuncSetAttribute(gemm_bf16<2,4>, cudaFuncAttributeMaxDynamicSharedMemorySize, SM_MF2);
    cudaFuncSetAttribute(gemm_bf16<1,0>, cudaFuncAttributeMaxDynamicSharedMemorySize, SM_MF1);
    cudaFuncSetAttribute(gemm_bf16<2,2>, cudaFuncAttributeMaxDynamicSharedMemorySize, SM_MF2);
    cudaFuncSetAttribute(gemm_bf16<2,3>, cudaFuncAttributeMaxDynamicSharedMemorySize, SM_MF2);
    cudaFuncSetAttribute(scan_pass3,     cudaFuncAttributeMaxDynamicSharedMemorySize, SM_P3);

    // 0) conversions (one fused launch + pad)
    {
        const int n0 = MROWS * DM;         // x
        const int n1 = DM * 2 * DI;        // W_in
        const int n2 = DI * DM;            // W_out
        const int n3 = DR * DI;            // W_dt
        const int total4 = (n0 + n1 + n2 + n3) / 4;
        cvt_all<<<(total4 + 255) / 256, 256>>>(x, xh, n0, W_in, w1h, n1,
                                               W_out, woh, n2, W_dt, wdh, n3);
        pad_cvt_wxproj<<<(DI * NXPP + 255) / 256, 256>>>(W_xprj);
    }

    // 1) GEMM1: xz = x @ W_in -> bf16  (M=4096, N=4096, K=1024)
    {
        dim3 grid(2 * DI / 128, MROWS / 128);
        gemm_bf16<2, 4><<<grid, 256, SM_MF2>>>(xh, DM, w1h, 2 * DI,
                                               nullptr, 2 * DI, DM, nullptr, xzh, 0);
    }

    // 2) conv + silu -> u (bf16), register-tiled
    {
        size_t n = (size_t)BB * (LL / CTL) * (DI / 2);
        conv_silu<<<(unsigned)((n + 255) / 256), 256>>>(conv_w, conv_b);
    }

    // 3) GEMM2: x_dbl partials = u @ W_xproj(pad), split-K=2 -> g_P; then reduce
    {
        dim3 grid(NXPP / 128, MROWS / 64, 2);
        gemm_bf16<1, 0><<<grid, 256, SM_MF1>>>(uh, DI, wxh, NXPP,
                                               P, NXPP, DI / 2, nullptr, nullptr,
                                               (size_t)MROWS * NXPP);
        reduce_xdbl<<<(MROWS * NXPP / 4 + 255) / 256, 256>>>();
    }

    // 4) GEMM4: dt = softplus(dt_low @ W_dt + b_dt) -> bf16  (M=4096, N=2048, K=64)
    {
        dim3 grid(DI / 128, MROWS / 128);
        gemm_bf16<2, 2><<<grid, 256, SM_MF2>>>(xdh, NXPP, wdh, DI,
                                               nullptr, DI, DR, b_dt, dth, 0);
    }

    // 5) segmented selective scan -> y (bf16)
    {
        dim3 grid(DI / 32, SEG, BB);
        scan_pass1<<<grid, 128>>>(A_log);
        scan_combine<<<(BB * DI * DS + 255) / 256, 256>>>();
        scan_pass3<<<grid, 128, SM_P3>>>(A_log, Dvec);
    }

    // 6) GEMM3: out = y @ W_out + x  (M=4096, N=1024, K=2048; fp32 residual)
    {
        dim3 grid(DM / 128, MROWS / 128);
        gemm_bf16<2, 3><<<grid, 256, SM_MF2>>>(yh, DI, woh, DM,
                                               out, DM, DI, x, nullptr, 0);
    }

    // 7) LayerNorm in-place
    ln_kernel<<<MROWS, 256>>>(out, gamma, beta);
}

// round 13
// speedup vs baseline: 5.4120x; 1.0067x over previous
#include <cuda_runtime.h>
#include <cuda_bf16.h>
#include <math.h>
#include <stdint.h>
#include <cstdint>

// ---------------------------------------------------------------------------
// Problem constants
// ---------------------------------------------------------------------------
#define BB   2
#define LL   2048
#define DM   1024
#define DI   2048
#define DS   16
#define DR   64
#define DCONV 4
#define NXP  96
#define NXPP 128
#define MROWS (BB*LL)
#define SEG  16
#define SLEN (LL/SEG)
#define NCHG (DI/32)                // 64 channel groups
#define CTL  8                      // conv timesteps per thread
#define LOG2E 1.44269504088896f

// ---------------------------------------------------------------------------
// Scratch (device globals — no allocation allowed)
// ---------------------------------------------------------------------------
__device__ float g_xdbl [(size_t)BB*LL*NXPP];        // fp32 x_dbl (B,C for scan)
__device__ float g_P    [(size_t)2*MROWS*NXPP];      // GEMM2 split-K partials
__device__ float g_hseg [(size_t)BB*SEG*DI*DS];      // inclusive seg-end states
__device__ int   g_sflag[BB*SEG*NCHG];               // publication flags

__device__ __nv_bfloat16 g_xh  [(size_t)MROWS*DM];   // x bf16 (GEMM1 A)
__device__ __nv_bfloat16 g_w1h [(size_t)DM*2*DI];    // W_in bf16
__device__ __nv_bfloat16 g_xzh [(size_t)MROWS*2*DI]; // xz bf16: [0:DI]=xin, [DI:2DI]=z
__device__ __nv_bfloat16 g_uh  [(size_t)MROWS*DI];   // u bf16
__device__ __nv_bfloat16 g_wxh [(size_t)DI*NXPP];    // W_xproj padded bf16
__device__ __nv_bfloat16 g_xdh [(size_t)MROWS*NXPP]; // x_dbl bf16 (GEMM4 A)
__device__ __nv_bfloat16 g_wdh [(size_t)DR*DI];      // W_dt bf16
__device__ __nv_bfloat16 g_dth [(size_t)MROWS*DI];   // dt bf16
__device__ __nv_bfloat16 g_yh  [(size_t)MROWS*DI];   // y bf16
__device__ __nv_bfloat16 g_woh [(size_t)DI*DM];      // W_out bf16

// ---------------------------------------------------------------------------
// PTX helpers
// ---------------------------------------------------------------------------
__device__ __forceinline__ unsigned cvta_s(const void* p) {
    return (unsigned)__cvta_generic_to_shared(p);
}
__device__ __forceinline__ void ldsm4(unsigned* r, unsigned a) {
    asm volatile("ldmatrix.sync.aligned.m8n8.x4.shared.b16 {%0,%1,%2,%3}, [%4];"
        : "=r"(r[0]), "=r"(r[1]), "=r"(r[2]), "=r"(r[3]) : "r"(a));
}
__device__ __forceinline__ void ldsm4t(unsigned* r, unsigned a) {
    asm volatile("ldmatrix.sync.aligned.m8n8.x4.trans.shared.b16 {%0,%1,%2,%3}, [%4];"
        : "=r"(r[0]), "=r"(r[1]), "=r"(r[2]), "=r"(r[3]) : "r"(a));
}
__device__ __forceinline__ void mma16816(float* d, const unsigned* a, const unsigned* b) {
    asm volatile("mma.sync.aligned.m16n8k16.row.col.f32.bf16.bf16.f32 "
        "{%0,%1,%2,%3}, {%4,%5,%6,%7}, {%8,%9}, {%0,%1,%2,%3};"
        : "+f"(d[0]), "+f"(d[1]), "+f"(d[2]), "+f"(d[3])
        : "r"(a[0]), "r"(a[1]), "r"(a[2]), "r"(a[3]), "r"(b[0]), "r"(b[1]));
}
__device__ __forceinline__ void cpa16(void* s, const void* g) {
    unsigned sa = cvta_s(s);
    asm volatile("cp.async.cg.shared.global [%0], [%1], 16;" :: "r"(sa), "l"(g));
}
__device__ __forceinline__ void cpcommit() {
    asm volatile("cp.async.commit_group;");
}
template<int N>
__device__ __forceinline__ void cpwait() {
    asm volatile("cp.async.wait_group %0;" :: "n"(N));
}

// ---------------------------------------------------------------------------
// bf16 tensor-core GEMM, cp.async 3-stage pipeline, ONE sync per K-tile.
// (unchanged from R11 — passed at 483.3us)
// ---------------------------------------------------------------------------
template<int MF, int EPI>
__global__ __launch_bounds__(256) void gemm_bf16(
    const __nv_bfloat16* __restrict__ A, int lda,
    const __nv_bfloat16* __restrict__ B, int ldb,
    float* __restrict__ C, int ldc, int K,
    const float* __restrict__ E0,
    __nv_bfloat16* __restrict__ Chi,
    size_t partStride)
{
    const int BM = 64 * MF;
    const int LDA = 40;
    const int LDB = 136;
    const int A_SZ = BM * LDA;
    const int B_SZ = 32 * LDB;
    const int STAGE = A_SZ + B_SZ;

    extern __shared__ __nv_bfloat16 smem[];

    const int tid  = threadIdx.x;
    const int lane = tid & 31;
    const int wid  = tid >> 5;
    const int wm   = (wid >> 1) * (16 * MF);
    const int wn   = (wid & 1) * 64;
    const int bm   = blockIdx.y * BM;
    const int bn   = blockIdx.x * 128;
    const int kbase = blockIdx.z * K;
    C += (size_t)blockIdx.z * partStride;

    __nv_bfloat16* sA[3];
    __nv_bfloat16* sB[3];
    #pragma unroll
    for (int s = 0; s < 3; s++) {
        sA[s] = smem + s * STAGE;
        sB[s] = sA[s] + A_SZ;
    }

    float acc[MF][8][4];
    #pragma unroll
    for (int i = 0; i < MF; i++) {
        #pragma unroll
        for (int j = 0; j < 8; j++) {
            #pragma unroll
            for (int q = 0; q < 4; q++) acc[i][j][q] = 0.f;
        }
    }

    unsigned aB[3], bB[3];
    #pragma unroll
    for (int s = 0; s < 3; s++) {
        aB[s] = cvta_s(sA[s] + (wm + (lane & 15)) * LDA + ((lane >> 4) << 3));
        bB[s] = cvta_s(sB[s] + (lane & 15) * LDB + wn + ((lane >> 4) << 3));
    }

    const int ar = tid >> 2;
    const int ac = (tid & 3) * 8;
    const int br = tid >> 4;
    const int bc = (tid & 15) * 8;

    const int T = K / 32;

    #define ISSUE_TILE(t_)                                                          \
    {                                                                               \
        const int st_ = (t_) % 3;                                                   \
        const int k0_ = kbase + (t_) * 32;                                          \
        _Pragma("unroll")                                                           \
        for (int p = 0; p < MF; p++) {                                              \
            const int row = p * 64 + ar;                                            \
            cpa16(sA[st_] + row * LDA + ac, A + (size_t)(bm + row) * lda + k0_ + ac); \
        }                                                                           \
        _Pragma("unroll")                                                           \
        for (int p = 0; p < 2; p++) {                                               \
            const int row = p * 16 + br;                                            \
            cpa16(sB[st_] + row * LDB + bc, B + (size_t)(k0_ + row) * ldb + bn + bc); \
        }                                                                           \
        cpcommit();                                                                 \
    }

    ISSUE_TILE(0);
    if (T > 1) ISSUE_TILE(1);

    for (int t = 0; t < T; t++) {
        if (t + 2 < T) {
            cpwait<1>();
        } else {
            cpwait<0>();
        }
        __syncthreads();
        if (t + 2 < T) ISSUE_TILE(t + 2);

        const int st = t % 3;
        #pragma unroll
        for (int s = 0; s < 2; s++) {
            unsigned af[MF][4];
            #pragma unroll
            for (int mi = 0; mi < MF; mi++)
                ldsm4(af[mi], aB[st] + (unsigned)((mi * 16 * LDA + s * 16) * 2));
            unsigned bf[8][2];
            #pragma unroll
            for (int pr = 0; pr < 4; pr++) {
                unsigned t4[4];
                ldsm4t(t4, bB[st] + (unsigned)((s * 16 * LDB + pr * 16) * 2));
                bf[2 * pr][0] = t4[0]; bf[2 * pr][1] = t4[1];
                bf[2 * pr + 1][0] = t4[2]; bf[2 * pr + 1][1] = t4[3];
            }
            #pragma unroll
            for (int mi = 0; mi < MF; mi++) {
                #pragma unroll
                for (int nj = 0; nj < 8; nj++)
                    mma16816(acc[mi][nj], af[mi], bf[nj]);
            }
        }
    }
    #undef ISSUE_TILE

    // ---- epilogue ----
    #pragma unroll
    for (int mi = 0; mi < MF; mi++) {
        #pragma unroll
        for (int nj = 0; nj < 8; nj++) {
            const int r0 = bm + wm + mi * 16 + (lane >> 2);
            const int c  = bn + wn + nj * 8 + (lane & 3) * 2;
            #pragma unroll
            for (int hh = 0; hh < 2; hh++) {
                const int r = r0 + hh * 8;
                float vx = acc[mi][nj][2 * hh];
                float vy = acc[mi][nj][2 * hh + 1];
                if (EPI == 2) {
                    vx += E0[c];
                    vy += E0[c + 1];
                    vx = (vx > 20.f) ? vx : log1pf(expf(vx));
                    vy = (vy > 20.f) ? vy : log1pf(expf(vy));
                }
                if (EPI == 3) {
                    const float2 rr = *(const float2*)&E0[(size_t)r * ldc + c];
                    vx += rr.x;
                    vy += rr.y;
                }
                if (EPI == 0 || EPI == 3) {
                    float2 v2; v2.x = vx; v2.y = vy;
                    *(float2*)&C[(size_t)r * ldc + c] = v2;
                }
                if (EPI == 2 || EPI == 4) {
                    __nv_bfloat162 hv;
                    hv.x = __float2bfloat16(vx);
                    hv.y = __float2bfloat16(vy);
                    *(__nv_bfloat162*)&Chi[(size_t)r * ldc + c] = hv;
                }
            }
        }
    }
}

// ---------------------------------------------------------------------------
// GEMM2 split-K reduce: xdbl = p0 + p1 (fp32), xdh = bf16(xdbl).
// ---------------------------------------------------------------------------
__global__ void reduce_xdbl()
{
    const int i = (blockIdx.x * blockDim.x + threadIdx.x) * 4;
    if (i >= MROWS * NXPP) return;
    float4 a = *(const float4*)&g_P[i];
    float4 b = *(const float4*)&g_P[(size_t)MROWS * NXPP + i];
    float4 v;
    v.x = a.x + b.x; v.y = a.y + b.y; v.z = a.z + b.z; v.w = a.w + b.w;
    *(float4*)&g_xdbl[i] = v;
    __nv_bfloat162 h0; h0.x = __float2bfloat16(v.x); h0.y = __float2bfloat16(v.y);
    __nv_bfloat162 h1; h1.x = __float2bfloat16(v.z); h1.y = __float2bfloat16(v.w);
    *(__nv_bfloat162*)&g_xdh[i]     = h0;
    *(__nv_bfloat162*)&g_xdh[i + 2] = h1;
}

// ---------------------------------------------------------------------------
// Zero the scan chain flags (must run before each fused scan; in-stream)
// ---------------------------------------------------------------------------
__global__ void clear_flags()
{
    int i = blockIdx.x * blockDim.x + threadIdx.x;
    if (i < BB * SEG * NCHG) g_sflag[i] = 0;
}

// ---------------------------------------------------------------------------
// Fused conversions: x, W_in, W_out, W_dt in one launch (each n % 4 == 0)
// ---------------------------------------------------------------------------
__global__ void cvt_all(
    const float* __restrict__ s0, __nv_bfloat16* __restrict__ d0, int n0,
    const float* __restrict__ s1, __nv_bfloat16* __restrict__ d1, int n1,
    const float* __restrict__ s2, __nv_bfloat16* __restrict__ d2, int n2,
    const float* __restrict__ s3, __nv_bfloat16* __restrict__ d3, int n3)
{
    int i = (blockIdx.x * blockDim.x + threadIdx.x) * 4;
    const float* s; __nv_bfloat16* d;
    if (i < n0)                { s = s0 + i;               d = d0 + i; }
    else if (i < n0 + n1)      { s = s1 + (i - n0);        d = d1 + (i - n0); }
    else if (i < n0 + n1 + n2) { s = s2 + (i - n0 - n1);   d = d2 + (i - n0 - n1); }
    else if (i < n0 + n1 + n2 + n3) { s = s3 + (i - n0 - n1 - n2); d = d3 + (i - n0 - n1 - n2); }
    else return;
    float4 v = *(const float4*)s;
    __nv_bfloat162 hA; hA.x = __float2bfloat16(v.x); hA.y = __float2bfloat16(v.y);
    __nv_bfloat162 hB; hB.x = __float2bfloat16(v.z); hB.y = __float2bfloat16(v.w);
    *(__nv_bfloat162*)(d)     = hA;
    *(__nv_bfloat162*)(d + 2) = hB;
}

__global__ void pad_cvt_wxproj(const float* __restrict__ W)
{
    int idx = blockIdx.x * blockDim.x + threadIdx.x;
    if (idx >= DI * NXPP) return;
    int row = idx / NXPP;
    int col = idx % NXPP;
    float v = (col < NXP) ? W[row * NXP + col] : 0.f;
    g_wxh[idx] = __float2bfloat16(v);
}

// ---------------------------------------------------------------------------
// Causal depthwise conv (k=4) + bias + silu, register-tiled (CTL=8 steps/thr)
// ---------------------------------------------------------------------------
__global__ __launch_bounds__(256) void conv_silu(
    const float* __restrict__ cw, const float* __restrict__ cb)
{
    const size_t total = (size_t)BB * (LL / CTL) * (DI / 2);
    size_t idx = (size_t)blockIdx.x * blockDim.x + threadIdx.x;
    if (idx >= total) return;
    const int d2 = (int)(idx % (DI / 2)) * 2;
    const int lt = (int)((idx / (DI / 2)) % (LL / CTL));
    const int b  = (int)(idx / ((size_t)(LL / CTL) * (DI / 2)));
    const int l0 = lt * CTL;

    float w0[DCONV], w1[DCONV];
    #pragma unroll
    for (int j = 0; j < DCONV; j++) {
        w0[j] = cw[d2 * DCONV + j];
        w1[j] = cw[(d2 + 1) * DCONV + j];
    }
    const float b0 = cb[d2];
    const float b1 = cb[d2 + 1];

    const __nv_bfloat162* base = (const __nv_bfloat162*)
        (g_xzh + ((size_t)b * LL) * (2 * DI) + d2);
    float x0[CTL + 3], x1[CTL + 3];
    #pragma unroll
    for (int j = 0; j < CTL + 3; j++) {
        const int ls = l0 - 3 + j;
        if (ls >= 0) {
            __nv_bfloat162 xv = base[(size_t)ls * DI];
            x0[j] = __bfloat162float(xv.x);
            x1[j] = __bfloat162float(xv.y);
        } else {
            x0[j] = 0.f;
            x1[j] = 0.f;
        }
    }

    __nv_bfloat162* up = (__nv_bfloat162*)(g_uh + ((size_t)b * LL + l0) * DI + d2);
    #pragma unroll
    for (int t = 0; t < CTL; t++) {
        float a0 = b0, a1 = b1;
        #pragma unroll
        for (int j = 0; j < DCONV; j++) {
            a0 = fmaf(w0[j], x0[t + j], a0);
            a1 = fmaf(w1[j], x1[t + j], a1);
        }
        const float s0 = 1.f / (1.f + __expf(-a0));
        const float s1 = 1.f / (1.f + __expf(-a1));
        __nv_bfloat162 o;
        o.x = __float2bfloat16(a0 * s0);
        o.y = __float2bfloat16(a1 * s1);
        up[(size_t)t * (DI / 2)] = o;
    }
}

// ---------------------------------------------------------------------------
// Fused single-pass chained selective scan.
// grid(NCHG, BB, SEG) — z (seg) varies slowest so predecessor segments are
// dispatched first. Each block: load tile to smem once; local scan -> (P,q);
// chain h through g_hseg/g_sflag (release/acquire); rescan from smem -> y.
// ---------------------------------------------------------------------------
__global__ __launch_bounds__(128) void scan_fused(
    const float* __restrict__ A_log, const float* __restrict__ Dvec)
{
    extern __shared__ char smraw[];
    __nv_bfloat16 (*sdt)[32] = (__nv_bfloat16(*)[32])(smraw);
    __nv_bfloat16 (*su )[32] = (__nv_bfloat16(*)[32])(smraw + 8192);
    __nv_bfloat16 (*sz )[32] = (__nv_bfloat16(*)[32])(smraw + 16384);
    float         (*sB )[16] = (float(*)[16])        (smraw + 24576);
    float         (*sC )[16] = (float(*)[16])        (smraw + 32768);

    const int chg = blockIdx.x;
    const int b   = blockIdx.y;
    const int seg = blockIdx.z;
    const int chB = chg * 32;
    const int tid = threadIdx.x;
    const size_t rowBase = (size_t)b * LL + (size_t)seg * SLEN;

    for (int i = tid; i < SLEN * 32; i += 128) {
        int t = i >> 5, c = i & 31;
        sdt[t][c] = g_dth[(rowBase + t) * DI + chB + c];
        su [t][c] = g_uh [(rowBase + t) * DI + chB + c];
        sz [t][c] = g_xzh[(rowBase + t) * (2 * DI) + DI + chB + c];
    }
    for (int i = tid; i < SLEN * 16; i += 128) {
        int t = i >> 4, c = i & 15;
        sB[t][c] = g_xdbl[(rowBase + t) * NXPP + DR + c];
        sC[t][c] = g_xdbl[(rowBase + t) * NXPP + DR + DS + c];
    }
    __syncthreads();

    const int chl = tid >> 2;
    const int ch  = chB + chl;
    const int sg  = tid & 3;
    const int n0  = sg * 4;

    float Ae[4], h[4];
    #pragma unroll
    for (int j = 0; j < 4; j++) {
        Ae[j] = -expf(A_log[ch * DS + n0 + j]) * LOG2E;
        h[j] = 0.f;
    }
    float sumdt = 0.f;

    // ---- local scan (h from 0) -> q = h_local_end, P = exp2(sumdt*Ae) ----
    for (int t = 0; t < SLEN; t++) {
        const float dtv = __bfloat162float(sdt[t][chl]);
        const float uv  = __bfloat162float(su[t][chl]);
        const float du  = dtv * uv;
        sumdt += dtv;
        h[0] = fmaf(exp2f(dtv * Ae[0]), h[0], du * __bfloat162float(__float2bfloat16(0.f)) + du * sB[t][n0 + 0] - du * 0.f);
        // NOTE: simple form below (kept identical to prior rounds)
        h[0] = h[0]; // no-op guard
        h[1] = fmaf(exp2f(dtv * Ae[1]), h[1], du * sB[t][n0 + 1]);
        h[2] = fmaf(exp2f(dtv * Ae[2]), h[2], du * sB[t][n0 + 2]);
        h[3] = fmaf(exp2f(dtv * Ae[3]), h[3], du * sB[t][n0 + 3]);
    }
    // Redo h[0] cleanly (the guard above must not alter arithmetic):
    // (recompute h[0] from scratch to keep arithmetic identical)
    {
        float h0 = 0.f;
        for (int t = 0; t < SLEN; t++) {
            const float dtv = __bfloat162float(sdt[t][chl]);
            const float uv  = __bfloat162float(su[t][chl]);
            const float du  = dtv * uv;
            h0 = fmaf(exp2f(dtv * Ae[0]), h0, du * sB[t][n0 + 0]);
        }
        h[0] = h0;
    }

    float P4[4];
    #pragma unroll
    for (int j = 0; j < 4; j++) P4[j] = exp2f(sumdt * Ae[j]);

    // ---- chain: acquire h_in from predecessor, publish inclusive h_out ----
    const size_t hcur = (((size_t)b * SEG + seg) * DI + ch) * DS + n0;
    const int fcur = (b * SEG + seg) * NCHG + chg;
    float hin[4] = {0.f, 0.f, 0.f, 0.f};

    if (seg > 0) {
        const int fprev = fcur - NCHG;
        if (tid == 0) {
            volatile int* fp = &g_sflag[fprev];
            while (*fp == 0) { __nanosleep(64); }
        }
        __syncthreads();
        __threadfence();    // acquire: order hseg reads after flag observation
        const size_t hprev = hcur - (size_t)DI * DS;
        float4 h4 = *(const float4*)&g_hseg[hprev];
        hin[0] = h4.x; hin[1] = h4.y; hin[2] = h4.z; hin[3] = h4.w;
    }

    {
        float4 ho;
        ho.x = fmaf(P4[0], hin[0], h[0]);
        ho.y = fmaf(P4[1], hin[1], h[1]);
        ho.z = fmaf(P4[2], hin[2], h[2]);
        ho.w = fmaf(P4[3], hin[3], h[3]);
        *(float4*)&g_hseg[hcur] = ho;
    }
    __threadfence();        // release: hseg visible before flag
    __syncthreads();        // all threads' stores done
    if (tid == 0) g_sflag[fcur] = 1;

    // ---- rescan from hin, emit y ----
    const float Dv = Dvec[ch];
    h[0] = hin[0]; h[1] = hin[1]; h[2] = hin[2]; h[3] = hin[3];
    __nv_bfloat16* yph = g_yh + rowBase * DI + ch;

    for (int t = 0; t < SLEN; t++) {
        const float dtv = __bfloat162float(sdt[t][chl]);
        const float uv  = __bfloat162float(su[t][chl]);
        const float du  = dtv * uv;
        float4 B4 = *(const float4*)&sB[t][n0];
        float4 C4 = *(const float4*)&sC[t][n0];
        h[0] = fmaf(exp2f(dtv * Ae[0]), h[0], du * B4.x);
        h[1] = fmaf(exp2f(dtv * Ae[1]), h[1], du * B4.y);
        h[2] = fmaf(exp2f(dtv * Ae[2]), h[2], du * B4.z);
        h[3] = fmaf(exp2f(dtv * Ae[3]), h[3], du * B4.w);

        float yv = h[0] * C4.x;
        yv = fmaf(h[1], C4.y, yv);
        yv = fmaf(h[2], C4.z, yv);
        yv = fmaf(h[3], C4.w, yv);
        yv += __shfl_xor_sync(0xffffffffu, yv, 1);
        yv += __shfl_xor_sync(0xffffffffu, yv, 2);

        if (sg == 0) {
            const float zv  = __bfloat162float(sz[t][chl]);
            const float ys  = fmaf(uv, Dv, yv);
            const float sig = 1.f / (1.f + __expf(-zv));
            const float yo  = ys * (zv * sig);
            yph[(size_t)t * DI] = __float2bfloat16(yo);
        }
    }
}

// ---------------------------------------------------------------------------
// In-place row LayerNorm on d_out (4096 rows x 1024)
// ---------------------------------------------------------------------------
__global__ __launch_bounds__(256) void ln_kernel(
    float* __restrict__ out, const float* __restrict__ gamma,
    const float* __restrict__ beta)
{
    __shared__ float red[8];
    const int row = blockIdx.x;
    float* p = out + (size_t)row * DM;
    const int tid  = threadIdx.x;
    const int lane = tid & 31;
    const int warp = tid >> 5;

    float v[4];
    float s = 0.f;
    #pragma unroll
    for (int i = 0; i < 4; i++) { v[i] = p[tid + 256 * i]; s += v[i]; }
    #pragma unroll
    for (int o = 16; o > 0; o >>= 1) s += __shfl_xor_sync(0xffffffffu, s, o);
    if (lane == 0) red[warp] = s;
    __syncthreads();
    s = 0.f;
    #pragma unroll
    for (int w = 0; w < 8; w++) s += red[w];
    const float mu = s * (1.f / DM);
    __syncthreads();

    float s2 = 0.f;
    #pragma unroll
    for (int i = 0; i < 4; i++) { float d = v[i] - mu; s2 += d * d; }
    #pragma unroll
    for (int o = 16; o > 0; o >>= 1) s2 += __shfl_xor_sync(0xffffffffu, s2, o);
    if (lane == 0) red[warp] = s2;
    __syncthreads();
    s2 = 0.f;
    #pragma unroll
    for (int w = 0; w < 8; w++) s2 += red[w];
    const float rstd = rsqrtf(s2 * (1.f / DM) + 1e-5f);

    #pragma unroll
    for (int i = 0; i < 4; i++) {
        const int col = tid + 256 * i;
        p[col] = (v[i] - mu) * rstd * gamma[col] + beta[col];
    }
}

// ---------------------------------------------------------------------------
// Launcher
// ---------------------------------------------------------------------------
extern "C" void kernel_launch(void* const* d_in, const int* in_sizes, int n_in,
                              void* d_out, int out_size)
{
    const float* x      = (const float*)d_in[0];
    const float* W_in   = (const float*)d_in[1];
    const float* conv_w = (const float*)d_in[2];
    const float* conv_b = (const float*)d_in[3];
    const float* W_xprj = (const float*)d_in[4];
    const float* W_dt   = (const float*)d_in[5];
    const float* b_dt   = (const float*)d_in[6];
    const float* A_log  = (const float*)d_in[7];
    const float* Dvec   = (const float*)d_in[8];
    const float* W_out  = (const float*)d_in[9];
    const float* gamma  = (const float*)d_in[10];
    const float* beta   = (const float*)d_in[11];
    float* out = (float*)d_out;

    float *P;
    cudaGetSymbolAddress((void**)&P, g_P);
    __nv_bfloat16 *xh, *w1h, *xzh, *uh, *wxh, *xdh, *wdh, *dth, *yh, *woh;
    cudaGetSymbolAddress((void**)&xh,  g_xh);
    cudaGetSymbolAddress((void**)&w1h, g_w1h);
    cudaGetSymbolAddress((void**)&xzh, g_xzh);
    cudaGetSymbolAddress((void**)&uh,  g_uh);
    cudaGetSymbolAddress((void**)&wxh, g_wxh);
    cudaGetSymbolAddress((void**)&xdh, g_xdh);
    cudaGetSymbolAddress((void**)&wdh, g_wdh);
    cudaGetSymbolAddress((void**)&dth, g_dth);
    cudaGetSymbolAddress((void**)&yh,  g_yh);
    cudaGetSymbolAddress((void**)&woh, g_woh);

    // dynamic smem sizes (bytes)
    const int SM_MF2 = 3 * (128 * 40 + 32 * 136) * 2;            // 56832
    const int SM_MF1 = 3 * (64 * 40 + 32 * 136) * 2;             // 41472
    const int SM_SC  = 40960;
    cudaFuncSetAttribute(gemm_bf16<2,4>, cudaFuncAttributeMaxDynamicSharedMemorySize, SM_MF2);
    cudaFuncSetAttribute(gemm_bf16<1,0>, cudaFuncAttributeMaxDynamicSharedMemorySize, SM_MF1);
    cudaFuncSetAttribute(gemm_bf16<2,2>, cudaFuncAttributeMaxDynamicSharedMemorySize, SM_MF2);
    cudaFuncSetAttribute(gemm_bf16<2,3>, cudaFuncAttributeMaxDynamicSharedMemorySize, SM_MF2);
    cudaFuncSetAttribute(scan_fused,     cudaFuncAttributeMaxDynamicSharedMemorySize, SM_SC);

    // 0) conversions (one fused launch + pad)
    {
        const int n0 = MROWS * DM;         // x
        const int n1 = DM * 2 * DI;        // W_in
        const int n2 = DI * DM;            // W_out
        const int n3 = DR * DI;            // W_dt
        const int total4 = (n0 + n1 + n2 + n3) / 4;
        cvt_all<<<(total4 + 255) / 256, 256>>>(x, xh, n0, W_in, w1h, n1,
                                               W_out, woh, n2, W_dt, wdh, n3);
        pad_cvt_wxproj<<<(DI * NXPP + 255) / 256, 256>>>(W_xprj);
    }

    // 1) GEMM1: xz = x @ W_in -> bf16  (M=4096, N=4096, K=1024)
    {
        dim3 grid(2 * DI / 128, MROWS / 128);
        gemm_bf16<2, 4><<<grid, 256, SM_MF2>>>(xh, DM, w1h, 2 * DI,
                                               nullptr, 2 * DI, DM, nullptr, xzh, 0);
    }

    // 2) conv + silu -> u (bf16), register-tiled
    {
        size_t n = (size_t)BB * (LL / CTL) * (DI / 2);
        conv_silu<<<(unsigned)((n + 255) / 256), 256>>>(conv_w, conv_b);
    }

    // 3) GEMM2: x_dbl partials, split-K=2 -> g_P; reduce; clear scan flags
    {
        dim3 grid(NXPP / 128, MROWS / 64, 2);
        gemm_bf16<1, 0><<<grid, 256, SM_MF1>>>(uh, DI, wxh, NXPP,
                                               P, NXPP, DI / 2, nullptr, nullptr,
                                               (size_t)MROWS * NXPP);
        reduce_xdbl<<<(MROWS * NXPP / 4 + 255) / 256, 256>>>();
        clear_flags<<<(BB * SEG * NCHG + 255) / 256, 256>>>();
    }

    // 4) GEMM4: dt = softplus(dt_low @ W_dt + b_dt) -> bf16  (M=4096, N=2048, K=64)
    {
        dim3 grid(DI / 128, MROWS / 128);
        gemm_bf16<2, 2><<<grid, 256, SM_MF2>>>(xdh, NXPP, wdh, DI,
                                               nullptr, DI, DR, b_dt, dth, 0);
    }

    // 5) fused single-pass chained scan -> y (bf16)
    {
        dim3 grid(NCHG, BB, SEG);
        scan_fused<<<grid, 128, SM_SC>>>(A_log, Dvec);
    }

    // 6) GEMM3: out = y @ W_out + x  (M=4096, N=1024, K=2048; fp32 residual)
    {
        dim3 grid(DM / 128, MROWS / 128);
        gemm_bf16<2, 3><<<grid, 256, SM_MF2>>>(yh, DI, woh, DM,
                                               out, DM, DI, x, nullptr, 0);
    }

    // 7) LayerNorm in-place
    ln_kernel<<<MROWS, 256>>>(out, gamma, beta);
}